// round 1
// baseline (speedup 1.0000x reference)
#include <cuda_runtime.h>

#define BSZ  8
#define NSEQ 1024
#define DIM  768
#define NH   12
#define HD   64
#define RNK  64
#define BN   (BSZ*NSEQ)          /* 8192 */
#define POFF (BSZ*NH*NSEQ*HD)    /* 6291456 */

// Scratch (device globals: allocation-free per harness rules)
__device__ float g_Weff[DIM*192];     // [c][p*64+r]
__device__ float g_T[BN*192];         // [i][p*64+r]
__device__ float g_QKV[3*POFF];       // [p][b][h][l][d]
__device__ float g_AO[BN*DIM];        // [b*l][h*64+d]

// ---------------------------------------------------------------------------
// Stage 1: Weff[c, p*64+r] = W1_p[c/64, r] * W2_p[c%64, r]
__global__ void k_build_weff(const float* __restrict__ W1q, const float* __restrict__ W2q,
                             const float* __restrict__ W1k, const float* __restrict__ W2k,
                             const float* __restrict__ W1v, const float* __restrict__ W2v) {
    int idx = blockIdx.x * blockDim.x + threadIdx.x;
    if (idx >= 3 * DIM * RNK) return;
    int p = idx / (DIM * RNK);
    int rem = idx % (DIM * RNK);
    int c = rem / RNK, r = rem % RNK;
    const float* W1 = (p == 0) ? W1q : ((p == 1) ? W1k : W1v);
    const float* W2 = (p == 0) ? W2q : ((p == 1) ? W2k : W2v);
    g_Weff[c * 192 + p * 64 + r] = W1[(c >> 6) * RNK + r] * W2[(c & 63) * RNK + r];
}

// ---------------------------------------------------------------------------
// Stage 2: T = x @ Weff   [8192,768] x [768,192]
// BM=128, BN=64, BK=16, 256 threads, 8x4 thread tile. A staged transposed.
__global__ void k_gemm_T(const float* __restrict__ x) {
    __shared__ float As[16][128];
    __shared__ float Bs[16][64];
    int tid = threadIdx.x;
    int i0 = blockIdx.x * 128, n0 = blockIdx.y * 64;
    int ty = tid >> 4, tx = tid & 15;
    float acc[8][4] = {};
    for (int k0 = 0; k0 < DIM; k0 += 16) {
#pragma unroll
        for (int t = 0; t < 2; t++) {
            int idx4 = tid + t * 256;
            int r = idx4 >> 2, kq = (idx4 & 3) * 4;
            float4 v = *(const float4*)(x + (size_t)(i0 + r) * DIM + k0 + kq);
            As[kq + 0][r] = v.x; As[kq + 1][r] = v.y; As[kq + 2][r] = v.z; As[kq + 3][r] = v.w;
        }
        {
            int kr = tid >> 4, c4 = (tid & 15) * 4;
            *(float4*)(&Bs[kr][c4]) = *(const float4*)(g_Weff + (k0 + kr) * 192 + n0 + c4);
        }
        __syncthreads();
#pragma unroll
        for (int k = 0; k < 16; k++) {
            float a[8], b[4];
#pragma unroll
            for (int i = 0; i < 8; i++) a[i] = As[k][ty + i * 16];
#pragma unroll
            for (int j = 0; j < 4; j++) b[j] = Bs[k][tx + j * 16];
#pragma unroll
            for (int i = 0; i < 8; i++)
#pragma unroll
                for (int j = 0; j < 4; j++) acc[i][j] += a[i] * b[j];
        }
        __syncthreads();
    }
#pragma unroll
    for (int i = 0; i < 8; i++)
#pragma unroll
        for (int j = 0; j < 4; j++)
            g_T[(size_t)(i0 + ty + i * 16) * 192 + n0 + tx + j * 16] = acc[i][j];
}

// ---------------------------------------------------------------------------
// Stage 3: Q/K/V[p][b][h][l][d] = sum_r T[i, p*64+r] * W0_p[h*64+d, r]
// One block = 64 rows x 64 d for one (row-tile, h, p). K=64 fully in smem.
__global__ void k_expand(const float* __restrict__ W0q, const float* __restrict__ W0k,
                         const float* __restrict__ W0v) {
    __shared__ float Ts[64][65];
    __shared__ float Ws[64][65];
    int p = blockIdx.z, h = blockIdx.y;
    int i0 = blockIdx.x * 64;
    const float* W0 = (p == 0) ? W0q : ((p == 1) ? W0k : W0v);
    int tid = threadIdx.x;
    for (int idx4 = tid; idx4 < 1024; idx4 += 256) {
        int r = idx4 >> 4, c4 = (idx4 & 15) * 4;
        float4 v = *(const float4*)(g_T + (size_t)(i0 + r) * 192 + p * 64 + c4);
        Ts[r][c4] = v.x; Ts[r][c4 + 1] = v.y; Ts[r][c4 + 2] = v.z; Ts[r][c4 + 3] = v.w;
    }
    const float* Wbase = W0 + h * 64 * 64;
    for (int idx4 = tid; idx4 < 1024; idx4 += 256) {
        int d = idx4 >> 4, c4 = (idx4 & 15) * 4;
        float4 v = *(const float4*)(Wbase + d * 64 + c4);
        Ws[d][c4] = v.x; Ws[d][c4 + 1] = v.y; Ws[d][c4 + 2] = v.z; Ws[d][c4 + 3] = v.w;
    }
    __syncthreads();
    int ty = tid >> 4, tx = tid & 15;
    float acc[4][4] = {};
#pragma unroll 16
    for (int r = 0; r < 64; r++) {
        float a[4], b[4];
#pragma unroll
        for (int i = 0; i < 4; i++) a[i] = Ts[ty + i * 16][r];
#pragma unroll
        for (int j = 0; j < 4; j++) b[j] = Ws[tx + j * 16][r];
#pragma unroll
        for (int i = 0; i < 4; i++)
#pragma unroll
            for (int j = 0; j < 4; j++) acc[i][j] += a[i] * b[j];
    }
    float* out = g_QKV + (size_t)p * POFF;
#pragma unroll
    for (int i = 0; i < 4; i++) {
        int row = i0 + ty + i * 16;
        int b_ = row >> 10, l = row & 1023;
        float* orow = out + (size_t)((b_ * NH + h) * NSEQ + l) * HD;
#pragma unroll
        for (int j = 0; j < 4; j++) orow[tx + j * 16] = acc[i][j];
    }
}

// ---------------------------------------------------------------------------
// Stage 4: flash attention. Block = one 64-row Q tile of one (b,h).
// 256 threads, 4x4 thread tiles; online softmax with shfl row reductions.
__global__ void k_attn() {
    extern __shared__ float sm[];
    float* Qs = sm;               // [64][65]
    float* Ks = sm + 64 * 65;     // [64][65]
    float* Ps = sm + 2 * 64 * 65; // [64][65]
    float* Vs = sm + 3 * 64 * 65; // [64][64]
    int bh = blockIdx.y;
    int qt = blockIdx.x * 64;
    const float* Q = g_QKV + 0 * (size_t)POFF + (size_t)bh * NSEQ * HD;
    const float* K = g_QKV + 1 * (size_t)POFF + (size_t)bh * NSEQ * HD;
    const float* V = g_QKV + 2 * (size_t)POFF + (size_t)bh * NSEQ * HD;
    int tid = threadIdx.x;
    int ty = tid >> 4, tx = tid & 15;
    const float scale = 0.125f;  // 64^-0.5

    for (int idx4 = tid; idx4 < 1024; idx4 += 256) {
        int r = idx4 >> 4, c4 = (idx4 & 15) * 4;
        float4 v = *(const float4*)(Q + (size_t)(qt + r) * HD + c4);
        Qs[r * 65 + c4] = v.x * scale; Qs[r * 65 + c4 + 1] = v.y * scale;
        Qs[r * 65 + c4 + 2] = v.z * scale; Qs[r * 65 + c4 + 3] = v.w * scale;
    }
    float m[4], l[4], acc[4][4] = {};
#pragma unroll
    for (int i = 0; i < 4; i++) { m[i] = -1e30f; l[i] = 0.f; }

    for (int kt = 0; kt < NSEQ; kt += 64) {
        for (int idx4 = tid; idx4 < 1024; idx4 += 256) {
            int r = idx4 >> 4, c4 = (idx4 & 15) * 4;
            float4 kv = *(const float4*)(K + (size_t)(kt + r) * HD + c4);
            Ks[r * 65 + c4] = kv.x; Ks[r * 65 + c4 + 1] = kv.y;
            Ks[r * 65 + c4 + 2] = kv.z; Ks[r * 65 + c4 + 3] = kv.w;
            *(float4*)(Vs + r * 64 + c4) = *(const float4*)(V + (size_t)(kt + r) * HD + c4);
        }
        __syncthreads();
        float s[4][4] = {};
#pragma unroll 16
        for (int k = 0; k < 64; k++) {
            float a[4], b[4];
#pragma unroll
            for (int i = 0; i < 4; i++) a[i] = Qs[(ty + i * 16) * 65 + k];
#pragma unroll
            for (int j = 0; j < 4; j++) b[j] = Ks[(tx + j * 16) * 65 + k];
#pragma unroll
            for (int i = 0; i < 4; i++)
#pragma unroll
                for (int j = 0; j < 4; j++) s[i][j] += a[i] * b[j];
        }
#pragma unroll
        for (int i = 0; i < 4; i++) {
            float mloc = fmaxf(fmaxf(s[i][0], s[i][1]), fmaxf(s[i][2], s[i][3]));
#pragma unroll
            for (int off = 8; off; off >>= 1)
                mloc = fmaxf(mloc, __shfl_xor_sync(0xffffffffu, mloc, off));
            float mnew = fmaxf(m[i], mloc);
            float alpha = __expf(m[i] - mnew);
            float rs = 0.f;
#pragma unroll
            for (int j = 0; j < 4; j++) { s[i][j] = __expf(s[i][j] - mnew); rs += s[i][j]; }
#pragma unroll
            for (int off = 8; off; off >>= 1) rs += __shfl_xor_sync(0xffffffffu, rs, off);
            l[i] = l[i] * alpha + rs;
            m[i] = mnew;
#pragma unroll
            for (int j = 0; j < 4; j++) acc[i][j] *= alpha;
#pragma unroll
            for (int j = 0; j < 4; j++) Ps[(ty + i * 16) * 65 + tx + j * 16] = s[i][j];
        }
        __syncthreads();
#pragma unroll 16
        for (int c = 0; c < 64; c++) {
            float pv[4], vv[4];
#pragma unroll
            for (int i = 0; i < 4; i++) pv[i] = Ps[(ty + i * 16) * 65 + c];
#pragma unroll
            for (int j = 0; j < 4; j++) vv[j] = Vs[c * 64 + tx + j * 16];
#pragma unroll
            for (int i = 0; i < 4; i++)
#pragma unroll
                for (int j = 0; j < 4; j++) acc[i][j] += pv[i] * vv[j];
        }
        __syncthreads();
    }
    int b_ = bh / NH, h = bh % NH;
#pragma unroll
    for (int i = 0; i < 4; i++) {
        float inv = 1.f / l[i];
        int row = qt + ty + i * 16;
        float* orow = g_AO + (size_t)(b_ * NSEQ + row) * DIM + h * HD;
#pragma unroll
        for (int j = 0; j < 4; j++) orow[tx + j * 16] = acc[i][j] * inv;
    }
}

// ---------------------------------------------------------------------------
// Stage 5: out = AO @ proj_w^T + proj_b   (NT GEMM, 128x128x16, 8x8 tiles)
__global__ void k_proj(const float* __restrict__ pw, const float* __restrict__ pb,
                       float* __restrict__ out) {
    __shared__ float As[128][17];
    __shared__ float Bs[128][17];
    int tid = threadIdx.x;
    int i0 = blockIdx.x * 128, n0 = blockIdx.y * 128;
    int ty = tid >> 4, tx = tid & 15;
    float acc[8][8] = {};
    for (int k0 = 0; k0 < DIM; k0 += 16) {
#pragma unroll
        for (int t = 0; t < 2; t++) {
            int idx4 = tid + t * 256;
            int r = idx4 >> 2, kq = (idx4 & 3) * 4;
            float4 a = *(const float4*)(g_AO + (size_t)(i0 + r) * DIM + k0 + kq);
            As[r][kq] = a.x; As[r][kq + 1] = a.y; As[r][kq + 2] = a.z; As[r][kq + 3] = a.w;
            float4 b = *(const float4*)(pw + (size_t)(n0 + r) * DIM + k0 + kq);
            Bs[r][kq] = b.x; Bs[r][kq + 1] = b.y; Bs[r][kq + 2] = b.z; Bs[r][kq + 3] = b.w;
        }
        __syncthreads();
#pragma unroll
        for (int k = 0; k < 16; k++) {
            float a[8], b[8];
#pragma unroll
            for (int i = 0; i < 8; i++) a[i] = As[ty + i * 16][k];
#pragma unroll
            for (int j = 0; j < 8; j++) b[j] = Bs[tx + j * 16][k];
#pragma unroll
            for (int i = 0; i < 8; i++)
#pragma unroll
                for (int j = 0; j < 8; j++) acc[i][j] += a[i] * b[j];
        }
        __syncthreads();
    }
#pragma unroll
    for (int i = 0; i < 8; i++) {
        int row = i0 + ty + i * 16;
#pragma unroll
        for (int j = 0; j < 8; j++) {
            int col = n0 + tx + j * 16;
            out[(size_t)row * DIM + col] = acc[i][j] + pb[col];
        }
    }
}

// ---------------------------------------------------------------------------
extern "C" void kernel_launch(void* const* d_in, const int* in_sizes, int n_in,
                              void* d_out, int out_size) {
    const float* x   = (const float*)d_in[0];
    const float* WQ0 = (const float*)d_in[1];
    const float* WQ1 = (const float*)d_in[2];
    const float* WQ2 = (const float*)d_in[3];
    const float* WK0 = (const float*)d_in[4];
    const float* WK1 = (const float*)d_in[5];
    const float* WK2 = (const float*)d_in[6];
    const float* WV0 = (const float*)d_in[7];
    const float* WV1 = (const float*)d_in[8];
    const float* WV2 = (const float*)d_in[9];
    const float* pw  = (const float*)d_in[10];
    const float* pb  = (const float*)d_in[11];
    float* out = (float*)d_out;

    k_build_weff<<<(3 * DIM * RNK + 255) / 256, 256>>>(WQ1, WQ2, WK1, WK2, WV1, WV2);
    k_gemm_T<<<dim3(BN / 128, 3), 256>>>(x);
    k_expand<<<dim3(BN / 64, NH, 3), 256>>>(WQ0, WK0, WV0);

    int smem_attn = (3 * 64 * 65 + 64 * 64) * (int)sizeof(float);  // 66304 B
    cudaFuncSetAttribute(k_attn, cudaFuncAttributeMaxDynamicSharedMemorySize, smem_attn);
    k_attn<<<dim3(NSEQ / 64, BSZ * NH), 256, smem_attn>>>();

    k_proj<<<dim3(BN / 128, DIM / 128), 256>>>(pw, pb, out);
}

// round 3
// speedup vs baseline: 1.8493x; 1.8493x over previous
#include <cuda_runtime.h>
#include <cuda_bf16.h>
#include <cstdint>

#define BSZ  8
#define NSEQ 1024
#define DIM  768
#define NH   12
#define HD   64
#define RNK  64
#define BN   (BSZ*NSEQ)          /* 8192 */
#define NBH  (BSZ*NH)            /* 96 */
#define PAD  72                  /* padded smem row stride in bf16 */

// ---------------------------------------------------------------------------
// Scratch (device globals; allocation-free per harness rules)
__device__ float g_Weff[DIM*192];                    // [c][p*64+r]
__device__ float g_T[BN*192];                        // [i][p*64+r]
__device__ __nv_bfloat16 g_Qh[(size_t)NBH*NSEQ*HD];  // [bh][l][d] (pre-scaled)
__device__ __nv_bfloat16 g_Ql[(size_t)NBH*NSEQ*HD];
__device__ __nv_bfloat16 g_Kh[(size_t)NBH*NSEQ*HD];
__device__ __nv_bfloat16 g_Kl[(size_t)NBH*NSEQ*HD];
__device__ __nv_bfloat16 g_Vh[(size_t)NBH*NSEQ*HD];  // row-major [l][d]
__device__ __nv_bfloat16 g_Vl[(size_t)NBH*NSEQ*HD];
__device__ __nv_bfloat16 g_AOh[(size_t)BN*DIM];      // [b*l][h*64+d]
__device__ __nv_bfloat16 g_AOl[(size_t)BN*DIM];
__device__ __nv_bfloat16 g_pwh[DIM*DIM];
__device__ __nv_bfloat16 g_pwl[DIM*DIM];

// ---------------------------------------------------------------------------
// warp-mma helpers (baseline PTX, sm_80+: compiles for sm_103 base target)
__device__ __forceinline__ uint32_t smem_u32(const void* p) {
    uint32_t a;
    asm("{ .reg .u64 t; cvta.to.shared.u64 t, %1; cvt.u32.u64 %0, t; }" : "=r"(a) : "l"(p));
    return a;
}
#define LDSM_X4(r0,r1,r2,r3,addr) \
    asm volatile("ldmatrix.sync.aligned.m8n8.x4.shared.b16 {%0,%1,%2,%3}, [%4];" \
        : "=r"(r0), "=r"(r1), "=r"(r2), "=r"(r3) : "r"(addr))
#define LDSM_X4_T(r0,r1,r2,r3,addr) \
    asm volatile("ldmatrix.sync.aligned.m8n8.x4.trans.shared.b16 {%0,%1,%2,%3}, [%4];" \
        : "=r"(r0), "=r"(r1), "=r"(r2), "=r"(r3) : "r"(addr))
#define MMA16816(c, a, b0_, b1_) \
    asm volatile("mma.sync.aligned.m16n8k16.row.col.f32.bf16.bf16.f32 " \
        "{%0,%1,%2,%3}, {%4,%5,%6,%7}, {%8,%9}, {%0,%1,%2,%3};" \
        : "+f"((c)[0]), "+f"((c)[1]), "+f"((c)[2]), "+f"((c)[3]) \
        : "r"((a)[0]), "r"((a)[1]), "r"((a)[2]), "r"((a)[3]), "r"(b0_), "r"(b1_))

__device__ __forceinline__ void split2(float f, __nv_bfloat16& h, __nv_bfloat16& l) {
    h = __float2bfloat16(f);
    l = __float2bfloat16(f - __bfloat162float(h));
}
__device__ __forceinline__ uint32_t packbf2(__nv_bfloat16 a, __nv_bfloat16 b) {
    __nv_bfloat162 t = __halves2bfloat162(a, b);
    return *(uint32_t*)&t;
}
__device__ __forceinline__ void split_pack(float f0, float f1, uint32_t& h, uint32_t& l) {
    __nv_bfloat16 h0, l0, h1, l1;
    split2(f0, h0, l0);
    split2(f1, h1, l1);
    h = packbf2(h0, h1);
    l = packbf2(l0, l1);
}

// ---------------------------------------------------------------------------
// Stage 1: Weff[c, p*64+r] = W1_p[c/64, r] * W2_p[c%64, r]
__global__ void k_build_weff(const float* __restrict__ W1q, const float* __restrict__ W2q,
                             const float* __restrict__ W1k, const float* __restrict__ W2k,
                             const float* __restrict__ W1v, const float* __restrict__ W2v) {
    int idx = blockIdx.x * blockDim.x + threadIdx.x;
    if (idx >= 3 * DIM * RNK) return;
    int p = idx / (DIM * RNK);
    int rem = idx % (DIM * RNK);
    int c = rem / RNK, r = rem % RNK;
    const float* W1 = (p == 0) ? W1q : ((p == 1) ? W1k : W1v);
    const float* W2 = (p == 0) ? W2q : ((p == 1) ? W2k : W2v);
    g_Weff[c * 192 + p * 64 + r] = W1[(c >> 6) * RNK + r] * W2[(c & 63) * RNK + r];
}

__global__ void k_split_pw(const float* __restrict__ pw) {
    int i = blockIdx.x * blockDim.x + threadIdx.x;
    if (i >= DIM * DIM) return;
    split2(pw[i], g_pwh[i], g_pwl[i]);
}

// ---------------------------------------------------------------------------
// Stage 2: T = x @ Weff   [8192,768] x [768,192]  (SIMT fp32)
__global__ void k_gemm_T(const float* __restrict__ x) {
    __shared__ float As[16][128];
    __shared__ float Bs[16][64];
    int tid = threadIdx.x;
    int i0 = blockIdx.x * 128, n0 = blockIdx.y * 64;
    int ty = tid >> 4, tx = tid & 15;
    float acc[8][4] = {};
    for (int k0 = 0; k0 < DIM; k0 += 16) {
#pragma unroll
        for (int t = 0; t < 2; t++) {
            int idx4 = tid + t * 256;
            int r = idx4 >> 2, kq = (idx4 & 3) * 4;
            float4 v = *(const float4*)(x + (size_t)(i0 + r) * DIM + k0 + kq);
            As[kq + 0][r] = v.x; As[kq + 1][r] = v.y; As[kq + 2][r] = v.z; As[kq + 3][r] = v.w;
        }
        {
            int kr = tid >> 4, c4 = (tid & 15) * 4;
            *(float4*)(&Bs[kr][c4]) = *(const float4*)(g_Weff + (k0 + kr) * 192 + n0 + c4);
        }
        __syncthreads();
#pragma unroll
        for (int k = 0; k < 16; k++) {
            float a[8], b[4];
#pragma unroll
            for (int i = 0; i < 8; i++) a[i] = As[k][ty + i * 16];
#pragma unroll
            for (int j = 0; j < 4; j++) b[j] = Bs[k][tx + j * 16];
#pragma unroll
            for (int i = 0; i < 8; i++)
#pragma unroll
                for (int j = 0; j < 4; j++) acc[i][j] += a[i] * b[j];
        }
        __syncthreads();
    }
#pragma unroll
    for (int i = 0; i < 8; i++)
#pragma unroll
        for (int j = 0; j < 4; j++)
            g_T[(size_t)(i0 + ty + i * 16) * 192 + n0 + tx + j * 16] = acc[i][j];
}

// ---------------------------------------------------------------------------
// Stage 3: expand T -> Q/K/V, emit split bf16 (Q scaled; all row-major [l][d])
__global__ void k_expand_split(const float* __restrict__ W0q, const float* __restrict__ W0k,
                               const float* __restrict__ W0v) {
    __shared__ float Ts[64][65];
    __shared__ float Ws[64][65];
    int p = blockIdx.z, h = blockIdx.y;
    int i0 = blockIdx.x * 64;
    const float* W0 = (p == 0) ? W0q : ((p == 1) ? W0k : W0v);
    int tid = threadIdx.x;
    for (int idx4 = tid; idx4 < 1024; idx4 += 256) {
        int r = idx4 >> 4, c4 = (idx4 & 15) * 4;
        float4 v = *(const float4*)(g_T + (size_t)(i0 + r) * 192 + p * 64 + c4);
        Ts[r][c4] = v.x; Ts[r][c4 + 1] = v.y; Ts[r][c4 + 2] = v.z; Ts[r][c4 + 3] = v.w;
    }
    const float* Wbase = W0 + h * 64 * 64;
    for (int idx4 = tid; idx4 < 1024; idx4 += 256) {
        int d = idx4 >> 4, c4 = (idx4 & 15) * 4;
        float4 v = *(const float4*)(Wbase + d * 64 + c4);
        Ws[d][c4] = v.x; Ws[d][c4 + 1] = v.y; Ws[d][c4 + 2] = v.z; Ws[d][c4 + 3] = v.w;
    }
    __syncthreads();
    int ty = tid >> 4, tx = tid & 15;
    float acc[4][4] = {};
#pragma unroll 16
    for (int r = 0; r < 64; r++) {
        float a[4], b[4];
#pragma unroll
        for (int i = 0; i < 4; i++) a[i] = Ts[ty + i * 16][r];
#pragma unroll
        for (int j = 0; j < 4; j++) b[j] = Ws[tx + j * 16][r];
#pragma unroll
        for (int i = 0; i < 4; i++)
#pragma unroll
            for (int j = 0; j < 4; j++) acc[i][j] += a[i] * b[j];
    }
#pragma unroll
    for (int i = 0; i < 4; i++) {
        int row = i0 + ty + i * 16;
        int b_ = row >> 10, l = row & 1023;
        long bh = (long)b_ * NH + h;
        long base = bh * 65536 + (long)l * 64;
#pragma unroll
        for (int j = 0; j < 4; j++) {
            int d = tx + j * 16;
            float f = acc[i][j];
            __nv_bfloat16 hi, lo;
            if (p == 0) {
                split2(f * 0.125f, hi, lo);
                g_Qh[base + d] = hi; g_Ql[base + d] = lo;
            } else if (p == 1) {
                split2(f, hi, lo);
                g_Kh[base + d] = hi; g_Kl[base + d] = lo;
            } else {
                split2(f, hi, lo);
                g_Vh[base + d] = hi; g_Vl[base + d] = lo;
            }
        }
    }
}

// ---------------------------------------------------------------------------
// Stage 4: fused flash attention, mma.sync bf16x3.
// Block = (bh, 128-row q tile), 8 warps, each warp 16 q rows.
// smem: K/V tiles 64 rows x 64 bf16 (PAD=72) x {h,l} = 36864 B.
__global__ void __launch_bounds__(256) k_flash() {
    extern __shared__ __align__(16) char smraw[];
    __nv_bfloat16* sKh = (__nv_bfloat16*)smraw;
    __nv_bfloat16* sKl = sKh + 64 * PAD;
    __nv_bfloat16* sVh = sKl + 64 * PAD;
    __nv_bfloat16* sVl = sVh + 64 * PAD;
    int tid = threadIdx.x, wid = tid >> 5, lane = tid & 31;
    int bh = blockIdx.y, qb = blockIdx.x * 128;
    long base = (long)bh * NSEQ * HD;

    // ---- stage Q tile (hi into sKh+sKl span, lo into sVh+sVl span), extract frags
    {
        __nv_bfloat16* sQh = sKh;  // 128 rows * PAD spans both K regions
        __nv_bfloat16* sQl = sVh;
        for (int i = tid; i < 128 * 8; i += 256) {
            int r = i >> 3, c = (i & 7) * 8;
            *(uint4*)(sQh + r * PAD + c) = *(const uint4*)(g_Qh + base + (long)(qb + r) * 64 + c);
            *(uint4*)(sQl + r * PAD + c) = *(const uint4*)(g_Ql + base + (long)(qb + r) * 64 + c);
        }
    }
    __syncthreads();
    uint32_t qh[4][4], ql[4][4];
    {
        int rowb = wid * 16 + (lane & 15);
        int colb = (lane >> 4) * 8;
#pragma unroll
        for (int c = 0; c < 4; c++) {
            LDSM_X4(qh[c][0], qh[c][1], qh[c][2], qh[c][3],
                    smem_u32(sKh + rowb * PAD + c * 16 + colb));
            LDSM_X4(ql[c][0], ql[c][1], ql[c][2], ql[c][3],
                    smem_u32(sVh + rowb * PAD + c * 16 + colb));
        }
    }
    __syncthreads();

    float m0 = -1e30f, m1 = -1e30f, l0 = 0.f, l1 = 0.f;
    float O[8][4] = {};

    for (int t = 0; t < 16; t++) {
        // ---- stage K/V block (64 rows)
        for (int i = tid; i < 64 * 8; i += 256) {
            int r = i >> 3, c = (i & 7) * 8;
            long g = base + (long)(t * 64 + r) * 64 + c;
            *(uint4*)(sKh + r * PAD + c) = *(const uint4*)(g_Kh + g);
            *(uint4*)(sKl + r * PAD + c) = *(const uint4*)(g_Kl + g);
            *(uint4*)(sVh + r * PAD + c) = *(const uint4*)(g_Vh + g);
            *(uint4*)(sVl + r * PAD + c) = *(const uint4*)(g_Vl + g);
        }
        __syncthreads();

        // ---- S = Q K^T (3-pass)
        float S[8][4] = {};
        {
            int rbase = (lane & 7);
            int cbase = (lane >> 3) * 8;
#pragma unroll
            for (int j = 0; j < 8; j++) {
                uint32_t off = (uint32_t)((8 * j + rbase) * PAD + cbase);
                uint32_t bh01[4], bh23[4], bl01[4], bl23[4];
                LDSM_X4(bh01[0], bh01[1], bh01[2], bh01[3], smem_u32(sKh + off));
                LDSM_X4(bh23[0], bh23[1], bh23[2], bh23[3], smem_u32(sKh + off + 32));
                LDSM_X4(bl01[0], bl01[1], bl01[2], bl01[3], smem_u32(sKl + off));
                LDSM_X4(bl23[0], bl23[1], bl23[2], bl23[3], smem_u32(sKl + off + 32));
                MMA16816(S[j], qh[0], bh01[0], bh01[1]);
                MMA16816(S[j], qh[1], bh01[2], bh01[3]);
                MMA16816(S[j], qh[2], bh23[0], bh23[1]);
                MMA16816(S[j], qh[3], bh23[2], bh23[3]);
                MMA16816(S[j], qh[0], bl01[0], bl01[1]);
                MMA16816(S[j], qh[1], bl01[2], bl01[3]);
                MMA16816(S[j], qh[2], bl23[0], bl23[1]);
                MMA16816(S[j], qh[3], bl23[2], bl23[3]);
                MMA16816(S[j], ql[0], bh01[0], bh01[1]);
                MMA16816(S[j], ql[1], bh01[2], bh01[3]);
                MMA16816(S[j], ql[2], bh23[0], bh23[1]);
                MMA16816(S[j], ql[3], bh23[2], bh23[3]);
            }
        }

        // ---- online softmax (rows g, g+8; quad = 4 lanes share a row)
        float mx0 = -1e30f, mx1 = -1e30f;
#pragma unroll
        for (int j = 0; j < 8; j++) {
            mx0 = fmaxf(mx0, fmaxf(S[j][0], S[j][1]));
            mx1 = fmaxf(mx1, fmaxf(S[j][2], S[j][3]));
        }
        mx0 = fmaxf(mx0, __shfl_xor_sync(~0u, mx0, 1));
        mx0 = fmaxf(mx0, __shfl_xor_sync(~0u, mx0, 2));
        mx1 = fmaxf(mx1, __shfl_xor_sync(~0u, mx1, 1));
        mx1 = fmaxf(mx1, __shfl_xor_sync(~0u, mx1, 2));
        float mn0 = fmaxf(m0, mx0), mn1 = fmaxf(m1, mx1);
        float a0 = __expf(m0 - mn0), a1 = __expf(m1 - mn1);
        float rs0 = 0.f, rs1 = 0.f;
#pragma unroll
        for (int j = 0; j < 8; j++) {
            S[j][0] = __expf(S[j][0] - mn0); S[j][1] = __expf(S[j][1] - mn0);
            S[j][2] = __expf(S[j][2] - mn1); S[j][3] = __expf(S[j][3] - mn1);
            rs0 += S[j][0] + S[j][1];
            rs1 += S[j][2] + S[j][3];
        }
        rs0 += __shfl_xor_sync(~0u, rs0, 1); rs0 += __shfl_xor_sync(~0u, rs0, 2);
        rs1 += __shfl_xor_sync(~0u, rs1, 1); rs1 += __shfl_xor_sync(~0u, rs1, 2);
        l0 = l0 * a0 + rs0; l1 = l1 * a1 + rs1;
        m0 = mn0; m1 = mn1;
#pragma unroll
        for (int j = 0; j < 8; j++) {
            O[j][0] *= a0; O[j][1] *= a0; O[j][2] *= a1; O[j][3] *= a1;
        }

        // ---- P fragments (A-layout) from S regs, split hi/lo
        uint32_t ph[4][4], pl[4][4];
#pragma unroll
        for (int c = 0; c < 4; c++) {
            split_pack(S[2 * c][0],     S[2 * c][1],     ph[c][0], pl[c][0]);
            split_pack(S[2 * c][2],     S[2 * c][3],     ph[c][1], pl[c][1]);
            split_pack(S[2 * c + 1][0], S[2 * c + 1][1], ph[c][2], pl[c][2]);
            split_pack(S[2 * c + 1][2], S[2 * c + 1][3], ph[c][3], pl[c][3]);
        }

        // ---- O += P V (3-pass); V B-frags via ldmatrix.trans
        {
            int rbase = (lane & 15);
            int cb2 = (lane >> 4) * 8;
#pragma unroll
            for (int jj = 0; jj < 8; jj += 2) {
#pragma unroll
                for (int c = 0; c < 4; c++) {
                    uint32_t off = (uint32_t)((c * 16 + rbase) * PAD + jj * 8 + cb2);
                    uint32_t vh[4], vl[4];
                    LDSM_X4_T(vh[0], vh[1], vh[2], vh[3], smem_u32(sVh + off));
                    LDSM_X4_T(vl[0], vl[1], vl[2], vl[3], smem_u32(sVl + off));
                    MMA16816(O[jj],     ph[c], vh[0], vh[1]);
                    MMA16816(O[jj],     ph[c], vl[0], vl[1]);
                    MMA16816(O[jj],     pl[c], vh[0], vh[1]);
                    MMA16816(O[jj + 1], ph[c], vh[2], vh[3]);
                    MMA16816(O[jj + 1], ph[c], vl[2], vl[3]);
                    MMA16816(O[jj + 1], pl[c], vh[2], vh[3]);
                }
            }
        }
        __syncthreads();
    }

    // ---- epilogue: normalize, split, write AO
    float inv0 = 1.f / l0, inv1 = 1.f / l1;
    int g = lane >> 2, tg = lane & 3;
    int b_ = bh / NH, h = bh % NH;
    int r0 = qb + wid * 16 + g, r1 = r0 + 8;
    long ob0 = ((long)b_ * NSEQ + r0) * DIM + h * HD;
    long ob1 = ((long)b_ * NSEQ + r1) * DIM + h * HD;
#pragma unroll
    for (int j = 0; j < 8; j++) {
        int d = 8 * j + tg * 2;
        uint32_t hh, ll;
        split_pack(O[j][0] * inv0, O[j][1] * inv0, hh, ll);
        *(uint32_t*)(g_AOh + ob0 + d) = hh;
        *(uint32_t*)(g_AOl + ob0 + d) = ll;
        split_pack(O[j][2] * inv1, O[j][3] * inv1, hh, ll);
        *(uint32_t*)(g_AOh + ob1 + d) = hh;
        *(uint32_t*)(g_AOl + ob1 + d) = ll;
    }
}

// ---------------------------------------------------------------------------
// Stage 5: out = AO @ pw^T + pb  (mma.sync bf16x3, 128x128 tiles)
__global__ void __launch_bounds__(256) k_proj_mma(const float* __restrict__ pb,
                                                  float* __restrict__ out) {
    extern __shared__ __align__(16) char smraw[];
    __nv_bfloat16* sAh = (__nv_bfloat16*)smraw;          // 128 x PAD
    __nv_bfloat16* sAl = sAh + 128 * PAD;
    __nv_bfloat16* sBh = sAl + 128 * PAD;
    __nv_bfloat16* sBl = sBh + 128 * PAD;
    int tid = threadIdx.x, wid = tid >> 5, lane = tid & 31;
    int m0 = blockIdx.x * 128, n0 = blockIdx.y * 128;
    float C[16][4] = {};

    for (int kb = 0; kb < 12; kb++) {
        for (int i = tid; i < 128 * 8; i += 256) {
            int r = i >> 3, c = (i & 7) * 8;
            long ga = (long)(m0 + r) * DIM + kb * 64 + c;
            long gb = (long)(n0 + r) * DIM + kb * 64 + c;
            *(uint4*)(sAh + r * PAD + c) = *(const uint4*)(g_AOh + ga);
            *(uint4*)(sAl + r * PAD + c) = *(const uint4*)(g_AOl + ga);
            *(uint4*)(sBh + r * PAD + c) = *(const uint4*)(g_pwh + gb);
            *(uint4*)(sBl + r * PAD + c) = *(const uint4*)(g_pwl + gb);
        }
        __syncthreads();

        uint32_t ah[4][4], al[4][4];
        {
            int rowb = wid * 16 + (lane & 15);
            int colb = (lane >> 4) * 8;
#pragma unroll
            for (int c = 0; c < 4; c++) {
                LDSM_X4(ah[c][0], ah[c][1], ah[c][2], ah[c][3],
                        smem_u32(sAh + rowb * PAD + c * 16 + colb));
                LDSM_X4(al[c][0], al[c][1], al[c][2], al[c][3],
                        smem_u32(sAl + rowb * PAD + c * 16 + colb));
            }
        }
        {
            int rbase = (lane & 7);
            int cbase = (lane >> 3) * 8;
#pragma unroll
            for (int j = 0; j < 16; j++) {
                uint32_t off = (uint32_t)((8 * j + rbase) * PAD + cbase);
                uint32_t bh01[4], bh23[4], bl01[4], bl23[4];
                LDSM_X4(bh01[0], bh01[1], bh01[2], bh01[3], smem_u32(sBh + off));
                LDSM_X4(bh23[0], bh23[1], bh23[2], bh23[3], smem_u32(sBh + off + 32));
                LDSM_X4(bl01[0], bl01[1], bl01[2], bl01[3], smem_u32(sBl + off));
                LDSM_X4(bl23[0], bl23[1], bl23[2], bl23[3], smem_u32(sBl + off + 32));
                MMA16816(C[j], ah[0], bh01[0], bh01[1]);
                MMA16816(C[j], ah[1], bh01[2], bh01[3]);
                MMA16816(C[j], ah[2], bh23[0], bh23[1]);
                MMA16816(C[j], ah[3], bh23[2], bh23[3]);
                MMA16816(C[j], ah[0], bl01[0], bl01[1]);
                MMA16816(C[j], ah[1], bl01[2], bl01[3]);
                MMA16816(C[j], ah[2], bl23[0], bl23[1]);
                MMA16816(C[j], ah[3], bl23[2], bl23[3]);
                MMA16816(C[j], al[0], bh01[0], bh01[1]);
                MMA16816(C[j], al[1], bh01[2], bh01[3]);
                MMA16816(C[j], al[2], bh23[0], bh23[1]);
                MMA16816(C[j], al[3], bh23[2], bh23[3]);
            }
        }
        __syncthreads();
    }

    int g = lane >> 2, tg = lane & 3;
    int r0 = m0 + wid * 16 + g, r1 = r0 + 8;
#pragma unroll
    for (int j = 0; j < 16; j++) {
        int col = n0 + 8 * j + tg * 2;
        float b0 = pb[col], b1 = pb[col + 1];
        *(float2*)(out + (long)r0 * DIM + col) = make_float2(C[j][0] + b0, C[j][1] + b1);
        *(float2*)(out + (long)r1 * DIM + col) = make_float2(C[j][2] + b0, C[j][3] + b1);
    }
}

// ---------------------------------------------------------------------------
extern "C" void kernel_launch(void* const* d_in, const int* in_sizes, int n_in,
                              void* d_out, int out_size) {
    const float* x   = (const float*)d_in[0];
    const float* WQ0 = (const float*)d_in[1];
    const float* WQ1 = (const float*)d_in[2];
    const float* WQ2 = (const float*)d_in[3];
    const float* WK0 = (const float*)d_in[4];
    const float* WK1 = (const float*)d_in[5];
    const float* WK2 = (const float*)d_in[6];
    const float* WV0 = (const float*)d_in[7];
    const float* WV1 = (const float*)d_in[8];
    const float* WV2 = (const float*)d_in[9];
    const float* pw  = (const float*)d_in[10];
    const float* pb  = (const float*)d_in[11];
    float* out = (float*)d_out;

    const int SM_FLASH = 4 * 64 * PAD * 2;   // 36864 B
    const int SM_PROJ  = 4 * 128 * PAD * 2;  // 73728 B
    cudaFuncSetAttribute(k_proj_mma, cudaFuncAttributeMaxDynamicSharedMemorySize, SM_PROJ);

    k_build_weff<<<(3 * DIM * RNK + 255) / 256, 256>>>(WQ1, WQ2, WK1, WK2, WV1, WV2);
    k_split_pw<<<(DIM * DIM + 255) / 256, 256>>>(pw);
    k_gemm_T<<<dim3(BN / 128, 3), 256>>>(x);
    k_expand_split<<<dim3(BN / 64, NH, 3), 256>>>(WQ0, WK0, WV0);
    k_flash<<<dim3(NSEQ / 128, NBH), 256, SM_FLASH>>>();
    k_proj_mma<<<dim3(BN / 128, DIM / 128), 256, SM_PROJ>>>(pb, out);
}

// round 4
// speedup vs baseline: 2.4680x; 1.3345x over previous
#include <cuda_runtime.h>
#include <cuda_bf16.h>
#include <cstdint>

#define BSZ  8
#define NSEQ 1024
#define DIM  768
#define NH   12
#define HD   64
#define RNK  64
#define BN   (BSZ*NSEQ)          /* 8192 */
#define NBH  (BSZ*NH)            /* 96 */
#define PAD  72                  /* padded smem row stride in bf16 */

// ---------------------------------------------------------------------------
// Scratch (device globals; allocation-free per harness rules)
__device__ __nv_bfloat16 g_xh[(size_t)BN*DIM];
__device__ __nv_bfloat16 g_xl[(size_t)BN*DIM];
__device__ __nv_bfloat16 g_Wefh[192*DIM];            // [n=p*64+r][k=dim]
__device__ __nv_bfloat16 g_Wefl[192*DIM];
__device__ __nv_bfloat16 g_Th[(size_t)BN*192];       // [i][p*64+r]
__device__ __nv_bfloat16 g_Tl[(size_t)BN*192];
__device__ __nv_bfloat16 g_Qh[(size_t)NBH*NSEQ*HD];  // [bh][l][d] (pre-scaled)
__device__ __nv_bfloat16 g_Ql[(size_t)NBH*NSEQ*HD];
__device__ __nv_bfloat16 g_Kh[(size_t)NBH*NSEQ*HD];
__device__ __nv_bfloat16 g_Kl[(size_t)NBH*NSEQ*HD];
__device__ __nv_bfloat16 g_Vh[(size_t)NBH*NSEQ*HD];  // row-major [l][d]
__device__ __nv_bfloat16 g_Vl[(size_t)NBH*NSEQ*HD];
__device__ __nv_bfloat16 g_AOh[(size_t)BN*DIM];      // [b*l][h*64+d]
__device__ __nv_bfloat16 g_AOl[(size_t)BN*DIM];
__device__ __nv_bfloat16 g_pwh[DIM*DIM];
__device__ __nv_bfloat16 g_pwl[DIM*DIM];

// ---------------------------------------------------------------------------
// helpers (baseline PTX, sm_80+)
__device__ __forceinline__ uint32_t smem_u32(const void* p) {
    uint32_t a;
    asm("{ .reg .u64 t; cvta.to.shared.u64 t, %1; cvt.u32.u64 %0, t; }" : "=r"(a) : "l"(p));
    return a;
}
#define LDSM_X4(r0,r1,r2,r3,addr) \
    asm volatile("ldmatrix.sync.aligned.m8n8.x4.shared.b16 {%0,%1,%2,%3}, [%4];" \
        : "=r"(r0), "=r"(r1), "=r"(r2), "=r"(r3) : "r"(addr))
#define LDSM_X4_T(r0,r1,r2,r3,addr) \
    asm volatile("ldmatrix.sync.aligned.m8n8.x4.trans.shared.b16 {%0,%1,%2,%3}, [%4];" \
        : "=r"(r0), "=r"(r1), "=r"(r2), "=r"(r3) : "r"(addr))
#define MMA16816(c, a, b0_, b1_) \
    asm volatile("mma.sync.aligned.m16n8k16.row.col.f32.bf16.bf16.f32 " \
        "{%0,%1,%2,%3}, {%4,%5,%6,%7}, {%8,%9}, {%0,%1,%2,%3};" \
        : "+f"((c)[0]), "+f"((c)[1]), "+f"((c)[2]), "+f"((c)[3]) \
        : "r"((a)[0]), "r"((a)[1]), "r"((a)[2]), "r"((a)[3]), "r"(b0_), "r"(b1_))
#define CP16(dst, src) \
    asm volatile("cp.async.cg.shared.global [%0], [%1], 16;" :: "r"(dst), "l"(src))
#define CPCOMMIT() asm volatile("cp.async.commit_group;" ::: "memory")
#define CPWAIT1()  asm volatile("cp.async.wait_group 1;" ::: "memory")
#define CPWAIT0()  asm volatile("cp.async.wait_group 0;" ::: "memory")

__device__ __forceinline__ void split2(float f, __nv_bfloat16& h, __nv_bfloat16& l) {
    h = __float2bfloat16(f);
    l = __float2bfloat16(f - __bfloat162float(h));
}
__device__ __forceinline__ uint32_t packbf2(__nv_bfloat16 a, __nv_bfloat16 b) {
    __nv_bfloat162 t = __halves2bfloat162(a, b);
    return *(uint32_t*)&t;
}
__device__ __forceinline__ void split_pack(float f0, float f1, uint32_t& h, uint32_t& l) {
    __nv_bfloat16 h0, l0, h1, l1;
    split2(f0, h0, l0);
    split2(f1, h1, l1);
    h = packbf2(h0, h1);
    l = packbf2(l0, l1);
}

// ---------------------------------------------------------------------------
// Stage 0: split x into bf16 hi/lo
__global__ void k_split_x(const float* __restrict__ x) {
    int i = blockIdx.x * blockDim.x + threadIdx.x;
    if (i >= BN * DIM / 2) return;
    float2 v = *(const float2*)(x + 2 * (size_t)i);
    uint32_t h, l;
    split_pack(v.x, v.y, h, l);
    *(uint32_t*)(g_xh + 2 * (size_t)i) = h;
    *(uint32_t*)(g_xl + 2 * (size_t)i) = l;
}

// Stage 1: Weff (transposed, split): g_Wef[n=p*64+r][k=c] = W1_p[c/64,r]*W2_p[c%64,r]
__global__ void k_build_weff(const float* __restrict__ W1q, const float* __restrict__ W2q,
                             const float* __restrict__ W1k, const float* __restrict__ W2k,
                             const float* __restrict__ W1v, const float* __restrict__ W2v) {
    int idx = blockIdx.x * blockDim.x + threadIdx.x;
    if (idx >= 3 * DIM * RNK) return;
    int p = idx / (DIM * RNK);
    int rem = idx % (DIM * RNK);
    int c = rem / RNK, r = rem % RNK;
    const float* W1 = (p == 0) ? W1q : ((p == 1) ? W1k : W1v);
    const float* W2 = (p == 0) ? W2q : ((p == 1) ? W2k : W2v);
    float f = W1[(c >> 6) * RNK + r] * W2[(c & 63) * RNK + r];
    __nv_bfloat16 h, l;
    split2(f, h, l);
    g_Wefh[(p * 64 + r) * DIM + c] = h;
    g_Wefl[(p * 64 + r) * DIM + c] = l;
}

__global__ void k_split_pw(const float* __restrict__ pw) {
    int i = blockIdx.x * blockDim.x + threadIdx.x;
    if (i >= DIM * DIM) return;
    split2(pw[i], g_pwh[i], g_pwl[i]);
}

// ---------------------------------------------------------------------------
// Stage 2: T = x @ Weff^T-layout (mma bf16x3). M=128, N=64, K=768 (12 chunks).
// Epilogue writes T as split bf16.
__global__ void __launch_bounds__(256) k_gemm_T_mma() {
    extern __shared__ __align__(16) char smraw[];
    __nv_bfloat16* sAh = (__nv_bfloat16*)smraw;          // 128 x PAD
    __nv_bfloat16* sAl = sAh + 128 * PAD;
    __nv_bfloat16* sBh = sAl + 128 * PAD;                // 64 x PAD
    __nv_bfloat16* sBl = sBh + 64 * PAD;
    int tid = threadIdx.x, wid = tid >> 5, lane = tid & 31;
    int m0 = blockIdx.x * 128, n0 = blockIdx.y * 64;
    float C[8][4] = {};

    for (int kb = 0; kb < 12; kb++) {
        for (int i = tid; i < 128 * 8; i += 256) {
            int r = i >> 3, c = (i & 7) * 8;
            long ga = (long)(m0 + r) * DIM + kb * 64 + c;
            *(uint4*)(sAh + r * PAD + c) = *(const uint4*)(g_xh + ga);
            *(uint4*)(sAl + r * PAD + c) = *(const uint4*)(g_xl + ga);
        }
        for (int i = tid; i < 64 * 8; i += 256) {
            int r = i >> 3, c = (i & 7) * 8;
            long gb = (long)(n0 + r) * DIM + kb * 64 + c;
            *(uint4*)(sBh + r * PAD + c) = *(const uint4*)(g_Wefh + gb);
            *(uint4*)(sBl + r * PAD + c) = *(const uint4*)(g_Wefl + gb);
        }
        __syncthreads();
        uint32_t ah[4][4], al[4][4];
        {
            int rowb = wid * 16 + (lane & 15);
            int colb = (lane >> 4) * 8;
#pragma unroll
            for (int c = 0; c < 4; c++) {
                LDSM_X4(ah[c][0], ah[c][1], ah[c][2], ah[c][3],
                        smem_u32(sAh + rowb * PAD + c * 16 + colb));
                LDSM_X4(al[c][0], al[c][1], al[c][2], al[c][3],
                        smem_u32(sAl + rowb * PAD + c * 16 + colb));
            }
        }
        {
            int rbase = (lane & 7);
            int cbase = (lane >> 3) * 8;
#pragma unroll
            for (int j = 0; j < 8; j++) {
                uint32_t off = (uint32_t)((8 * j + rbase) * PAD + cbase);
                uint32_t bh01[4], bh23[4], bl01[4], bl23[4];
                LDSM_X4(bh01[0], bh01[1], bh01[2], bh01[3], smem_u32(sBh + off));
                LDSM_X4(bh23[0], bh23[1], bh23[2], bh23[3], smem_u32(sBh + off + 32));
                LDSM_X4(bl01[0], bl01[1], bl01[2], bl01[3], smem_u32(sBl + off));
                LDSM_X4(bl23[0], bl23[1], bl23[2], bl23[3], smem_u32(sBl + off + 32));
                MMA16816(C[j], ah[0], bh01[0], bh01[1]);
                MMA16816(C[j], ah[1], bh01[2], bh01[3]);
                MMA16816(C[j], ah[2], bh23[0], bh23[1]);
                MMA16816(C[j], ah[3], bh23[2], bh23[3]);
                MMA16816(C[j], ah[0], bl01[0], bl01[1]);
                MMA16816(C[j], ah[1], bl01[2], bl01[3]);
                MMA16816(C[j], ah[2], bl23[0], bl23[1]);
                MMA16816(C[j], ah[3], bl23[2], bl23[3]);
                MMA16816(C[j], al[0], bh01[0], bh01[1]);
                MMA16816(C[j], al[1], bh01[2], bh01[3]);
                MMA16816(C[j], al[2], bh23[0], bh23[1]);
                MMA16816(C[j], al[3], bh23[2], bh23[3]);
            }
        }
        __syncthreads();
    }
    int g = lane >> 2, tg = lane & 3;
    int r0 = m0 + wid * 16 + g, r1 = r0 + 8;
#pragma unroll
    for (int j = 0; j < 8; j++) {
        int col = n0 + 8 * j + tg * 2;
        uint32_t hh, ll;
        split_pack(C[j][0], C[j][1], hh, ll);
        *(uint32_t*)(g_Th + (long)r0 * 192 + col) = hh;
        *(uint32_t*)(g_Tl + (long)r0 * 192 + col) = ll;
        split_pack(C[j][2], C[j][3], hh, ll);
        *(uint32_t*)(g_Th + (long)r1 * 192 + col) = hh;
        *(uint32_t*)(g_Tl + (long)r1 * 192 + col) = ll;
    }
}

// ---------------------------------------------------------------------------
// Stage 3: Q/K/V = T_p @ W0_h^T (mma bf16x3). M=128, N=64, K=64.
__global__ void __launch_bounds__(256) k_expand_mma(const float* __restrict__ W0q,
                                                    const float* __restrict__ W0k,
                                                    const float* __restrict__ W0v) {
    extern __shared__ __align__(16) char smraw[];
    __nv_bfloat16* sAh = (__nv_bfloat16*)smraw;          // 128 x PAD
    __nv_bfloat16* sAl = sAh + 128 * PAD;
    __nv_bfloat16* sBh = sAl + 128 * PAD;                // 64 x PAD
    __nv_bfloat16* sBl = sBh + 64 * PAD;
    int p = blockIdx.z, h = blockIdx.y;
    int m0 = blockIdx.x * 128;
    const float* W0 = (p == 0) ? W0q : ((p == 1) ? W0k : W0v);
    int tid = threadIdx.x, wid = tid >> 5, lane = tid & 31;

    for (int i = tid; i < 128 * 8; i += 256) {
        int r = i >> 3, c = (i & 7) * 8;
        long ga = (long)(m0 + r) * 192 + p * 64 + c;
        *(uint4*)(sAh + r * PAD + c) = *(const uint4*)(g_Th + ga);
        *(uint4*)(sAl + r * PAD + c) = *(const uint4*)(g_Tl + ga);
    }
    for (int i = tid; i < 64 * 16; i += 256) {
        int d = i >> 4, c4 = (i & 15) * 4;
        float4 v = *(const float4*)(W0 + (long)(h * 64 + d) * 64 + c4);
        __nv_bfloat16 hh, ll;
        split2(v.x, hh, ll); sBh[d * PAD + c4]     = hh; sBl[d * PAD + c4]     = ll;
        split2(v.y, hh, ll); sBh[d * PAD + c4 + 1] = hh; sBl[d * PAD + c4 + 1] = ll;
        split2(v.z, hh, ll); sBh[d * PAD + c4 + 2] = hh; sBl[d * PAD + c4 + 2] = ll;
        split2(v.w, hh, ll); sBh[d * PAD + c4 + 3] = hh; sBl[d * PAD + c4 + 3] = ll;
    }
    __syncthreads();

    float C[8][4] = {};
    uint32_t ah[4][4], al[4][4];
    {
        int rowb = wid * 16 + (lane & 15);
        int colb = (lane >> 4) * 8;
#pragma unroll
        for (int c = 0; c < 4; c++) {
            LDSM_X4(ah[c][0], ah[c][1], ah[c][2], ah[c][3],
                    smem_u32(sAh + rowb * PAD + c * 16 + colb));
            LDSM_X4(al[c][0], al[c][1], al[c][2], al[c][3],
                    smem_u32(sAl + rowb * PAD + c * 16 + colb));
        }
    }
    {
        int rbase = (lane & 7);
        int cbase = (lane >> 3) * 8;
#pragma unroll
        for (int j = 0; j < 8; j++) {
            uint32_t off = (uint32_t)((8 * j + rbase) * PAD + cbase);
            uint32_t bh01[4], bh23[4], bl01[4], bl23[4];
            LDSM_X4(bh01[0], bh01[1], bh01[2], bh01[3], smem_u32(sBh + off));
            LDSM_X4(bh23[0], bh23[1], bh23[2], bh23[3], smem_u32(sBh + off + 32));
            LDSM_X4(bl01[0], bl01[1], bl01[2], bl01[3], smem_u32(sBl + off));
            LDSM_X4(bl23[0], bl23[1], bl23[2], bl23[3], smem_u32(sBl + off + 32));
            MMA16816(C[j], ah[0], bh01[0], bh01[1]);
            MMA16816(C[j], ah[1], bh01[2], bh01[3]);
            MMA16816(C[j], ah[2], bh23[0], bh23[1]);
            MMA16816(C[j], ah[3], bh23[2], bh23[3]);
            MMA16816(C[j], ah[0], bl01[0], bl01[1]);
            MMA16816(C[j], ah[1], bl01[2], bl01[3]);
            MMA16816(C[j], ah[2], bl23[0], bl23[1]);
            MMA16816(C[j], ah[3], bl23[2], bl23[3]);
            MMA16816(C[j], al[0], bh01[0], bh01[1]);
            MMA16816(C[j], al[1], bh01[2], bh01[3]);
            MMA16816(C[j], al[2], bh23[0], bh23[1]);
            MMA16816(C[j], al[3], bh23[2], bh23[3]);
        }
    }

    int g = lane >> 2, tg = lane & 3;
    float sc = (p == 0) ? 0.125f : 1.0f;
    __nv_bfloat16* gh = (p == 0) ? g_Qh : ((p == 1) ? g_Kh : g_Vh);
    __nv_bfloat16* gl = (p == 0) ? g_Ql : ((p == 1) ? g_Kl : g_Vl);
#pragma unroll
    for (int rr = 0; rr < 2; rr++) {
        int row = m0 + wid * 16 + g + rr * 8;
        int b_ = row >> 10, l = row & 1023;
        long base = ((long)b_ * NH + h) * 65536 + (long)l * 64;
#pragma unroll
        for (int j = 0; j < 8; j++) {
            int d = 8 * j + tg * 2;
            uint32_t hh, ll;
            split_pack(C[j][2 * rr] * sc, C[j][2 * rr + 1] * sc, hh, ll);
            *(uint32_t*)(gh + base + d) = hh;
            *(uint32_t*)(gl + base + d) = ll;
        }
    }
}

// ---------------------------------------------------------------------------
// Stage 4: fused flash attention, mma.sync bf16x3, cp.async double-buffered.
// Block = (bh, 128-row q tile), 8 warps x 16 q rows. Buf = 4 x 64 x PAD bf16.
#define FBUF (4 * 64 * PAD * 2)   /* 36864 B per buffer */
__global__ void __launch_bounds__(256) k_flash() {
    extern __shared__ __align__(16) char smraw[];
    int tid = threadIdx.x, wid = tid >> 5, lane = tid & 31;
    int bh = blockIdx.y, qb = blockIdx.x * 128;
    long base = (long)bh * NSEQ * HD;
    uint32_t sb = smem_u32(smraw);

    // ---- stage Q tile into buf0 region, extract frags
    {
        __nv_bfloat16* sQh = (__nv_bfloat16*)smraw;
        __nv_bfloat16* sQl = sQh + 128 * PAD;
        for (int i = tid; i < 128 * 8; i += 256) {
            int r = i >> 3, c = (i & 7) * 8;
            *(uint4*)(sQh + r * PAD + c) = *(const uint4*)(g_Qh + base + (long)(qb + r) * 64 + c);
            *(uint4*)(sQl + r * PAD + c) = *(const uint4*)(g_Ql + base + (long)(qb + r) * 64 + c);
        }
    }
    __syncthreads();
    uint32_t qh[4][4], ql[4][4];
    {
        __nv_bfloat16* sQh = (__nv_bfloat16*)smraw;
        __nv_bfloat16* sQl = sQh + 128 * PAD;
        int rowb = wid * 16 + (lane & 15);
        int colb = (lane >> 4) * 8;
#pragma unroll
        for (int c = 0; c < 4; c++) {
            LDSM_X4(qh[c][0], qh[c][1], qh[c][2], qh[c][3],
                    smem_u32(sQh + rowb * PAD + c * 16 + colb));
            LDSM_X4(ql[c][0], ql[c][1], ql[c][2], ql[c][3],
                    smem_u32(sQl + rowb * PAD + c * 16 + colb));
        }
    }
    __syncthreads();

    // ---- prefetch t=0 into buf0
    {
        long g0 = base;
#pragma unroll
        for (int a = 0; a < 2; a++) {
            const __nv_bfloat16* srcs[4] = {g_Kh + g0, g_Kl + g0, g_Vh + g0, g_Vl + g0};
            (void)srcs; break;
        }
        for (int i = tid; i < 64 * 8; i += 256) {
            int r = i >> 3, c = (i & 7) * 8;
            uint32_t doff = (uint32_t)((r * PAD + c) * 2);
            long g = base + (long)r * 64 + c;
            CP16(sb + 0 * 9216 + doff, g_Kh + g);
            CP16(sb + 1 * 9216 + doff, g_Kl + g);
            CP16(sb + 2 * 9216 + doff, g_Vh + g);
            CP16(sb + 3 * 9216 + doff, g_Vl + g);
        }
        CPCOMMIT();
    }

    float m0 = -1e30f, m1 = -1e30f, l0 = 0.f, l1 = 0.f;
    float O[8][4] = {};

    for (int t = 0; t < 16; t++) {
        // prefetch t+1 into other buffer
        if (t < 15) {
            uint32_t dbase = sb + ((t + 1) & 1) * FBUF;
            long gb = base + (long)(t + 1) * 64 * 64;
            for (int i = tid; i < 64 * 8; i += 256) {
                int r = i >> 3, c = (i & 7) * 8;
                uint32_t doff = (uint32_t)((r * PAD + c) * 2);
                long g = gb + (long)r * 64 + c;
                CP16(dbase + 0 * 9216 + doff, g_Kh + g);
                CP16(dbase + 1 * 9216 + doff, g_Kl + g);
                CP16(dbase + 2 * 9216 + doff, g_Vh + g);
                CP16(dbase + 3 * 9216 + doff, g_Vl + g);
            }
            CPCOMMIT();
            CPWAIT1();
        } else {
            CPWAIT0();
        }
        __syncthreads();

        __nv_bfloat16* bufp = (__nv_bfloat16*)(smraw + (t & 1) * FBUF);
        __nv_bfloat16* sKh = bufp;
        __nv_bfloat16* sKl = sKh + 64 * PAD;
        __nv_bfloat16* sVh = sKl + 64 * PAD;
        __nv_bfloat16* sVl = sVh + 64 * PAD;

        // ---- S = Q K^T (3-pass)
        float S[8][4] = {};
        {
            int rbase = (lane & 7);
            int cbase = (lane >> 3) * 8;
#pragma unroll
            for (int j = 0; j < 8; j++) {
                uint32_t off = (uint32_t)((8 * j + rbase) * PAD + cbase);
                uint32_t bh01[4], bh23[4], bl01[4], bl23[4];
                LDSM_X4(bh01[0], bh01[1], bh01[2], bh01[3], smem_u32(sKh + off));
                LDSM_X4(bh23[0], bh23[1], bh23[2], bh23[3], smem_u32(sKh + off + 32));
                LDSM_X4(bl01[0], bl01[1], bl01[2], bl01[3], smem_u32(sKl + off));
                LDSM_X4(bl23[0], bl23[1], bl23[2], bl23[3], smem_u32(sKl + off + 32));
                MMA16816(S[j], qh[0], bh01[0], bh01[1]);
                MMA16816(S[j], qh[1], bh01[2], bh01[3]);
                MMA16816(S[j], qh[2], bh23[0], bh23[1]);
                MMA16816(S[j], qh[3], bh23[2], bh23[3]);
                MMA16816(S[j], qh[0], bl01[0], bl01[1]);
                MMA16816(S[j], qh[1], bl01[2], bl01[3]);
                MMA16816(S[j], qh[2], bl23[0], bl23[1]);
                MMA16816(S[j], qh[3], bl23[2], bl23[3]);
                MMA16816(S[j], ql[0], bh01[0], bh01[1]);
                MMA16816(S[j], ql[1], bh01[2], bh01[3]);
                MMA16816(S[j], ql[2], bh23[0], bh23[1]);
                MMA16816(S[j], ql[3], bh23[2], bh23[3]);
            }
        }

        // ---- online softmax
        float mx0 = -1e30f, mx1 = -1e30f;
#pragma unroll
        for (int j = 0; j < 8; j++) {
            mx0 = fmaxf(mx0, fmaxf(S[j][0], S[j][1]));
            mx1 = fmaxf(mx1, fmaxf(S[j][2], S[j][3]));
        }
        mx0 = fmaxf(mx0, __shfl_xor_sync(~0u, mx0, 1));
        mx0 = fmaxf(mx0, __shfl_xor_sync(~0u, mx0, 2));
        mx1 = fmaxf(mx1, __shfl_xor_sync(~0u, mx1, 1));
        mx1 = fmaxf(mx1, __shfl_xor_sync(~0u, mx1, 2));
        float mn0 = fmaxf(m0, mx0), mn1 = fmaxf(m1, mx1);
        float a0 = __expf(m0 - mn0), a1 = __expf(m1 - mn1);
        float rs0 = 0.f, rs1 = 0.f;
#pragma unroll
        for (int j = 0; j < 8; j++) {
            S[j][0] = __expf(S[j][0] - mn0); S[j][1] = __expf(S[j][1] - mn0);
            S[j][2] = __expf(S[j][2] - mn1); S[j][3] = __expf(S[j][3] - mn1);
            rs0 += S[j][0] + S[j][1];
            rs1 += S[j][2] + S[j][3];
        }
        rs0 += __shfl_xor_sync(~0u, rs0, 1); rs0 += __shfl_xor_sync(~0u, rs0, 2);
        rs1 += __shfl_xor_sync(~0u, rs1, 1); rs1 += __shfl_xor_sync(~0u, rs1, 2);
        l0 = l0 * a0 + rs0; l1 = l1 * a1 + rs1;
        m0 = mn0; m1 = mn1;
#pragma unroll
        for (int j = 0; j < 8; j++) {
            O[j][0] *= a0; O[j][1] *= a0; O[j][2] *= a1; O[j][3] *= a1;
        }

        // ---- P fragments (A-layout), split hi/lo
        uint32_t ph[4][4], pl[4][4];
#pragma unroll
        for (int c = 0; c < 4; c++) {
            split_pack(S[2 * c][0],     S[2 * c][1],     ph[c][0], pl[c][0]);
            split_pack(S[2 * c][2],     S[2 * c][3],     ph[c][1], pl[c][1]);
            split_pack(S[2 * c + 1][0], S[2 * c + 1][1], ph[c][2], pl[c][2]);
            split_pack(S[2 * c + 1][2], S[2 * c + 1][3], ph[c][3], pl[c][3]);
        }

        // ---- O += P V (3-pass)
        {
            int rbase = (lane & 15);
            int cb2 = (lane >> 4) * 8;
#pragma unroll
            for (int jj = 0; jj < 8; jj += 2) {
#pragma unroll
                for (int c = 0; c < 4; c++) {
                    uint32_t off = (uint32_t)((c * 16 + rbase) * PAD + jj * 8 + cb2);
                    uint32_t vh[4], vl[4];
                    LDSM_X4_T(vh[0], vh[1], vh[2], vh[3], smem_u32(sVh + off));
                    LDSM_X4_T(vl[0], vl[1], vl[2], vl[3], smem_u32(sVl + off));
                    MMA16816(O[jj],     ph[c], vh[0], vh[1]);
                    MMA16816(O[jj],     ph[c], vl[0], vl[1]);
                    MMA16816(O[jj],     pl[c], vh[0], vh[1]);
                    MMA16816(O[jj + 1], ph[c], vh[2], vh[3]);
                    MMA16816(O[jj + 1], ph[c], vl[2], vl[3]);
                    MMA16816(O[jj + 1], pl[c], vh[2], vh[3]);
                }
            }
        }
        __syncthreads();
    }

    // ---- epilogue
    float inv0 = 1.f / l0, inv1 = 1.f / l1;
    int g = lane >> 2, tg = lane & 3;
    int b_ = bh / NH, h = bh % NH;
    int r0 = qb + wid * 16 + g, r1 = r0 + 8;
    long ob0 = ((long)b_ * NSEQ + r0) * DIM + h * HD;
    long ob1 = ((long)b_ * NSEQ + r1) * DIM + h * HD;
#pragma unroll
    for (int j = 0; j < 8; j++) {
        int d = 8 * j + tg * 2;
        uint32_t hh, ll;
        split_pack(O[j][0] * inv0, O[j][1] * inv0, hh, ll);
        *(uint32_t*)(g_AOh + ob0 + d) = hh;
        *(uint32_t*)(g_AOl + ob0 + d) = ll;
        split_pack(O[j][2] * inv1, O[j][3] * inv1, hh, ll);
        *(uint32_t*)(g_AOh + ob1 + d) = hh;
        *(uint32_t*)(g_AOl + ob1 + d) = ll;
    }
}

// ---------------------------------------------------------------------------
// Stage 5: out = AO @ pw^T + pb (mma bf16x3, 128x128 tiles, cp.async dbuf)
#define PBUF (4 * 128 * PAD * 2)  /* 73728 B per buffer */
__global__ void __launch_bounds__(256) k_proj_mma(const float* __restrict__ pb,
                                                  float* __restrict__ out) {
    extern __shared__ __align__(16) char smraw[];
    int tid = threadIdx.x, wid = tid >> 5, lane = tid & 31;
    int m0 = blockIdx.x * 128, n0 = blockIdx.y * 128;
    uint32_t sb = smem_u32(smraw);
    float C[16][4] = {};

    // prefetch kb=0
    for (int i = tid; i < 128 * 8; i += 256) {
        int r = i >> 3, c = (i & 7) * 8;
        uint32_t doff = (uint32_t)((r * PAD + c) * 2);
        long ga = (long)(m0 + r) * DIM + c;
        long gb = (long)(n0 + r) * DIM + c;
        CP16(sb + 0 * 18432 + doff, g_AOh + ga);
        CP16(sb + 1 * 18432 + doff, g_AOl + ga);
        CP16(sb + 2 * 18432 + doff, g_pwh + gb);
        CP16(sb + 3 * 18432 + doff, g_pwl + gb);
    }
    CPCOMMIT();

    for (int kb = 0; kb < 12; kb++) {
        if (kb < 11) {
            uint32_t dbase = sb + ((kb + 1) & 1) * PBUF;
            for (int i = tid; i < 128 * 8; i += 256) {
                int r = i >> 3, c = (i & 7) * 8;
                uint32_t doff = (uint32_t)((r * PAD + c) * 2);
                long ga = (long)(m0 + r) * DIM + (kb + 1) * 64 + c;
                long gb = (long)(n0 + r) * DIM + (kb + 1) * 64 + c;
                CP16(dbase + 0 * 18432 + doff, g_AOh + ga);
                CP16(dbase + 1 * 18432 + doff, g_AOl + ga);
                CP16(dbase + 2 * 18432 + doff, g_pwh + gb);
                CP16(dbase + 3 * 18432 + doff, g_pwl + gb);
            }
            CPCOMMIT();
            CPWAIT1();
        } else {
            CPWAIT0();
        }
        __syncthreads();

        __nv_bfloat16* bufp = (__nv_bfloat16*)(smraw + (kb & 1) * PBUF);
        __nv_bfloat16* sAh = bufp;
        __nv_bfloat16* sAl = sAh + 128 * PAD;
        __nv_bfloat16* sBh = sAl + 128 * PAD;
        __nv_bfloat16* sBl = sBh + 128 * PAD;

        uint32_t ah[4][4], al[4][4];
        {
            int rowb = wid * 16 + (lane & 15);
            int colb = (lane >> 4) * 8;
#pragma unroll
            for (int c = 0; c < 4; c++) {
                LDSM_X4(ah[c][0], ah[c][1], ah[c][2], ah[c][3],
                        smem_u32(sAh + rowb * PAD + c * 16 + colb));
                LDSM_X4(al[c][0], al[c][1], al[c][2], al[c][3],
                        smem_u32(sAl + rowb * PAD + c * 16 + colb));
            }
        }
        {
            int rbase = (lane & 7);
            int cbase = (lane >> 3) * 8;
#pragma unroll
            for (int j = 0; j < 16; j++) {
                uint32_t off = (uint32_t)((8 * j + rbase) * PAD + cbase);
                uint32_t bh01[4], bh23[4], bl01[4], bl23[4];
                LDSM_X4(bh01[0], bh01[1], bh01[2], bh01[3], smem_u32(sBh + off));
                LDSM_X4(bh23[0], bh23[1], bh23[2], bh23[3], smem_u32(sBh + off + 32));
                LDSM_X4(bl01[0], bl01[1], bl01[2], bl01[3], smem_u32(sBl + off));
                LDSM_X4(bl23[0], bl23[1], bl23[2], bl23[3], smem_u32(sBl + off + 32));
                MMA16816(C[j], ah[0], bh01[0], bh01[1]);
                MMA16816(C[j], ah[1], bh01[2], bh01[3]);
                MMA16816(C[j], ah[2], bh23[0], bh23[1]);
                MMA16816(C[j], ah[3], bh23[2], bh23[3]);
                MMA16816(C[j], ah[0], bl01[0], bl01[1]);
                MMA16816(C[j], ah[1], bl01[2], bl01[3]);
                MMA16816(C[j], ah[2], bl23[0], bl23[1]);
                MMA16816(C[j], ah[3], bl23[2], bl23[3]);
                MMA16816(C[j], al[0], bh01[0], bh01[1]);
                MMA16816(C[j], al[1], bh01[2], bh01[3]);
                MMA16816(C[j], al[2], bh23[0], bh23[1]);
                MMA16816(C[j], al[3], bh23[2], bh23[3]);
            }
        }
        __syncthreads();
    }

    int g = lane >> 2, tg = lane & 3;
    int r0 = m0 + wid * 16 + g, r1 = r0 + 8;
#pragma unroll
    for (int j = 0; j < 16; j++) {
        int col = n0 + 8 * j + tg * 2;
        float b0 = pb[col], b1 = pb[col + 1];
        *(float2*)(out + (long)r0 * DIM + col) = make_float2(C[j][0] + b0, C[j][1] + b1);
        *(float2*)(out + (long)r1 * DIM + col) = make_float2(C[j][2] + b0, C[j][3] + b1);
    }
}

// ---------------------------------------------------------------------------
extern "C" void kernel_launch(void* const* d_in, const int* in_sizes, int n_in,
                              void* d_out, int out_size) {
    const float* x   = (const float*)d_in[0];
    const float* WQ0 = (const float*)d_in[1];
    const float* WQ1 = (const float*)d_in[2];
    const float* WQ2 = (const float*)d_in[3];
    const float* WK0 = (const float*)d_in[4];
    const float* WK1 = (const float*)d_in[5];
    const float* WK2 = (const float*)d_in[6];
    const float* WV0 = (const float*)d_in[7];
    const float* WV1 = (const float*)d_in[8];
    const float* WV2 = (const float*)d_in[9];
    const float* pw  = (const float*)d_in[10];
    const float* pb  = (const float*)d_in[11];
    float* out = (float*)d_out;

    const int SM_GT    = (128 + 64) * PAD * 2 * 2;  // 55296
    const int SM_EXP   = (128 + 64) * PAD * 2 * 2;  // 55296
    const int SM_FLASH = 2 * FBUF;                   // 73728
    const int SM_PROJ  = 2 * PBUF;                   // 147456
    cudaFuncSetAttribute(k_gemm_T_mma, cudaFuncAttributeMaxDynamicSharedMemorySize, SM_GT);
    cudaFuncSetAttribute(k_expand_mma, cudaFuncAttributeMaxDynamicSharedMemorySize, SM_EXP);
    cudaFuncSetAttribute(k_flash,      cudaFuncAttributeMaxDynamicSharedMemorySize, SM_FLASH);
    cudaFuncSetAttribute(k_proj_mma,   cudaFuncAttributeMaxDynamicSharedMemorySize, SM_PROJ);

    k_split_x<<<(BN * DIM / 2 + 255) / 256, 256>>>(x);
    k_build_weff<<<(3 * DIM * RNK + 255) / 256, 256>>>(WQ1, WQ2, WK1, WK2, WV1, WV2);
    k_split_pw<<<(DIM * DIM + 255) / 256, 256>>>(pw);
    k_gemm_T_mma<<<dim3(BN / 128, 3), 256, SM_GT>>>();
    k_expand_mma<<<dim3(BN / 128, NH, 3), 256, SM_EXP>>>(WQ0, WK0, WV0);
    k_flash<<<dim3(NSEQ / 128, NBH), 256, SM_FLASH>>>();
    k_proj_mma<<<dim3(BN / 128, DIM / 128), 256, SM_PROJ>>>(pb, out);
}

// round 5
// speedup vs baseline: 2.8149x; 1.1405x over previous
#include <cuda_runtime.h>
#include <cuda_bf16.h>
#include <cstdint>

#define BSZ  8
#define NSEQ 1024
#define DIM  768
#define NH   12
#define HD   64
#define RNK  64
#define BN   (BSZ*NSEQ)          /* 8192 */
#define NBH  (BSZ*NH)            /* 96 */
#define PAD  72                  /* padded smem row stride in bf16 */

// ---------------------------------------------------------------------------
// Scratch (device globals; allocation-free per harness rules)
__device__ __nv_bfloat16 g_xh[(size_t)BN*DIM];
__device__ __nv_bfloat16 g_xl[(size_t)BN*DIM];
__device__ __nv_bfloat16 g_Wefh[192*DIM];            // [n=p*64+r][k=dim]
__device__ __nv_bfloat16 g_Wefl[192*DIM];
__device__ __nv_bfloat16 g_Th[(size_t)BN*192];       // [i][p*64+r]
__device__ __nv_bfloat16 g_Tl[(size_t)BN*192];
__device__ __nv_bfloat16 g_Qh[(size_t)NBH*NSEQ*HD];  // [bh][l][d] (pre-scaled)
__device__ __nv_bfloat16 g_Ql[(size_t)NBH*NSEQ*HD];
__device__ __nv_bfloat16 g_Kh[(size_t)NBH*NSEQ*HD];
__device__ __nv_bfloat16 g_Kl[(size_t)NBH*NSEQ*HD];
__device__ __nv_bfloat16 g_Vh[(size_t)NBH*NSEQ*HD];  // row-major [l][d]
__device__ __nv_bfloat16 g_Vl[(size_t)NBH*NSEQ*HD];
__device__ __nv_bfloat16 g_AOh[(size_t)BN*DIM];      // [b*l][h*64+d]
__device__ __nv_bfloat16 g_AOl[(size_t)BN*DIM];
__device__ __nv_bfloat16 g_pwh[DIM*DIM];
__device__ __nv_bfloat16 g_pwl[DIM*DIM];

// ---------------------------------------------------------------------------
// helpers (baseline PTX, sm_80+)
__device__ __forceinline__ uint32_t smem_u32(const void* p) {
    uint32_t a;
    asm("{ .reg .u64 t; cvta.to.shared.u64 t, %1; cvt.u32.u64 %0, t; }" : "=r"(a) : "l"(p));
    return a;
}
#define LDSM_X4(r0,r1,r2,r3,addr) \
    asm volatile("ldmatrix.sync.aligned.m8n8.x4.shared.b16 {%0,%1,%2,%3}, [%4];" \
        : "=r"(r0), "=r"(r1), "=r"(r2), "=r"(r3) : "r"(addr))
#define LDSM_X4_T(r0,r1,r2,r3,addr) \
    asm volatile("ldmatrix.sync.aligned.m8n8.x4.trans.shared.b16 {%0,%1,%2,%3}, [%4];" \
        : "=r"(r0), "=r"(r1), "=r"(r2), "=r"(r3) : "r"(addr))
#define MMA16816(c, a, b0_, b1_) \
    asm volatile("mma.sync.aligned.m16n8k16.row.col.f32.bf16.bf16.f32 " \
        "{%0,%1,%2,%3}, {%4,%5,%6,%7}, {%8,%9}, {%0,%1,%2,%3};" \
        : "+f"((c)[0]), "+f"((c)[1]), "+f"((c)[2]), "+f"((c)[3]) \
        : "r"((a)[0]), "r"((a)[1]), "r"((a)[2]), "r"((a)[3]), "r"(b0_), "r"(b1_))
#define CP16(dst, src) \
    asm volatile("cp.async.cg.shared.global [%0], [%1], 16;" :: "r"(dst), "l"(src))
#define CPCOMMIT() asm volatile("cp.async.commit_group;" ::: "memory")
#define CPWAIT1()  asm volatile("cp.async.wait_group 1;" ::: "memory")
#define CPWAIT0()  asm volatile("cp.async.wait_group 0;" ::: "memory")

__device__ __forceinline__ void split2(float f, __nv_bfloat16& h, __nv_bfloat16& l) {
    h = __float2bfloat16(f);
    l = __float2bfloat16(f - __bfloat162float(h));
}
__device__ __forceinline__ uint32_t packbf2(__nv_bfloat16 a, __nv_bfloat16 b) {
    __nv_bfloat162 t = __halves2bfloat162(a, b);
    return *(uint32_t*)&t;
}
__device__ __forceinline__ void split_pack(float f0, float f1, uint32_t& h, uint32_t& l) {
    __nv_bfloat16 h0, l0, h1, l1;
    split2(f0, h0, l0);
    split2(f1, h1, l1);
    h = packbf2(h0, h1);
    l = packbf2(l0, l1);
}

// ---------------------------------------------------------------------------
// Stage 0: split x into bf16 hi/lo
__global__ void k_split_x(const float* __restrict__ x) {
    int i = blockIdx.x * blockDim.x + threadIdx.x;
    if (i >= BN * DIM / 2) return;
    float2 v = *(const float2*)(x + 2 * (size_t)i);
    uint32_t h, l;
    split_pack(v.x, v.y, h, l);
    *(uint32_t*)(g_xh + 2 * (size_t)i) = h;
    *(uint32_t*)(g_xl + 2 * (size_t)i) = l;
}

// Stage 1: Weff (transposed, split)
__global__ void k_build_weff(const float* __restrict__ W1q, const float* __restrict__ W2q,
                             const float* __restrict__ W1k, const float* __restrict__ W2k,
                             const float* __restrict__ W1v, const float* __restrict__ W2v) {
    int idx = blockIdx.x * blockDim.x + threadIdx.x;
    if (idx >= 3 * DIM * RNK) return;
    int p = idx / (DIM * RNK);
    int rem = idx % (DIM * RNK);
    int c = rem / RNK, r = rem % RNK;
    const float* W1 = (p == 0) ? W1q : ((p == 1) ? W1k : W1v);
    const float* W2 = (p == 0) ? W2q : ((p == 1) ? W2k : W2v);
    float f = W1[(c >> 6) * RNK + r] * W2[(c & 63) * RNK + r];
    __nv_bfloat16 h, l;
    split2(f, h, l);
    g_Wefh[(p * 64 + r) * DIM + c] = h;
    g_Wefl[(p * 64 + r) * DIM + c] = l;
}

__global__ void k_split_pw(const float* __restrict__ pw) {
    int i = blockIdx.x * blockDim.x + threadIdx.x;
    if (i >= DIM * DIM) return;
    split2(pw[i], g_pwh[i], g_pwl[i]);
}

// ---------------------------------------------------------------------------
// Stage 2: T = x @ Weff (mma bf16x3). Retiled M=64, N=64, warps 4x2. Grid 384.
__global__ void __launch_bounds__(256, 2) k_gemm_T_mma() {
    extern __shared__ __align__(16) char smraw[];
    __nv_bfloat16* sAh = (__nv_bfloat16*)smraw;          // 64 x PAD
    __nv_bfloat16* sAl = sAh + 64 * PAD;
    __nv_bfloat16* sBh = sAl + 64 * PAD;
    __nv_bfloat16* sBl = sBh + 64 * PAD;
    int tid = threadIdx.x, wid = tid >> 5, lane = tid & 31;
    int wm = wid >> 1, wn = wid & 1;
    int m0 = blockIdx.x * 64, n0 = blockIdx.y * 64;
    float C[4][4] = {};

    for (int kb = 0; kb < 12; kb++) {
        for (int i = tid; i < 64 * 8; i += 256) {
            int r = i >> 3, c = (i & 7) * 8;
            long ga = (long)(m0 + r) * DIM + kb * 64 + c;
            long gb = (long)(n0 + r) * DIM + kb * 64 + c;
            *(uint4*)(sAh + r * PAD + c) = *(const uint4*)(g_xh + ga);
            *(uint4*)(sAl + r * PAD + c) = *(const uint4*)(g_xl + ga);
            *(uint4*)(sBh + r * PAD + c) = *(const uint4*)(g_Wefh + gb);
            *(uint4*)(sBl + r * PAD + c) = *(const uint4*)(g_Wefl + gb);
        }
        __syncthreads();
        uint32_t ah[4][4], al[4][4];
        {
            int rowb = wm * 16 + (lane & 15);
            int colb = (lane >> 4) * 8;
#pragma unroll
            for (int c = 0; c < 4; c++) {
                LDSM_X4(ah[c][0], ah[c][1], ah[c][2], ah[c][3],
                        smem_u32(sAh + rowb * PAD + c * 16 + colb));
                LDSM_X4(al[c][0], al[c][1], al[c][2], al[c][3],
                        smem_u32(sAl + rowb * PAD + c * 16 + colb));
            }
        }
        {
            int rbase = (lane & 7);
            int cbase = (lane >> 3) * 8;
#pragma unroll
            for (int j = 0; j < 4; j++) {
                uint32_t off = (uint32_t)((wn * 32 + 8 * j + rbase) * PAD + cbase);
                uint32_t bh01[4], bh23[4], bl01[4], bl23[4];
                LDSM_X4(bh01[0], bh01[1], bh01[2], bh01[3], smem_u32(sBh + off));
                LDSM_X4(bh23[0], bh23[1], bh23[2], bh23[3], smem_u32(sBh + off + 32));
                LDSM_X4(bl01[0], bl01[1], bl01[2], bl01[3], smem_u32(sBl + off));
                LDSM_X4(bl23[0], bl23[1], bl23[2], bl23[3], smem_u32(sBl + off + 32));
                MMA16816(C[j], ah[0], bh01[0], bh01[1]);
                MMA16816(C[j], ah[1], bh01[2], bh01[3]);
                MMA16816(C[j], ah[2], bh23[0], bh23[1]);
                MMA16816(C[j], ah[3], bh23[2], bh23[3]);
                MMA16816(C[j], ah[0], bl01[0], bl01[1]);
                MMA16816(C[j], ah[1], bl01[2], bl01[3]);
                MMA16816(C[j], ah[2], bl23[0], bl23[1]);
                MMA16816(C[j], ah[3], bl23[2], bl23[3]);
                MMA16816(C[j], al[0], bh01[0], bh01[1]);
                MMA16816(C[j], al[1], bh01[2], bh01[3]);
                MMA16816(C[j], al[2], bh23[0], bh23[1]);
                MMA16816(C[j], al[3], bh23[2], bh23[3]);
            }
        }
        __syncthreads();
    }
    int g = lane >> 2, tg = lane & 3;
    int r0 = m0 + wm * 16 + g, r1 = r0 + 8;
#pragma unroll
    for (int j = 0; j < 4; j++) {
        int col = n0 + wn * 32 + 8 * j + tg * 2;
        uint32_t hh, ll;
        split_pack(C[j][0], C[j][1], hh, ll);
        *(uint32_t*)(g_Th + (long)r0 * 192 + col) = hh;
        *(uint32_t*)(g_Tl + (long)r0 * 192 + col) = ll;
        split_pack(C[j][2], C[j][3], hh, ll);
        *(uint32_t*)(g_Th + (long)r1 * 192 + col) = hh;
        *(uint32_t*)(g_Tl + (long)r1 * 192 + col) = ll;
    }
}

// ---------------------------------------------------------------------------
// Stage 3: Q/K/V = T_p @ W0_h^T (mma bf16x3). M=128, N=64, K=64.
__global__ void __launch_bounds__(256) k_expand_mma(const float* __restrict__ W0q,
                                                    const float* __restrict__ W0k,
                                                    const float* __restrict__ W0v) {
    extern __shared__ __align__(16) char smraw[];
    __nv_bfloat16* sAh = (__nv_bfloat16*)smraw;          // 128 x PAD
    __nv_bfloat16* sAl = sAh + 128 * PAD;
    __nv_bfloat16* sBh = sAl + 128 * PAD;                // 64 x PAD
    __nv_bfloat16* sBl = sBh + 64 * PAD;
    int p = blockIdx.z, h = blockIdx.y;
    int m0 = blockIdx.x * 128;
    const float* W0 = (p == 0) ? W0q : ((p == 1) ? W0k : W0v);
    int tid = threadIdx.x, wid = tid >> 5, lane = tid & 31;

    for (int i = tid; i < 128 * 8; i += 256) {
        int r = i >> 3, c = (i & 7) * 8;
        long ga = (long)(m0 + r) * 192 + p * 64 + c;
        *(uint4*)(sAh + r * PAD + c) = *(const uint4*)(g_Th + ga);
        *(uint4*)(sAl + r * PAD + c) = *(const uint4*)(g_Tl + ga);
    }
    for (int i = tid; i < 64 * 16; i += 256) {
        int d = i >> 4, c4 = (i & 15) * 4;
        float4 v = *(const float4*)(W0 + (long)(h * 64 + d) * 64 + c4);
        __nv_bfloat16 hh, ll;
        split2(v.x, hh, ll); sBh[d * PAD + c4]     = hh; sBl[d * PAD + c4]     = ll;
        split2(v.y, hh, ll); sBh[d * PAD + c4 + 1] = hh; sBl[d * PAD + c4 + 1] = ll;
        split2(v.z, hh, ll); sBh[d * PAD + c4 + 2] = hh; sBl[d * PAD + c4 + 2] = ll;
        split2(v.w, hh, ll); sBh[d * PAD + c4 + 3] = hh; sBl[d * PAD + c4 + 3] = ll;
    }
    __syncthreads();

    float C[8][4] = {};
    uint32_t ah[4][4], al[4][4];
    {
        int rowb = wid * 16 + (lane & 15);
        int colb = (lane >> 4) * 8;
#pragma unroll
        for (int c = 0; c < 4; c++) {
            LDSM_X4(ah[c][0], ah[c][1], ah[c][2], ah[c][3],
                    smem_u32(sAh + rowb * PAD + c * 16 + colb));
            LDSM_X4(al[c][0], al[c][1], al[c][2], al[c][3],
                    smem_u32(sAl + rowb * PAD + c * 16 + colb));
        }
    }
    {
        int rbase = (lane & 7);
        int cbase = (lane >> 3) * 8;
#pragma unroll
        for (int j = 0; j < 8; j++) {
            uint32_t off = (uint32_t)((8 * j + rbase) * PAD + cbase);
            uint32_t bh01[4], bh23[4], bl01[4], bl23[4];
            LDSM_X4(bh01[0], bh01[1], bh01[2], bh01[3], smem_u32(sBh + off));
            LDSM_X4(bh23[0], bh23[1], bh23[2], bh23[3], smem_u32(sBh + off + 32));
            LDSM_X4(bl01[0], bl01[1], bl01[2], bl01[3], smem_u32(sBl + off));
            LDSM_X4(bl23[0], bl23[1], bl23[2], bl23[3], smem_u32(sBl + off + 32));
            MMA16816(C[j], ah[0], bh01[0], bh01[1]);
            MMA16816(C[j], ah[1], bh01[2], bh01[3]);
            MMA16816(C[j], ah[2], bh23[0], bh23[1]);
            MMA16816(C[j], ah[3], bh23[2], bh23[3]);
            MMA16816(C[j], ah[0], bl01[0], bl01[1]);
            MMA16816(C[j], ah[1], bl01[2], bl01[3]);
            MMA16816(C[j], ah[2], bl23[0], bl23[1]);
            MMA16816(C[j], ah[3], bl23[2], bl23[3]);
            MMA16816(C[j], al[0], bh01[0], bh01[1]);
            MMA16816(C[j], al[1], bh01[2], bh01[3]);
            MMA16816(C[j], al[2], bh23[0], bh23[1]);
            MMA16816(C[j], al[3], bh23[2], bh23[3]);
        }
    }

    int g = lane >> 2, tg = lane & 3;
    float sc = (p == 0) ? 0.125f : 1.0f;
    __nv_bfloat16* gh = (p == 0) ? g_Qh : ((p == 1) ? g_Kh : g_Vh);
    __nv_bfloat16* gl = (p == 0) ? g_Ql : ((p == 1) ? g_Kl : g_Vl);
#pragma unroll
    for (int rr = 0; rr < 2; rr++) {
        int row = m0 + wid * 16 + g + rr * 8;
        int b_ = row >> 10, l = row & 1023;
        long base = ((long)b_ * NH + h) * 65536 + (long)l * 64;
#pragma unroll
        for (int j = 0; j < 8; j++) {
            int d = 8 * j + tg * 2;
            uint32_t hh, ll;
            split_pack(C[j][2 * rr] * sc, C[j][2 * rr + 1] * sc, hh, ll);
            *(uint32_t*)(gh + base + d) = hh;
            *(uint32_t*)(gl + base + d) = ll;
        }
    }
}

// ---------------------------------------------------------------------------
// Stage 4: fused flash attention, mma.sync bf16x3, cp.async dbuf, 2 CTAs/SM.
// smem: Qh [0,18432), Ql [18432,36864), KV buf0 @36864, buf1 @73728 (each 36864:
//       Kh 0 | Kl 9216 | Vh 18432 | Vl 27648)
#define FQBYTES (128 * PAD * 2)          /* 18432 */
#define FKV0    (2 * FQBYTES)            /* 36864 */
#define FBUF    (4 * 64 * PAD * 2)       /* 36864 per buffer */
#define SM_FLASH (FKV0 + 2 * FBUF)       /* 110592 */
__global__ void __launch_bounds__(256, 2) k_flash() {
    extern __shared__ __align__(16) char smraw[];
    int tid = threadIdx.x, wid = tid >> 5, lane = tid & 31;
    int bh = blockIdx.y, qb = blockIdx.x * 128;
    long base = (long)bh * NSEQ * HD;
    uint32_t sb = smem_u32(smraw);
    __nv_bfloat16* sQh = (__nv_bfloat16*)smraw;
    __nv_bfloat16* sQl = sQh + 128 * PAD;

    // ---- stage Q tile (persistent) + prefetch t=0 K/V
    for (int i = tid; i < 128 * 8; i += 256) {
        int r = i >> 3, c = (i & 7) * 8;
        uint32_t doff = (uint32_t)((r * PAD + c) * 2);
        long g = base + (long)(qb + r) * 64 + c;
        CP16(sb + doff, g_Qh + g);
        CP16(sb + FQBYTES + doff, g_Ql + g);
    }
    for (int i = tid; i < 64 * 8; i += 256) {
        int r = i >> 3, c = (i & 7) * 8;
        uint32_t doff = (uint32_t)((r * PAD + c) * 2);
        long g = base + (long)r * 64 + c;
        CP16(sb + FKV0 + 0 * 9216 + doff, g_Kh + g);
        CP16(sb + FKV0 + 1 * 9216 + doff, g_Kl + g);
        CP16(sb + FKV0 + 2 * 9216 + doff, g_Vh + g);
        CP16(sb + FKV0 + 3 * 9216 + doff, g_Vl + g);
    }
    CPCOMMIT();
    CPWAIT0();
    __syncthreads();

    // Q-hi fragments stay in registers; Q-lo reloaded from smem each iter.
    uint32_t qh[4][4];
    int qrowb = wid * 16 + (lane & 15);
    int qcolb = (lane >> 4) * 8;
#pragma unroll
    for (int c = 0; c < 4; c++)
        LDSM_X4(qh[c][0], qh[c][1], qh[c][2], qh[c][3],
                smem_u32(sQh + qrowb * PAD + c * 16 + qcolb));

    float m0 = -1e30f, m1 = -1e30f, l0 = 0.f, l1 = 0.f;
    float O[8][4] = {};

    for (int t = 0; t < 16; t++) {
        // prefetch t+1 into the other KV buffer
        if (t < 15) {
            uint32_t dbase = sb + FKV0 + ((t + 1) & 1) * FBUF;
            long gb = base + (long)(t + 1) * 64 * 64;
            for (int i = tid; i < 64 * 8; i += 256) {
                int r = i >> 3, c = (i & 7) * 8;
                uint32_t doff = (uint32_t)((r * PAD + c) * 2);
                long g = gb + (long)r * 64 + c;
                CP16(dbase + 0 * 9216 + doff, g_Kh + g);
                CP16(dbase + 1 * 9216 + doff, g_Kl + g);
                CP16(dbase + 2 * 9216 + doff, g_Vh + g);
                CP16(dbase + 3 * 9216 + doff, g_Vl + g);
            }
            CPCOMMIT();
            CPWAIT1();
        } else {
            CPWAIT0();
        }
        __syncthreads();

        __nv_bfloat16* bufp = (__nv_bfloat16*)(smraw + FKV0 + (t & 1) * FBUF);
        __nv_bfloat16* sKh = bufp;
        __nv_bfloat16* sKl = sKh + 64 * PAD;
        __nv_bfloat16* sVh = sKl + 64 * PAD;
        __nv_bfloat16* sVl = sVh + 64 * PAD;

        // reload Q-lo fragments (cheap: 4 LDSM vs 96 MMA)
        uint32_t ql[4][4];
#pragma unroll
        for (int c = 0; c < 4; c++)
            LDSM_X4(ql[c][0], ql[c][1], ql[c][2], ql[c][3],
                    smem_u32(sQl + qrowb * PAD + c * 16 + qcolb));

        // ---- S = Q K^T (3-pass)
        float S[8][4] = {};
        {
            int rbase = (lane & 7);
            int cbase = (lane >> 3) * 8;
#pragma unroll
            for (int j = 0; j < 8; j++) {
                uint32_t off = (uint32_t)((8 * j + rbase) * PAD + cbase);
                uint32_t bh01[4], bh23[4], bl01[4], bl23[4];
                LDSM_X4(bh01[0], bh01[1], bh01[2], bh01[3], smem_u32(sKh + off));
                LDSM_X4(bh23[0], bh23[1], bh23[2], bh23[3], smem_u32(sKh + off + 32));
                LDSM_X4(bl01[0], bl01[1], bl01[2], bl01[3], smem_u32(sKl + off));
                LDSM_X4(bl23[0], bl23[1], bl23[2], bl23[3], smem_u32(sKl + off + 32));
                MMA16816(S[j], qh[0], bh01[0], bh01[1]);
                MMA16816(S[j], qh[1], bh01[2], bh01[3]);
                MMA16816(S[j], qh[2], bh23[0], bh23[1]);
                MMA16816(S[j], qh[3], bh23[2], bh23[3]);
                MMA16816(S[j], qh[0], bl01[0], bl01[1]);
                MMA16816(S[j], qh[1], bl01[2], bl01[3]);
                MMA16816(S[j], qh[2], bl23[0], bl23[1]);
                MMA16816(S[j], qh[3], bl23[2], bl23[3]);
                MMA16816(S[j], ql[0], bh01[0], bh01[1]);
                MMA16816(S[j], ql[1], bh01[2], bh01[3]);
                MMA16816(S[j], ql[2], bh23[0], bh23[1]);
                MMA16816(S[j], ql[3], bh23[2], bh23[3]);
            }
        }

        // ---- online softmax
        float mx0 = -1e30f, mx1 = -1e30f;
#pragma unroll
        for (int j = 0; j < 8; j++) {
            mx0 = fmaxf(mx0, fmaxf(S[j][0], S[j][1]));
            mx1 = fmaxf(mx1, fmaxf(S[j][2], S[j][3]));
        }
        mx0 = fmaxf(mx0, __shfl_xor_sync(~0u, mx0, 1));
        mx0 = fmaxf(mx0, __shfl_xor_sync(~0u, mx0, 2));
        mx1 = fmaxf(mx1, __shfl_xor_sync(~0u, mx1, 1));
        mx1 = fmaxf(mx1, __shfl_xor_sync(~0u, mx1, 2));
        float mn0 = fmaxf(m0, mx0), mn1 = fmaxf(m1, mx1);
        float a0 = __expf(m0 - mn0), a1 = __expf(m1 - mn1);
        float rs0 = 0.f, rs1 = 0.f;
#pragma unroll
        for (int j = 0; j < 8; j++) {
            S[j][0] = __expf(S[j][0] - mn0); S[j][1] = __expf(S[j][1] - mn0);
            S[j][2] = __expf(S[j][2] - mn1); S[j][3] = __expf(S[j][3] - mn1);
            rs0 += S[j][0] + S[j][1];
            rs1 += S[j][2] + S[j][3];
        }
        rs0 += __shfl_xor_sync(~0u, rs0, 1); rs0 += __shfl_xor_sync(~0u, rs0, 2);
        rs1 += __shfl_xor_sync(~0u, rs1, 1); rs1 += __shfl_xor_sync(~0u, rs1, 2);
        l0 = l0 * a0 + rs0; l1 = l1 * a1 + rs1;
        m0 = mn0; m1 = mn1;
#pragma unroll
        for (int j = 0; j < 8; j++) {
            O[j][0] *= a0; O[j][1] *= a0; O[j][2] *= a1; O[j][3] *= a1;
        }

        // ---- P fragments (A-layout), split hi/lo
        uint32_t ph[4][4], pl[4][4];
#pragma unroll
        for (int c = 0; c < 4; c++) {
            split_pack(S[2 * c][0],     S[2 * c][1],     ph[c][0], pl[c][0]);
            split_pack(S[2 * c][2],     S[2 * c][3],     ph[c][1], pl[c][1]);
            split_pack(S[2 * c + 1][0], S[2 * c + 1][1], ph[c][2], pl[c][2]);
            split_pack(S[2 * c + 1][2], S[2 * c + 1][3], ph[c][3], pl[c][3]);
        }

        // ---- O += P V (3-pass)
        {
            int rbase = (lane & 15);
            int cb2 = (lane >> 4) * 8;
#pragma unroll
            for (int jj = 0; jj < 8; jj += 2) {
#pragma unroll
                for (int c = 0; c < 4; c++) {
                    uint32_t off = (uint32_t)((c * 16 + rbase) * PAD + jj * 8 + cb2);
                    uint32_t vh[4], vl[4];
                    LDSM_X4_T(vh[0], vh[1], vh[2], vh[3], smem_u32(sVh + off));
                    LDSM_X4_T(vl[0], vl[1], vl[2], vl[3], smem_u32(sVl + off));
                    MMA16816(O[jj],     ph[c], vh[0], vh[1]);
                    MMA16816(O[jj],     ph[c], vl[0], vl[1]);
                    MMA16816(O[jj],     pl[c], vh[0], vh[1]);
                    MMA16816(O[jj + 1], ph[c], vh[2], vh[3]);
                    MMA16816(O[jj + 1], ph[c], vl[2], vl[3]);
                    MMA16816(O[jj + 1], pl[c], vh[2], vh[3]);
                }
            }
        }
        __syncthreads();
    }

    // ---- epilogue
    float inv0 = 1.f / l0, inv1 = 1.f / l1;
    int g = lane >> 2, tg = lane & 3;
    int b_ = bh / NH, h = bh % NH;
    int r0 = qb + wid * 16 + g, r1 = r0 + 8;
    long ob0 = ((long)b_ * NSEQ + r0) * DIM + h * HD;
    long ob1 = ((long)b_ * NSEQ + r1) * DIM + h * HD;
#pragma unroll
    for (int j = 0; j < 8; j++) {
        int d = 8 * j + tg * 2;
        uint32_t hh, ll;
        split_pack(O[j][0] * inv0, O[j][1] * inv0, hh, ll);
        *(uint32_t*)(g_AOh + ob0 + d) = hh;
        *(uint32_t*)(g_AOl + ob0 + d) = ll;
        split_pack(O[j][2] * inv1, O[j][3] * inv1, hh, ll);
        *(uint32_t*)(g_AOh + ob1 + d) = hh;
        *(uint32_t*)(g_AOl + ob1 + d) = ll;
    }
}

// ---------------------------------------------------------------------------
// Stage 5: out = AO @ pw^T + pb (mma bf16x3, M=128 N=64 tiles, cp.async dbuf,
// 2 CTAs/SM). Buffer: Ah 0 | Al 18432 | Bh 36864 | Bl 46080; PBUF 55296.
#define PBUF (55296)
__global__ void __launch_bounds__(256, 2) k_proj_mma(const float* __restrict__ pb,
                                                     float* __restrict__ out) {
    extern __shared__ __align__(16) char smraw[];
    int tid = threadIdx.x, wid = tid >> 5, lane = tid & 31;
    int m0 = blockIdx.x * 128, n0 = blockIdx.y * 64;
    uint32_t sb = smem_u32(smraw);
    float C[8][4] = {};

    // prefetch kb=0
    for (int i = tid; i < 128 * 8; i += 256) {
        int r = i >> 3, c = (i & 7) * 8;
        uint32_t doff = (uint32_t)((r * PAD + c) * 2);
        long ga = (long)(m0 + r) * DIM + c;
        CP16(sb + 0 + doff, g_AOh + ga);
        CP16(sb + 18432 + doff, g_AOl + ga);
    }
    for (int i = tid; i < 64 * 8; i += 256) {
        int r = i >> 3, c = (i & 7) * 8;
        uint32_t doff = (uint32_t)((r * PAD + c) * 2);
        long gb = (long)(n0 + r) * DIM + c;
        CP16(sb + 36864 + doff, g_pwh + gb);
        CP16(sb + 46080 + doff, g_pwl + gb);
    }
    CPCOMMIT();

    for (int kb = 0; kb < 12; kb++) {
        if (kb < 11) {
            uint32_t dbase = sb + ((kb + 1) & 1) * PBUF;
            for (int i = tid; i < 128 * 8; i += 256) {
                int r = i >> 3, c = (i & 7) * 8;
                uint32_t doff = (uint32_t)((r * PAD + c) * 2);
                long ga = (long)(m0 + r) * DIM + (kb + 1) * 64 + c;
                CP16(dbase + 0 + doff, g_AOh + ga);
                CP16(dbase + 18432 + doff, g_AOl + ga);
            }
            for (int i = tid; i < 64 * 8; i += 256) {
                int r = i >> 3, c = (i & 7) * 8;
                uint32_t doff = (uint32_t)((r * PAD + c) * 2);
                long gb = (long)(n0 + r) * DIM + (kb + 1) * 64 + c;
                CP16(dbase + 36864 + doff, g_pwh + gb);
                CP16(dbase + 46080 + doff, g_pwl + gb);
            }
            CPCOMMIT();
            CPWAIT1();
        } else {
            CPWAIT0();
        }
        __syncthreads();

        __nv_bfloat16* bufp = (__nv_bfloat16*)(smraw + (kb & 1) * PBUF);
        __nv_bfloat16* sAh = bufp;
        __nv_bfloat16* sAl = sAh + 128 * PAD;
        __nv_bfloat16* sBh = sAl + 128 * PAD;
        __nv_bfloat16* sBl = sBh + 64 * PAD;

        uint32_t ah[4][4], al[4][4];
        {
            int rowb = wid * 16 + (lane & 15);
            int colb = (lane >> 4) * 8;
#pragma unroll
            for (int c = 0; c < 4; c++) {
                LDSM_X4(ah[c][0], ah[c][1], ah[c][2], ah[c][3],
                        smem_u32(sAh + rowb * PAD + c * 16 + colb));
                LDSM_X4(al[c][0], al[c][1], al[c][2], al[c][3],
                        smem_u32(sAl + rowb * PAD + c * 16 + colb));
            }
        }
        {
            int rbase = (lane & 7);
            int cbase = (lane >> 3) * 8;
#pragma unroll
            for (int j = 0; j < 8; j++) {
                uint32_t off = (uint32_t)((8 * j + rbase) * PAD + cbase);
                uint32_t bh01[4], bh23[4], bl01[4], bl23[4];
                LDSM_X4(bh01[0], bh01[1], bh01[2], bh01[3], smem_u32(sBh + off));
                LDSM_X4(bh23[0], bh23[1], bh23[2], bh23[3], smem_u32(sBh + off + 32));
                LDSM_X4(bl01[0], bl01[1], bl01[2], bl01[3], smem_u32(sBl + off));
                LDSM_X4(bl23[0], bl23[1], bl23[2], bl23[3], smem_u32(sBl + off + 32));
                MMA16816(C[j], ah[0], bh01[0], bh01[1]);
                MMA16816(C[j], ah[1], bh01[2], bh01[3]);
                MMA16816(C[j], ah[2], bh23[0], bh23[1]);
                MMA16816(C[j], ah[3], bh23[2], bh23[3]);
                MMA16816(C[j], ah[0], bl01[0], bl01[1]);
                MMA16816(C[j], ah[1], bl01[2], bl01[3]);
                MMA16816(C[j], ah[2], bl23[0], bl23[1]);
                MMA16816(C[j], ah[3], bl23[2], bl23[3]);
                MMA16816(C[j], al[0], bh01[0], bh01[1]);
                MMA16816(C[j], al[1], bh01[2], bh01[3]);
                MMA16816(C[j], al[2], bh23[0], bh23[1]);
                MMA16816(C[j], al[3], bh23[2], bh23[3]);
            }
        }
        __syncthreads();
    }

    int g = lane >> 2, tg = lane & 3;
    int r0 = m0 + wid * 16 + g, r1 = r0 + 8;
#pragma unroll
    for (int j = 0; j < 8; j++) {
        int col = n0 + 8 * j + tg * 2;
        float b0 = pb[col], b1 = pb[col + 1];
        *(float2*)(out + (long)r0 * DIM + col) = make_float2(C[j][0] + b0, C[j][1] + b1);
        *(float2*)(out + (long)r1 * DIM + col) = make_float2(C[j][2] + b0, C[j][3] + b1);
    }
}

// ---------------------------------------------------------------------------
extern "C" void kernel_launch(void* const* d_in, const int* in_sizes, int n_in,
                              void* d_out, int out_size) {
    const float* x   = (const float*)d_in[0];
    const float* WQ0 = (const float*)d_in[1];
    const float* WQ1 = (const float*)d_in[2];
    const float* WQ2 = (const float*)d_in[3];
    const float* WK0 = (const float*)d_in[4];
    const float* WK1 = (const float*)d_in[5];
    const float* WK2 = (const float*)d_in[6];
    const float* WV0 = (const float*)d_in[7];
    const float* WV1 = (const float*)d_in[8];
    const float* WV2 = (const float*)d_in[9];
    const float* pw  = (const float*)d_in[10];
    const float* pb  = (const float*)d_in[11];
    float* out = (float*)d_out;

    const int SM_GT  = 4 * 64 * PAD * 2;            // 36864
    const int SM_EXP = (128 + 64) * PAD * 2 * 2;    // 55296
    const int SM_PROJ = 2 * PBUF;                   // 110592
    cudaFuncSetAttribute(k_expand_mma, cudaFuncAttributeMaxDynamicSharedMemorySize, SM_EXP);
    cudaFuncSetAttribute(k_flash,      cudaFuncAttributeMaxDynamicSharedMemorySize, SM_FLASH);
    cudaFuncSetAttribute(k_proj_mma,   cudaFuncAttributeMaxDynamicSharedMemorySize, SM_PROJ);

    k_split_x<<<(BN * DIM / 2 + 255) / 256, 256>>>(x);
    k_build_weff<<<(3 * DIM * RNK + 255) / 256, 256>>>(WQ1, WQ2, WK1, WK2, WV1, WV2);
    k_split_pw<<<(DIM * DIM + 255) / 256, 256>>>(pw);
    k_gemm_T_mma<<<dim3(BN / 64, 3), 256, SM_GT>>>();
    k_expand_mma<<<dim3(BN / 128, NH, 3), 256, SM_EXP>>>(WQ0, WK0, WV0);
    k_flash<<<dim3(NSEQ / 128, NBH), 256, SM_FLASH>>>();
    k_proj_mma<<<dim3(BN / 128, DIM / 64), 256, SM_PROJ>>>(pb, out);
}

// round 6
// speedup vs baseline: 2.9026x; 1.0312x over previous
#include <cuda_runtime.h>
#include <cuda_bf16.h>
#include <cstdint>

#define BSZ  8
#define NSEQ 1024
#define DIM  768
#define NH   12
#define HD   64
#define RNK  64
#define BN   (BSZ*NSEQ)          /* 8192 */
#define NBH  (BSZ*NH)            /* 96 */
#define PAD  72                  /* padded smem row stride in bf16 */
#define QSCALE 0.1803368801111f  /* 0.125 * log2(e) */

// ---------------------------------------------------------------------------
// Scratch (device globals; allocation-free per harness rules)
__device__ __nv_bfloat16 g_xh[(size_t)BN*DIM];
__device__ __nv_bfloat16 g_xl[(size_t)BN*DIM];
__device__ __nv_bfloat16 g_Wefh[192*DIM];            // [n=p*64+r][k=dim]
__device__ __nv_bfloat16 g_Wefl[192*DIM];
__device__ __nv_bfloat16 g_Th[(size_t)BN*192];       // [i][p*64+r]
__device__ __nv_bfloat16 g_Tl[(size_t)BN*192];
__device__ __nv_bfloat16 g_Qh[(size_t)NBH*NSEQ*HD];  // [bh][l][d] (pre-scaled by QSCALE)
__device__ __nv_bfloat16 g_Ql[(size_t)NBH*NSEQ*HD];
__device__ __nv_bfloat16 g_Kh[(size_t)NBH*NSEQ*HD];
__device__ __nv_bfloat16 g_Kl[(size_t)NBH*NSEQ*HD];
__device__ __nv_bfloat16 g_Vh[(size_t)NBH*NSEQ*HD];  // row-major [l][d]
__device__ __nv_bfloat16 g_Vl[(size_t)NBH*NSEQ*HD];
__device__ __nv_bfloat16 g_AOh[(size_t)BN*DIM];      // [b*l][h*64+d]
__device__ __nv_bfloat16 g_AOl[(size_t)BN*DIM];
__device__ __nv_bfloat16 g_pwh[DIM*DIM];
__device__ __nv_bfloat16 g_pwl[DIM*DIM];

// ---------------------------------------------------------------------------
// helpers (baseline PTX, sm_80+)
__device__ __forceinline__ uint32_t smem_u32(const void* p) {
    uint32_t a;
    asm("{ .reg .u64 t; cvta.to.shared.u64 t, %1; cvt.u32.u64 %0, t; }" : "=r"(a) : "l"(p));
    return a;
}
#define LDSM_X4(r0,r1,r2,r3,addr) \
    asm volatile("ldmatrix.sync.aligned.m8n8.x4.shared.b16 {%0,%1,%2,%3}, [%4];" \
        : "=r"(r0), "=r"(r1), "=r"(r2), "=r"(r3) : "r"(addr))
#define LDSM_X4_T(r0,r1,r2,r3,addr) \
    asm volatile("ldmatrix.sync.aligned.m8n8.x4.trans.shared.b16 {%0,%1,%2,%3}, [%4];" \
        : "=r"(r0), "=r"(r1), "=r"(r2), "=r"(r3) : "r"(addr))
#define MMA16816(c, a, b0_, b1_) \
    asm volatile("mma.sync.aligned.m16n8k16.row.col.f32.bf16.bf16.f32 " \
        "{%0,%1,%2,%3}, {%4,%5,%6,%7}, {%8,%9}, {%0,%1,%2,%3};" \
        : "+f"((c)[0]), "+f"((c)[1]), "+f"((c)[2]), "+f"((c)[3]) \
        : "r"((a)[0]), "r"((a)[1]), "r"((a)[2]), "r"((a)[3]), "r"(b0_), "r"(b1_))
#define CP16(dst, src) \
    asm volatile("cp.async.cg.shared.global [%0], [%1], 16;" :: "r"(dst), "l"(src))
#define CPCOMMIT() asm volatile("cp.async.commit_group;" ::: "memory")
#define CPWAIT1()  asm volatile("cp.async.wait_group 1;" ::: "memory")
#define CPWAIT0()  asm volatile("cp.async.wait_group 0;" ::: "memory")

__device__ __forceinline__ void split2(float f, __nv_bfloat16& h, __nv_bfloat16& l) {
    h = __float2bfloat16(f);
    l = __float2bfloat16(f - __bfloat162float(h));
}
// packed split: hi = bf16x2(f1,f0), lo = bf16x2 of residuals. 2 cvt + 2 sub + mask ops.
__device__ __forceinline__ void split_pack(float f0, float f1, uint32_t& h, uint32_t& l) {
    uint32_t hh;
    asm("cvt.rn.bf16x2.f32 %0, %1, %2;" : "=r"(hh) : "f"(f1), "f"(f0));
    float h0 = __uint_as_float(hh << 16);
    float h1 = __uint_as_float(hh & 0xffff0000u);
    float l0 = f0 - h0, l1 = f1 - h1;
    uint32_t ll;
    asm("cvt.rn.bf16x2.f32 %0, %1, %2;" : "=r"(ll) : "f"(l1), "f"(l0));
    h = hh; l = ll;
}

// ---------------------------------------------------------------------------
// Stage 0: split x into bf16 hi/lo
__global__ void k_split_x(const float* __restrict__ x) {
    int i = blockIdx.x * blockDim.x + threadIdx.x;
    if (i >= BN * DIM / 2) return;
    float2 v = *(const float2*)(x + 2 * (size_t)i);
    uint32_t h, l;
    split_pack(v.x, v.y, h, l);
    *(uint32_t*)(g_xh + 2 * (size_t)i) = h;
    *(uint32_t*)(g_xl + 2 * (size_t)i) = l;
}

// Stage 1: Weff (transposed, split)
__global__ void k_build_weff(const float* __restrict__ W1q, const float* __restrict__ W2q,
                             const float* __restrict__ W1k, const float* __restrict__ W2k,
                             const float* __restrict__ W1v, const float* __restrict__ W2v) {
    int idx = blockIdx.x * blockDim.x + threadIdx.x;
    if (idx >= 3 * DIM * RNK) return;
    int p = idx / (DIM * RNK);
    int rem = idx % (DIM * RNK);
    int c = rem / RNK, r = rem % RNK;
    const float* W1 = (p == 0) ? W1q : ((p == 1) ? W1k : W1v);
    const float* W2 = (p == 0) ? W2q : ((p == 1) ? W2k : W2v);
    float f = W1[(c >> 6) * RNK + r] * W2[(c & 63) * RNK + r];
    __nv_bfloat16 h, l;
    split2(f, h, l);
    g_Wefh[(p * 64 + r) * DIM + c] = h;
    g_Wefl[(p * 64 + r) * DIM + c] = l;
}

__global__ void k_split_pw(const float* __restrict__ pw) {
    int i = blockIdx.x * blockDim.x + threadIdx.x;
    if (i >= DIM * DIM) return;
    split2(pw[i], g_pwh[i], g_pwl[i]);
}

// ---------------------------------------------------------------------------
// Stage 2: T = x @ Weff (mma bf16x3). M=64, N=64, warps 4x2, cp.async dbuf.
// Buffer layout: Ah 0 | Al 9216 | Bh 18432 | Bl 27648 ; GBUF=36864.
#define GBUF 36864
__global__ void __launch_bounds__(256, 2) k_gemm_T_mma() {
    extern __shared__ __align__(16) char smraw[];
    uint32_t sb = smem_u32(smraw);
    int tid = threadIdx.x, wid = tid >> 5, lane = tid & 31;
    int wm = wid >> 1, wn = wid & 1;
    int m0 = blockIdx.x * 64, n0 = blockIdx.y * 64;
    float C[4][4] = {};

    // prefetch kb=0
    for (int i = tid; i < 64 * 8; i += 256) {
        int r = i >> 3, c = (i & 7) * 8;
        uint32_t doff = (uint32_t)((r * PAD + c) * 2);
        long ga = (long)(m0 + r) * DIM + c;
        long gb = (long)(n0 + r) * DIM + c;
        CP16(sb + 0     + doff, g_xh + ga);
        CP16(sb + 9216  + doff, g_xl + ga);
        CP16(sb + 18432 + doff, g_Wefh + gb);
        CP16(sb + 27648 + doff, g_Wefl + gb);
    }
    CPCOMMIT();

    for (int kb = 0; kb < 12; kb++) {
        if (kb < 11) {
            uint32_t dbase = sb + ((kb + 1) & 1) * GBUF;
            for (int i = tid; i < 64 * 8; i += 256) {
                int r = i >> 3, c = (i & 7) * 8;
                uint32_t doff = (uint32_t)((r * PAD + c) * 2);
                long ga = (long)(m0 + r) * DIM + (kb + 1) * 64 + c;
                long gb = (long)(n0 + r) * DIM + (kb + 1) * 64 + c;
                CP16(dbase + 0     + doff, g_xh + ga);
                CP16(dbase + 9216  + doff, g_xl + ga);
                CP16(dbase + 18432 + doff, g_Wefh + gb);
                CP16(dbase + 27648 + doff, g_Wefl + gb);
            }
            CPCOMMIT();
            CPWAIT1();
        } else {
            CPWAIT0();
        }
        __syncthreads();

        __nv_bfloat16* bufp = (__nv_bfloat16*)(smraw + (kb & 1) * GBUF);
        __nv_bfloat16* sAh = bufp;
        __nv_bfloat16* sAl = sAh + 64 * PAD;
        __nv_bfloat16* sBh = sAl + 64 * PAD;
        __nv_bfloat16* sBl = sBh + 64 * PAD;

        uint32_t ah[4][4], al[4][4];
        {
            int rowb = wm * 16 + (lane & 15);
            int colb = (lane >> 4) * 8;
#pragma unroll
            for (int c = 0; c < 4; c++) {
                LDSM_X4(ah[c][0], ah[c][1], ah[c][2], ah[c][3],
                        smem_u32(sAh + rowb * PAD + c * 16 + colb));
                LDSM_X4(al[c][0], al[c][1], al[c][2], al[c][3],
                        smem_u32(sAl + rowb * PAD + c * 16 + colb));
            }
        }
        {
            int rbase = (lane & 7);
            int cbase = (lane >> 3) * 8;
#pragma unroll
            for (int j = 0; j < 4; j++) {
                uint32_t off = (uint32_t)((wn * 32 + 8 * j + rbase) * PAD + cbase);
                uint32_t bh01[4], bh23[4], bl01[4], bl23[4];
                LDSM_X4(bh01[0], bh01[1], bh01[2], bh01[3], smem_u32(sBh + off));
                LDSM_X4(bh23[0], bh23[1], bh23[2], bh23[3], smem_u32(sBh + off + 32));
                LDSM_X4(bl01[0], bl01[1], bl01[2], bl01[3], smem_u32(sBl + off));
                LDSM_X4(bl23[0], bl23[1], bl23[2], bl23[3], smem_u32(sBl + off + 32));
                MMA16816(C[j], ah[0], bh01[0], bh01[1]);
                MMA16816(C[j], ah[1], bh01[2], bh01[3]);
                MMA16816(C[j], ah[2], bh23[0], bh23[1]);
                MMA16816(C[j], ah[3], bh23[2], bh23[3]);
                MMA16816(C[j], ah[0], bl01[0], bl01[1]);
                MMA16816(C[j], ah[1], bl01[2], bl01[3]);
                MMA16816(C[j], ah[2], bl23[0], bl23[1]);
                MMA16816(C[j], ah[3], bl23[2], bl23[3]);
                MMA16816(C[j], al[0], bh01[0], bh01[1]);
                MMA16816(C[j], al[1], bh01[2], bh01[3]);
                MMA16816(C[j], al[2], bh23[0], bh23[1]);
                MMA16816(C[j], al[3], bh23[2], bh23[3]);
            }
        }
        __syncthreads();
    }
    int g = lane >> 2, tg = lane & 3;
    int r0 = m0 + wm * 16 + g, r1 = r0 + 8;
#pragma unroll
    for (int j = 0; j < 4; j++) {
        int col = n0 + wn * 32 + 8 * j + tg * 2;
        uint32_t hh, ll;
        split_pack(C[j][0], C[j][1], hh, ll);
        *(uint32_t*)(g_Th + (long)r0 * 192 + col) = hh;
        *(uint32_t*)(g_Tl + (long)r0 * 192 + col) = ll;
        split_pack(C[j][2], C[j][3], hh, ll);
        *(uint32_t*)(g_Th + (long)r1 * 192 + col) = hh;
        *(uint32_t*)(g_Tl + (long)r1 * 192 + col) = ll;
    }
}

// ---------------------------------------------------------------------------
// Stage 3: Q/K/V = T_p @ W0_h^T (mma bf16x3). M=128, N=64, K=64. 2 CTAs/SM.
__global__ void __launch_bounds__(256, 2) k_expand_mma(const float* __restrict__ W0q,
                                                       const float* __restrict__ W0k,
                                                       const float* __restrict__ W0v) {
    extern __shared__ __align__(16) char smraw[];
    __nv_bfloat16* sAh = (__nv_bfloat16*)smraw;          // 128 x PAD
    __nv_bfloat16* sAl = sAh + 128 * PAD;
    __nv_bfloat16* sBh = sAl + 128 * PAD;                // 64 x PAD
    __nv_bfloat16* sBl = sBh + 64 * PAD;
    int p = blockIdx.z, h = blockIdx.y;
    int m0 = blockIdx.x * 128;
    const float* W0 = (p == 0) ? W0q : ((p == 1) ? W0k : W0v);
    int tid = threadIdx.x, wid = tid >> 5, lane = tid & 31;

    for (int i = tid; i < 128 * 8; i += 256) {
        int r = i >> 3, c = (i & 7) * 8;
        long ga = (long)(m0 + r) * 192 + p * 64 + c;
        *(uint4*)(sAh + r * PAD + c) = *(const uint4*)(g_Th + ga);
        *(uint4*)(sAl + r * PAD + c) = *(const uint4*)(g_Tl + ga);
    }
    for (int i = tid; i < 64 * 16; i += 256) {
        int d = i >> 4, c4 = (i & 15) * 4;
        float4 v = *(const float4*)(W0 + (long)(h * 64 + d) * 64 + c4);
        __nv_bfloat16 hh, ll;
        split2(v.x, hh, ll); sBh[d * PAD + c4]     = hh; sBl[d * PAD + c4]     = ll;
        split2(v.y, hh, ll); sBh[d * PAD + c4 + 1] = hh; sBl[d * PAD + c4 + 1] = ll;
        split2(v.z, hh, ll); sBh[d * PAD + c4 + 2] = hh; sBl[d * PAD + c4 + 2] = ll;
        split2(v.w, hh, ll); sBh[d * PAD + c4 + 3] = hh; sBl[d * PAD + c4 + 3] = ll;
    }
    __syncthreads();

    float C[8][4] = {};
    uint32_t ah[4][4], al[4][4];
    {
        int rowb = wid * 16 + (lane & 15);
        int colb = (lane >> 4) * 8;
#pragma unroll
        for (int c = 0; c < 4; c++) {
            LDSM_X4(ah[c][0], ah[c][1], ah[c][2], ah[c][3],
                    smem_u32(sAh + rowb * PAD + c * 16 + colb));
            LDSM_X4(al[c][0], al[c][1], al[c][2], al[c][3],
                    smem_u32(sAl + rowb * PAD + c * 16 + colb));
        }
    }
    {
        int rbase = (lane & 7);
        int cbase = (lane >> 3) * 8;
#pragma unroll
        for (int j = 0; j < 8; j++) {
            uint32_t off = (uint32_t)((8 * j + rbase) * PAD + cbase);
            uint32_t bh01[4], bh23[4], bl01[4], bl23[4];
            LDSM_X4(bh01[0], bh01[1], bh01[2], bh01[3], smem_u32(sBh + off));
            LDSM_X4(bh23[0], bh23[1], bh23[2], bh23[3], smem_u32(sBh + off + 32));
            LDSM_X4(bl01[0], bl01[1], bl01[2], bl01[3], smem_u32(sBl + off));
            LDSM_X4(bl23[0], bl23[1], bl23[2], bl23[3], smem_u32(sBl + off + 32));
            MMA16816(C[j], ah[0], bh01[0], bh01[1]);
            MMA16816(C[j], ah[1], bh01[2], bh01[3]);
            MMA16816(C[j], ah[2], bh23[0], bh23[1]);
            MMA16816(C[j], ah[3], bh23[2], bh23[3]);
            MMA16816(C[j], ah[0], bl01[0], bl01[1]);
            MMA16816(C[j], ah[1], bl01[2], bl01[3]);
            MMA16816(C[j], ah[2], bl23[0], bl23[1]);
            MMA16816(C[j], ah[3], bl23[2], bl23[3]);
            MMA16816(C[j], al[0], bh01[0], bh01[1]);
            MMA16816(C[j], al[1], bh01[2], bh01[3]);
            MMA16816(C[j], al[2], bh23[0], bh23[1]);
            MMA16816(C[j], al[3], bh23[2], bh23[3]);
        }
    }

    int g = lane >> 2, tg = lane & 3;
    float sc = (p == 0) ? QSCALE : 1.0f;   // Q pre-scaled for exp2 softmax
    __nv_bfloat16* gh = (p == 0) ? g_Qh : ((p == 1) ? g_Kh : g_Vh);
    __nv_bfloat16* gl = (p == 0) ? g_Ql : ((p == 1) ? g_Kl : g_Vl);
#pragma unroll
    for (int rr = 0; rr < 2; rr++) {
        int row = m0 + wid * 16 + g + rr * 8;
        int b_ = row >> 10, l = row & 1023;
        long base = ((long)b_ * NH + h) * 65536 + (long)l * 64;
#pragma unroll
        for (int j = 0; j < 8; j++) {
            int d = 8 * j + tg * 2;
            uint32_t hh, ll;
            split_pack(C[j][2 * rr] * sc, C[j][2 * rr + 1] * sc, hh, ll);
            *(uint32_t*)(gh + base + d) = hh;
            *(uint32_t*)(gl + base + d) = ll;
        }
    }
}

// ---------------------------------------------------------------------------
// Stage 4: fused flash attention, mma.sync bf16x3, cp.async dbuf, 2 CTAs/SM.
// exp2-domain softmax (Q pre-scaled by 0.125*log2e).
#define FQBYTES (128 * PAD * 2)          /* 18432 */
#define FKV0    (2 * FQBYTES)            /* 36864 */
#define FBUF    (4 * 64 * PAD * 2)       /* 36864 per buffer */
#define SM_FLASH (FKV0 + 2 * FBUF)       /* 110592 */
__global__ void __launch_bounds__(256, 2) k_flash() {
    extern __shared__ __align__(16) char smraw[];
    int tid = threadIdx.x, wid = tid >> 5, lane = tid & 31;
    int bh = blockIdx.y, qb = blockIdx.x * 128;
    long base = (long)bh * NSEQ * HD;
    uint32_t sb = smem_u32(smraw);
    __nv_bfloat16* sQh = (__nv_bfloat16*)smraw;
    __nv_bfloat16* sQl = sQh + 128 * PAD;

    // ---- stage Q tile (persistent) + prefetch t=0 K/V
    for (int i = tid; i < 128 * 8; i += 256) {
        int r = i >> 3, c = (i & 7) * 8;
        uint32_t doff = (uint32_t)((r * PAD + c) * 2);
        long g = base + (long)(qb + r) * 64 + c;
        CP16(sb + doff, g_Qh + g);
        CP16(sb + FQBYTES + doff, g_Ql + g);
    }
    for (int i = tid; i < 64 * 8; i += 256) {
        int r = i >> 3, c = (i & 7) * 8;
        uint32_t doff = (uint32_t)((r * PAD + c) * 2);
        long g = base + (long)r * 64 + c;
        CP16(sb + FKV0 + 0 * 9216 + doff, g_Kh + g);
        CP16(sb + FKV0 + 1 * 9216 + doff, g_Kl + g);
        CP16(sb + FKV0 + 2 * 9216 + doff, g_Vh + g);
        CP16(sb + FKV0 + 3 * 9216 + doff, g_Vl + g);
    }
    CPCOMMIT();
    CPWAIT0();
    __syncthreads();

    uint32_t qh[4][4];
    int qrowb = wid * 16 + (lane & 15);
    int qcolb = (lane >> 4) * 8;
#pragma unroll
    for (int c = 0; c < 4; c++)
        LDSM_X4(qh[c][0], qh[c][1], qh[c][2], qh[c][3],
                smem_u32(sQh + qrowb * PAD + c * 16 + qcolb));

    float m0 = -1e30f, m1 = -1e30f, l0 = 0.f, l1 = 0.f;
    float O[8][4] = {};

    for (int t = 0; t < 16; t++) {
        if (t < 15) {
            uint32_t dbase = sb + FKV0 + ((t + 1) & 1) * FBUF;
            long gb = base + (long)(t + 1) * 64 * 64;
            for (int i = tid; i < 64 * 8; i += 256) {
                int r = i >> 3, c = (i & 7) * 8;
                uint32_t doff = (uint32_t)((r * PAD + c) * 2);
                long g = gb + (long)r * 64 + c;
                CP16(dbase + 0 * 9216 + doff, g_Kh + g);
                CP16(dbase + 1 * 9216 + doff, g_Kl + g);
                CP16(dbase + 2 * 9216 + doff, g_Vh + g);
                CP16(dbase + 3 * 9216 + doff, g_Vl + g);
            }
            CPCOMMIT();
            CPWAIT1();
        } else {
            CPWAIT0();
        }
        __syncthreads();

        __nv_bfloat16* bufp = (__nv_bfloat16*)(smraw + FKV0 + (t & 1) * FBUF);
        __nv_bfloat16* sKh = bufp;
        __nv_bfloat16* sKl = sKh + 64 * PAD;
        __nv_bfloat16* sVh = sKl + 64 * PAD;
        __nv_bfloat16* sVl = sVh + 64 * PAD;

        uint32_t ql[4][4];
#pragma unroll
        for (int c = 0; c < 4; c++)
            LDSM_X4(ql[c][0], ql[c][1], ql[c][2], ql[c][3],
                    smem_u32(sQl + qrowb * PAD + c * 16 + qcolb));

        // ---- S = Q K^T (3-pass), S in log2 domain
        float S[8][4] = {};
        {
            int rbase = (lane & 7);
            int cbase = (lane >> 3) * 8;
#pragma unroll
            for (int j = 0; j < 8; j++) {
                uint32_t off = (uint32_t)((8 * j + rbase) * PAD + cbase);
                uint32_t bh01[4], bh23[4], bl01[4], bl23[4];
                LDSM_X4(bh01[0], bh01[1], bh01[2], bh01[3], smem_u32(sKh + off));
                LDSM_X4(bh23[0], bh23[1], bh23[2], bh23[3], smem_u32(sKh + off + 32));
                LDSM_X4(bl01[0], bl01[1], bl01[2], bl01[3], smem_u32(sKl + off));
                LDSM_X4(bl23[0], bl23[1], bl23[2], bl23[3], smem_u32(sKl + off + 32));
                MMA16816(S[j], qh[0], bh01[0], bh01[1]);
                MMA16816(S[j], qh[1], bh01[2], bh01[3]);
                MMA16816(S[j], qh[2], bh23[0], bh23[1]);
                MMA16816(S[j], qh[3], bh23[2], bh23[3]);
                MMA16816(S[j], qh[0], bl01[0], bl01[1]);
                MMA16816(S[j], qh[1], bl01[2], bl01[3]);
                MMA16816(S[j], qh[2], bl23[0], bl23[1]);
                MMA16816(S[j], qh[3], bl23[2], bl23[3]);
                MMA16816(S[j], ql[0], bh01[0], bh01[1]);
                MMA16816(S[j], ql[1], bh01[2], bh01[3]);
                MMA16816(S[j], ql[2], bh23[0], bh23[1]);
                MMA16816(S[j], ql[3], bh23[2], bh23[3]);
            }
        }

        // ---- online softmax (exp2 domain)
        float mx0 = -1e30f, mx1 = -1e30f;
#pragma unroll
        for (int j = 0; j < 8; j++) {
            mx0 = fmaxf(mx0, fmaxf(S[j][0], S[j][1]));
            mx1 = fmaxf(mx1, fmaxf(S[j][2], S[j][3]));
        }
        mx0 = fmaxf(mx0, __shfl_xor_sync(~0u, mx0, 1));
        mx0 = fmaxf(mx0, __shfl_xor_sync(~0u, mx0, 2));
        mx1 = fmaxf(mx1, __shfl_xor_sync(~0u, mx1, 1));
        mx1 = fmaxf(mx1, __shfl_xor_sync(~0u, mx1, 2));
        float mn0 = fmaxf(m0, mx0), mn1 = fmaxf(m1, mx1);
        float a0 = exp2f(m0 - mn0), a1 = exp2f(m1 - mn1);
        float rs0 = 0.f, rs1 = 0.f;
#pragma unroll
        for (int j = 0; j < 8; j++) {
            S[j][0] = exp2f(S[j][0] - mn0); S[j][1] = exp2f(S[j][1] - mn0);
            S[j][2] = exp2f(S[j][2] - mn1); S[j][3] = exp2f(S[j][3] - mn1);
            rs0 += S[j][0] + S[j][1];
            rs1 += S[j][2] + S[j][3];
        }
        rs0 += __shfl_xor_sync(~0u, rs0, 1); rs0 += __shfl_xor_sync(~0u, rs0, 2);
        rs1 += __shfl_xor_sync(~0u, rs1, 1); rs1 += __shfl_xor_sync(~0u, rs1, 2);
        l0 = l0 * a0 + rs0; l1 = l1 * a1 + rs1;
        m0 = mn0; m1 = mn1;
#pragma unroll
        for (int j = 0; j < 8; j++) {
            O[j][0] *= a0; O[j][1] *= a0; O[j][2] *= a1; O[j][3] *= a1;
        }

        // ---- P fragments (A-layout), split hi/lo
        uint32_t ph[4][4], pl[4][4];
#pragma unroll
        for (int c = 0; c < 4; c++) {
            split_pack(S[2 * c][0],     S[2 * c][1],     ph[c][0], pl[c][0]);
            split_pack(S[2 * c][2],     S[2 * c][3],     ph[c][1], pl[c][1]);
            split_pack(S[2 * c + 1][0], S[2 * c + 1][1], ph[c][2], pl[c][2]);
            split_pack(S[2 * c + 1][2], S[2 * c + 1][3], ph[c][3], pl[c][3]);
        }

        // ---- O += P V (3-pass)
        {
            int rbase = (lane & 15);
            int cb2 = (lane >> 4) * 8;
#pragma unroll
            for (int jj = 0; jj < 8; jj += 2) {
#pragma unroll
                for (int c = 0; c < 4; c++) {
                    uint32_t off = (uint32_t)((c * 16 + rbase) * PAD + jj * 8 + cb2);
                    uint32_t vh[4], vl[4];
                    LDSM_X4_T(vh[0], vh[1], vh[2], vh[3], smem_u32(sVh + off));
                    LDSM_X4_T(vl[0], vl[1], vl[2], vl[3], smem_u32(sVl + off));
                    MMA16816(O[jj],     ph[c], vh[0], vh[1]);
                    MMA16816(O[jj],     ph[c], vl[0], vl[1]);
                    MMA16816(O[jj],     pl[c], vh[0], vh[1]);
                    MMA16816(O[jj + 1], ph[c], vh[2], vh[3]);
                    MMA16816(O[jj + 1], ph[c], vl[2], vl[3]);
                    MMA16816(O[jj + 1], pl[c], vh[2], vh[3]);
                }
            }
        }
        __syncthreads();
    }

    // ---- epilogue
    float inv0 = 1.f / l0, inv1 = 1.f / l1;
    int g = lane >> 2, tg = lane & 3;
    int b_ = bh / NH, h = bh % NH;
    int r0 = qb + wid * 16 + g, r1 = r0 + 8;
    long ob0 = ((long)b_ * NSEQ + r0) * DIM + h * HD;
    long ob1 = ((long)b_ * NSEQ + r1) * DIM + h * HD;
#pragma unroll
    for (int j = 0; j < 8; j++) {
        int d = 8 * j + tg * 2;
        uint32_t hh, ll;
        split_pack(O[j][0] * inv0, O[j][1] * inv0, hh, ll);
        *(uint32_t*)(g_AOh + ob0 + d) = hh;
        *(uint32_t*)(g_AOl + ob0 + d) = ll;
        split_pack(O[j][2] * inv1, O[j][3] * inv1, hh, ll);
        *(uint32_t*)(g_AOh + ob1 + d) = hh;
        *(uint32_t*)(g_AOl + ob1 + d) = ll;
    }
}

// ---------------------------------------------------------------------------
// Stage 5: out = AO @ pw^T + pb (mma bf16x3, M=128 N=64, cp.async dbuf, 2/SM)
#define PBUF (55296)
__global__ void __launch_bounds__(256, 2) k_proj_mma(const float* __restrict__ pb,
                                                     float* __restrict__ out) {
    extern __shared__ __align__(16) char smraw[];
    int tid = threadIdx.x, wid = tid >> 5, lane = tid & 31;
    int m0 = blockIdx.x * 128, n0 = blockIdx.y * 64;
    uint32_t sb = smem_u32(smraw);
    float C[8][4] = {};

    for (int i = tid; i < 128 * 8; i += 256) {
        int r = i >> 3, c = (i & 7) * 8;
        uint32_t doff = (uint32_t)((r * PAD + c) * 2);
        long ga = (long)(m0 + r) * DIM + c;
        CP16(sb + 0 + doff, g_AOh + ga);
        CP16(sb + 18432 + doff, g_AOl + ga);
    }
    for (int i = tid; i < 64 * 8; i += 256) {
        int r = i >> 3, c = (i & 7) * 8;
        uint32_t doff = (uint32_t)((r * PAD + c) * 2);
        long gb = (long)(n0 + r) * DIM + c;
        CP16(sb + 36864 + doff, g_pwh + gb);
        CP16(sb + 46080 + doff, g_pwl + gb);
    }
    CPCOMMIT();

    for (int kb = 0; kb < 12; kb++) {
        if (kb < 11) {
            uint32_t dbase = sb + ((kb + 1) & 1) * PBUF;
            for (int i = tid; i < 128 * 8; i += 256) {
                int r = i >> 3, c = (i & 7) * 8;
                uint32_t doff = (uint32_t)((r * PAD + c) * 2);
                long ga = (long)(m0 + r) * DIM + (kb + 1) * 64 + c;
                CP16(dbase + 0 + doff, g_AOh + ga);
                CP16(dbase + 18432 + doff, g_AOl + ga);
            }
            for (int i = tid; i < 64 * 8; i += 256) {
                int r = i >> 3, c = (i & 7) * 8;
                uint32_t doff = (uint32_t)((r * PAD + c) * 2);
                long gb = (long)(n0 + r) * DIM + (kb + 1) * 64 + c;
                CP16(dbase + 36864 + doff, g_pwh + gb);
                CP16(dbase + 46080 + doff, g_pwl + gb);
            }
            CPCOMMIT();
            CPWAIT1();
        } else {
            CPWAIT0();
        }
        __syncthreads();

        __nv_bfloat16* bufp = (__nv_bfloat16*)(smraw + (kb & 1) * PBUF);
        __nv_bfloat16* sAh = bufp;
        __nv_bfloat16* sAl = sAh + 128 * PAD;
        __nv_bfloat16* sBh = sAl + 128 * PAD;
        __nv_bfloat16* sBl = sBh + 64 * PAD;

        uint32_t ah[4][4], al[4][4];
        {
            int rowb = wid * 16 + (lane & 15);
            int colb = (lane >> 4) * 8;
#pragma unroll
            for (int c = 0; c < 4; c++) {
                LDSM_X4(ah[c][0], ah[c][1], ah[c][2], ah[c][3],
                        smem_u32(sAh + rowb * PAD + c * 16 + colb));
                LDSM_X4(al[c][0], al[c][1], al[c][2], al[c][3],
                        smem_u32(sAl + rowb * PAD + c * 16 + colb));
            }
        }
        {
            int rbase = (lane & 7);
            int cbase = (lane >> 3) * 8;
#pragma unroll
            for (int j = 0; j < 8; j++) {
                uint32_t off = (uint32_t)((8 * j + rbase) * PAD + cbase);
                uint32_t bh01[4], bh23[4], bl01[4], bl23[4];
                LDSM_X4(bh01[0], bh01[1], bh01[2], bh01[3], smem_u32(sBh + off));
                LDSM_X4(bh23[0], bh23[1], bh23[2], bh23[3], smem_u32(sBh + off + 32));
                LDSM_X4(bl01[0], bl01[1], bl01[2], bl01[3], smem_u32(sBl + off));
                LDSM_X4(bl23[0], bl23[1], bl23[2], bl23[3], smem_u32(sBl + off + 32));
                MMA16816(C[j], ah[0], bh01[0], bh01[1]);
                MMA16816(C[j], ah[1], bh01[2], bh01[3]);
                MMA16816(C[j], ah[2], bh23[0], bh23[1]);
                MMA16816(C[j], ah[3], bh23[2], bh23[3]);
                MMA16816(C[j], ah[0], bl01[0], bl01[1]);
                MMA16816(C[j], ah[1], bl01[2], bl01[3]);
                MMA16816(C[j], ah[2], bl23[0], bl23[1]);
                MMA16816(C[j], ah[3], bl23[2], bl23[3]);
                MMA16816(C[j], al[0], bh01[0], bh01[1]);
                MMA16816(C[j], al[1], bh01[2], bh01[3]);
                MMA16816(C[j], al[2], bh23[0], bh23[1]);
                MMA16816(C[j], al[3], bh23[2], bh23[3]);
            }
        }
        __syncthreads();
    }

    int g = lane >> 2, tg = lane & 3;
    int r0 = m0 + wid * 16 + g, r1 = r0 + 8;
#pragma unroll
    for (int j = 0; j < 8; j++) {
        int col = n0 + 8 * j + tg * 2;
        float b0 = pb[col], b1 = pb[col + 1];
        *(float2*)(out + (long)r0 * DIM + col) = make_float2(C[j][0] + b0, C[j][1] + b1);
        *(float2*)(out + (long)r1 * DIM + col) = make_float2(C[j][2] + b0, C[j][3] + b1);
    }
}

// ---------------------------------------------------------------------------
extern "C" void kernel_launch(void* const* d_in, const int* in_sizes, int n_in,
                              void* d_out, int out_size) {
    const float* x   = (const float*)d_in[0];
    const float* WQ0 = (const float*)d_in[1];
    const float* WQ1 = (const float*)d_in[2];
    const float* WQ2 = (const float*)d_in[3];
    const float* WK0 = (const float*)d_in[4];
    const float* WK1 = (const float*)d_in[5];
    const float* WK2 = (const float*)d_in[6];
    const float* WV0 = (const float*)d_in[7];
    const float* WV1 = (const float*)d_in[8];
    const float* WV2 = (const float*)d_in[9];
    const float* pw  = (const float*)d_in[10];
    const float* pb  = (const float*)d_in[11];
    float* out = (float*)d_out;

    const int SM_GT   = 2 * GBUF;                   // 73728
    const int SM_EXP  = (128 + 64) * PAD * 2 * 2;   // 55296
    const int SM_PROJ = 2 * PBUF;                   // 110592
    cudaFuncSetAttribute(k_gemm_T_mma, cudaFuncAttributeMaxDynamicSharedMemorySize, SM_GT);
    cudaFuncSetAttribute(k_expand_mma, cudaFuncAttributeMaxDynamicSharedMemorySize, SM_EXP);
    cudaFuncSetAttribute(k_flash,      cudaFuncAttributeMaxDynamicSharedMemorySize, SM_FLASH);
    cudaFuncSetAttribute(k_proj_mma,   cudaFuncAttributeMaxDynamicSharedMemorySize, SM_PROJ);

    k_split_x<<<(BN * DIM / 2 + 255) / 256, 256>>>(x);
    k_build_weff<<<(3 * DIM * RNK + 255) / 256, 256>>>(WQ1, WQ2, WK1, WK2, WV1, WV2);
    k_split_pw<<<(DIM * DIM + 255) / 256, 256>>>(pw);
    k_gemm_T_mma<<<dim3(BN / 64, 3), 256, SM_GT>>>();
    k_expand_mma<<<dim3(BN / 128, NH, 3), 256, SM_EXP>>>(WQ0, WK0, WV0);
    k_flash<<<dim3(NSEQ / 128, NBH), 256, SM_FLASH>>>();
    k_proj_mma<<<dim3(BN / 128, DIM / 64), 256, SM_PROJ>>>(pb, out);
}

// round 7
// speedup vs baseline: 3.5554x; 1.2249x over previous
#include <cuda_runtime.h>
#include <cuda_bf16.h>
#include <cuda_fp16.h>
#include <cstdint>

#define BSZ  8
#define NSEQ 1024
#define DIM  768
#define NH   12
#define HD   64
#define RNK  64
#define BN   (BSZ*NSEQ)          /* 8192 */
#define NBH  (BSZ*NH)            /* 96 */
#define PAD  72                  /* padded smem row stride in 16-bit elems */
#define QSCALE 0.1803368801111f  /* 0.125 * log2(e) */

// ---------------------------------------------------------------------------
// Scratch (device globals; allocation-free per harness rules)
__device__ __nv_bfloat16 g_xh[(size_t)BN*DIM];
__device__ __nv_bfloat16 g_xl[(size_t)BN*DIM];
__device__ __nv_bfloat16 g_Wefh[192*DIM];            // [n=p*64+r][k=dim]
__device__ __nv_bfloat16 g_Wefl[192*DIM];
__device__ __nv_bfloat16 g_Th[(size_t)BN*192];       // [i][p*64+r]
__device__ __nv_bfloat16 g_Tl[(size_t)BN*192];
__device__ __nv_bfloat16 g_Qh[(size_t)NBH*NSEQ*HD];  // [bh][l][d] (pre-scaled by QSCALE)
__device__ __nv_bfloat16 g_Ql[(size_t)NBH*NSEQ*HD];
__device__ __nv_bfloat16 g_Kh[(size_t)NBH*NSEQ*HD];
__device__ __nv_bfloat16 g_Kl[(size_t)NBH*NSEQ*HD];
__device__ __half        g_Vf[(size_t)NBH*NSEQ*HD];  // single fp16, row-major [l][d]
__device__ __nv_bfloat16 g_AOh[(size_t)BN*DIM];      // [b*l][h*64+d]
__device__ __nv_bfloat16 g_AOl[(size_t)BN*DIM];
__device__ __nv_bfloat16 g_pwh[DIM*DIM];
__device__ __nv_bfloat16 g_pwl[DIM*DIM];

// ---------------------------------------------------------------------------
// helpers (baseline PTX, sm_80+)
__device__ __forceinline__ uint32_t smem_u32(const void* p) {
    uint32_t a;
    asm("{ .reg .u64 t; cvta.to.shared.u64 t, %1; cvt.u32.u64 %0, t; }" : "=r"(a) : "l"(p));
    return a;
}
#define LDSM_X4(r0,r1,r2,r3,addr) \
    asm volatile("ldmatrix.sync.aligned.m8n8.x4.shared.b16 {%0,%1,%2,%3}, [%4];" \
        : "=r"(r0), "=r"(r1), "=r"(r2), "=r"(r3) : "r"(addr))
#define LDSM_X4_T(r0,r1,r2,r3,addr) \
    asm volatile("ldmatrix.sync.aligned.m8n8.x4.trans.shared.b16 {%0,%1,%2,%3}, [%4];" \
        : "=r"(r0), "=r"(r1), "=r"(r2), "=r"(r3) : "r"(addr))
#define MMA16816(c, a, b0_, b1_) \
    asm volatile("mma.sync.aligned.m16n8k16.row.col.f32.bf16.bf16.f32 " \
        "{%0,%1,%2,%3}, {%4,%5,%6,%7}, {%8,%9}, {%0,%1,%2,%3};" \
        : "+f"((c)[0]), "+f"((c)[1]), "+f"((c)[2]), "+f"((c)[3]) \
        : "r"((a)[0]), "r"((a)[1]), "r"((a)[2]), "r"((a)[3]), "r"(b0_), "r"(b1_))
#define MMAF16(c, a, b0_, b1_) \
    asm volatile("mma.sync.aligned.m16n8k16.row.col.f32.f16.f16.f32 " \
        "{%0,%1,%2,%3}, {%4,%5,%6,%7}, {%8,%9}, {%0,%1,%2,%3};" \
        : "+f"((c)[0]), "+f"((c)[1]), "+f"((c)[2]), "+f"((c)[3]) \
        : "r"((a)[0]), "r"((a)[1]), "r"((a)[2]), "r"((a)[3]), "r"(b0_), "r"(b1_))
#define CP16(dst, src) \
    asm volatile("cp.async.cg.shared.global [%0], [%1], 16;" :: "r"(dst), "l"(src))
#define CPCOMMIT() asm volatile("cp.async.commit_group;" ::: "memory")
#define CPWAIT1()  asm volatile("cp.async.wait_group 1;" ::: "memory")
#define CPWAIT0()  asm volatile("cp.async.wait_group 0;" ::: "memory")

__device__ __forceinline__ void split2(float f, __nv_bfloat16& h, __nv_bfloat16& l) {
    h = __float2bfloat16(f);
    l = __float2bfloat16(f - __bfloat162float(h));
}
__device__ __forceinline__ void split_pack(float f0, float f1, uint32_t& h, uint32_t& l) {
    uint32_t hh;
    asm("cvt.rn.bf16x2.f32 %0, %1, %2;" : "=r"(hh) : "f"(f1), "f"(f0));
    float h0 = __uint_as_float(hh << 16);
    float h1 = __uint_as_float(hh & 0xffff0000u);
    float l0 = f0 - h0, l1 = f1 - h1;
    uint32_t ll;
    asm("cvt.rn.bf16x2.f32 %0, %1, %2;" : "=r"(ll) : "f"(l1), "f"(l0));
    h = hh; l = ll;
}
__device__ __forceinline__ uint32_t pack_f16x2(float f0, float f1) {
    uint32_t r;
    asm("cvt.rn.f16x2.f32 %0, %1, %2;" : "=r"(r) : "f"(f1), "f"(f0));
    return r;
}

// ---------------------------------------------------------------------------
// Stage 0: split x into bf16 hi/lo
__global__ void k_split_x(const float* __restrict__ x) {
    int i = blockIdx.x * blockDim.x + threadIdx.x;
    if (i >= BN * DIM / 2) return;
    float2 v = *(const float2*)(x + 2 * (size_t)i);
    uint32_t h, l;
    split_pack(v.x, v.y, h, l);
    *(uint32_t*)(g_xh + 2 * (size_t)i) = h;
    *(uint32_t*)(g_xl + 2 * (size_t)i) = l;
}

// Stage 1: Weff (transposed, split)
__global__ void k_build_weff(const float* __restrict__ W1q, const float* __restrict__ W2q,
                             const float* __restrict__ W1k, const float* __restrict__ W2k,
                             const float* __restrict__ W1v, const float* __restrict__ W2v) {
    int idx = blockIdx.x * blockDim.x + threadIdx.x;
    if (idx >= 3 * DIM * RNK) return;
    int p = idx / (DIM * RNK);
    int rem = idx % (DIM * RNK);
    int c = rem / RNK, r = rem % RNK;
    const float* W1 = (p == 0) ? W1q : ((p == 1) ? W1k : W1v);
    const float* W2 = (p == 0) ? W2q : ((p == 1) ? W2k : W2v);
    float f = W1[(c >> 6) * RNK + r] * W2[(c & 63) * RNK + r];
    __nv_bfloat16 h, l;
    split2(f, h, l);
    g_Wefh[(p * 64 + r) * DIM + c] = h;
    g_Wefl[(p * 64 + r) * DIM + c] = l;
}

__global__ void k_split_pw(const float* __restrict__ pw) {
    int i = blockIdx.x * blockDim.x + threadIdx.x;
    if (i >= DIM * DIM) return;
    split2(pw[i], g_pwh[i], g_pwl[i]);
}

// ---------------------------------------------------------------------------
// Stage 2: T = x @ Weff (mma bf16x3). M=64, N=64, warps 4x2, cp.async dbuf.
#define GBUF 36864
__global__ void __launch_bounds__(256, 2) k_gemm_T_mma() {
    extern __shared__ __align__(16) char smraw[];
    uint32_t sb = smem_u32(smraw);
    int tid = threadIdx.x, wid = tid >> 5, lane = tid & 31;
    int wm = wid >> 1, wn = wid & 1;
    int m0 = blockIdx.x * 64, n0 = blockIdx.y * 64;
    float C[4][4] = {};

    for (int i = tid; i < 64 * 8; i += 256) {
        int r = i >> 3, c = (i & 7) * 8;
        uint32_t doff = (uint32_t)((r * PAD + c) * 2);
        long ga = (long)(m0 + r) * DIM + c;
        long gb = (long)(n0 + r) * DIM + c;
        CP16(sb + 0     + doff, g_xh + ga);
        CP16(sb + 9216  + doff, g_xl + ga);
        CP16(sb + 18432 + doff, g_Wefh + gb);
        CP16(sb + 27648 + doff, g_Wefl + gb);
    }
    CPCOMMIT();

    for (int kb = 0; kb < 12; kb++) {
        if (kb < 11) {
            uint32_t dbase = sb + ((kb + 1) & 1) * GBUF;
            for (int i = tid; i < 64 * 8; i += 256) {
                int r = i >> 3, c = (i & 7) * 8;
                uint32_t doff = (uint32_t)((r * PAD + c) * 2);
                long ga = (long)(m0 + r) * DIM + (kb + 1) * 64 + c;
                long gb = (long)(n0 + r) * DIM + (kb + 1) * 64 + c;
                CP16(dbase + 0     + doff, g_xh + ga);
                CP16(dbase + 9216  + doff, g_xl + ga);
                CP16(dbase + 18432 + doff, g_Wefh + gb);
                CP16(dbase + 27648 + doff, g_Wefl + gb);
            }
            CPCOMMIT();
            CPWAIT1();
        } else {
            CPWAIT0();
        }
        __syncthreads();

        __nv_bfloat16* bufp = (__nv_bfloat16*)(smraw + (kb & 1) * GBUF);
        __nv_bfloat16* sAh = bufp;
        __nv_bfloat16* sAl = sAh + 64 * PAD;
        __nv_bfloat16* sBh = sAl + 64 * PAD;
        __nv_bfloat16* sBl = sBh + 64 * PAD;

        uint32_t ah[4][4], al[4][4];
        {
            int rowb = wm * 16 + (lane & 15);
            int colb = (lane >> 4) * 8;
#pragma unroll
            for (int c = 0; c < 4; c++) {
                LDSM_X4(ah[c][0], ah[c][1], ah[c][2], ah[c][3],
                        smem_u32(sAh + rowb * PAD + c * 16 + colb));
                LDSM_X4(al[c][0], al[c][1], al[c][2], al[c][3],
                        smem_u32(sAl + rowb * PAD + c * 16 + colb));
            }
        }
        {
            int rbase = (lane & 7);
            int cbase = (lane >> 3) * 8;
#pragma unroll
            for (int j = 0; j < 4; j++) {
                uint32_t off = (uint32_t)((wn * 32 + 8 * j + rbase) * PAD + cbase);
                uint32_t bh01[4], bh23[4], bl01[4], bl23[4];
                LDSM_X4(bh01[0], bh01[1], bh01[2], bh01[3], smem_u32(sBh + off));
                LDSM_X4(bh23[0], bh23[1], bh23[2], bh23[3], smem_u32(sBh + off + 32));
                LDSM_X4(bl01[0], bl01[1], bl01[2], bl01[3], smem_u32(sBl + off));
                LDSM_X4(bl23[0], bl23[1], bl23[2], bl23[3], smem_u32(sBl + off + 32));
                MMA16816(C[j], ah[0], bh01[0], bh01[1]);
                MMA16816(C[j], ah[1], bh01[2], bh01[3]);
                MMA16816(C[j], ah[2], bh23[0], bh23[1]);
                MMA16816(C[j], ah[3], bh23[2], bh23[3]);
                MMA16816(C[j], ah[0], bl01[0], bl01[1]);
                MMA16816(C[j], ah[1], bl01[2], bl01[3]);
                MMA16816(C[j], ah[2], bl23[0], bl23[1]);
                MMA16816(C[j], ah[3], bl23[2], bl23[3]);
                MMA16816(C[j], al[0], bh01[0], bh01[1]);
                MMA16816(C[j], al[1], bh01[2], bh01[3]);
                MMA16816(C[j], al[2], bh23[0], bh23[1]);
                MMA16816(C[j], al[3], bh23[2], bh23[3]);
            }
        }
        __syncthreads();
    }
    int g = lane >> 2, tg = lane & 3;
    int r0 = m0 + wm * 16 + g, r1 = r0 + 8;
#pragma unroll
    for (int j = 0; j < 4; j++) {
        int col = n0 + wn * 32 + 8 * j + tg * 2;
        uint32_t hh, ll;
        split_pack(C[j][0], C[j][1], hh, ll);
        *(uint32_t*)(g_Th + (long)r0 * 192 + col) = hh;
        *(uint32_t*)(g_Tl + (long)r0 * 192 + col) = ll;
        split_pack(C[j][2], C[j][3], hh, ll);
        *(uint32_t*)(g_Th + (long)r1 * 192 + col) = hh;
        *(uint32_t*)(g_Tl + (long)r1 * 192 + col) = ll;
    }
}

// ---------------------------------------------------------------------------
// Stage 3: Q/K/V = T_p @ W0_h^T. M=128, N=64, K=64. cp.async for T; V -> fp16.
__global__ void __launch_bounds__(256, 2) k_expand_mma(const float* __restrict__ W0q,
                                                       const float* __restrict__ W0k,
                                                       const float* __restrict__ W0v) {
    extern __shared__ __align__(16) char smraw[];
    __nv_bfloat16* sAh = (__nv_bfloat16*)smraw;          // 128 x PAD
    __nv_bfloat16* sAl = sAh + 128 * PAD;
    __nv_bfloat16* sBh = sAl + 128 * PAD;                // 64 x PAD
    __nv_bfloat16* sBl = sBh + 64 * PAD;
    int p = blockIdx.z, h = blockIdx.y;
    int m0 = blockIdx.x * 128;
    const float* W0 = (p == 0) ? W0q : ((p == 1) ? W0k : W0v);
    int tid = threadIdx.x, wid = tid >> 5, lane = tid & 31;
    uint32_t sb = smem_u32(smraw);

    for (int i = tid; i < 128 * 8; i += 256) {
        int r = i >> 3, c = (i & 7) * 8;
        uint32_t doff = (uint32_t)((r * PAD + c) * 2);
        long ga = (long)(m0 + r) * 192 + p * 64 + c;
        CP16(sb + doff, g_Th + ga);
        CP16(sb + 128 * PAD * 2 + doff, g_Tl + ga);
    }
    CPCOMMIT();
    for (int i = tid; i < 64 * 16; i += 256) {
        int d = i >> 4, c4 = (i & 15) * 4;
        float4 v = *(const float4*)(W0 + (long)(h * 64 + d) * 64 + c4);
        __nv_bfloat16 hh, ll;
        split2(v.x, hh, ll); sBh[d * PAD + c4]     = hh; sBl[d * PAD + c4]     = ll;
        split2(v.y, hh, ll); sBh[d * PAD + c4 + 1] = hh; sBl[d * PAD + c4 + 1] = ll;
        split2(v.z, hh, ll); sBh[d * PAD + c4 + 2] = hh; sBl[d * PAD + c4 + 2] = ll;
        split2(v.w, hh, ll); sBh[d * PAD + c4 + 3] = hh; sBl[d * PAD + c4 + 3] = ll;
    }
    CPWAIT0();
    __syncthreads();

    float C[8][4] = {};
    uint32_t ah[4][4], al[4][4];
    {
        int rowb = wid * 16 + (lane & 15);
        int colb = (lane >> 4) * 8;
#pragma unroll
        for (int c = 0; c < 4; c++) {
            LDSM_X4(ah[c][0], ah[c][1], ah[c][2], ah[c][3],
                    smem_u32(sAh + rowb * PAD + c * 16 + colb));
            LDSM_X4(al[c][0], al[c][1], al[c][2], al[c][3],
                    smem_u32(sAl + rowb * PAD + c * 16 + colb));
        }
    }
    {
        int rbase = (lane & 7);
        int cbase = (lane >> 3) * 8;
#pragma unroll
        for (int j = 0; j < 8; j++) {
            uint32_t off = (uint32_t)((8 * j + rbase) * PAD + cbase);
            uint32_t bh01[4], bh23[4], bl01[4], bl23[4];
            LDSM_X4(bh01[0], bh01[1], bh01[2], bh01[3], smem_u32(sBh + off));
            LDSM_X4(bh23[0], bh23[1], bh23[2], bh23[3], smem_u32(sBh + off + 32));
            LDSM_X4(bl01[0], bl01[1], bl01[2], bl01[3], smem_u32(sBl + off));
            LDSM_X4(bl23[0], bl23[1], bl23[2], bl23[3], smem_u32(sBl + off + 32));
            MMA16816(C[j], ah[0], bh01[0], bh01[1]);
            MMA16816(C[j], ah[1], bh01[2], bh01[3]);
            MMA16816(C[j], ah[2], bh23[0], bh23[1]);
            MMA16816(C[j], ah[3], bh23[2], bh23[3]);
            MMA16816(C[j], ah[0], bl01[0], bl01[1]);
            MMA16816(C[j], ah[1], bl01[2], bl01[3]);
            MMA16816(C[j], ah[2], bl23[0], bl23[1]);
            MMA16816(C[j], ah[3], bl23[2], bl23[3]);
            MMA16816(C[j], al[0], bh01[0], bh01[1]);
            MMA16816(C[j], al[1], bh01[2], bh01[3]);
            MMA16816(C[j], al[2], bh23[0], bh23[1]);
            MMA16816(C[j], al[3], bh23[2], bh23[3]);
        }
    }

    int g = lane >> 2, tg = lane & 3;
    float sc = (p == 0) ? QSCALE : 1.0f;
#pragma unroll
    for (int rr = 0; rr < 2; rr++) {
        int row = m0 + wid * 16 + g + rr * 8;
        int b_ = row >> 10, l = row & 1023;
        long base = ((long)b_ * NH + h) * 65536 + (long)l * 64;
        if (p == 2) {
#pragma unroll
            for (int j = 0; j < 8; j++) {
                int d = 8 * j + tg * 2;
                *(uint32_t*)(g_Vf + base + d) = pack_f16x2(C[j][2 * rr], C[j][2 * rr + 1]);
            }
        } else {
            __nv_bfloat16* gh = (p == 0) ? g_Qh : g_Kh;
            __nv_bfloat16* gl = (p == 0) ? g_Ql : g_Kl;
#pragma unroll
            for (int j = 0; j < 8; j++) {
                int d = 8 * j + tg * 2;
                uint32_t hh, ll;
                split_pack(C[j][2 * rr] * sc, C[j][2 * rr + 1] * sc, hh, ll);
                *(uint32_t*)(gh + base + d) = hh;
                *(uint32_t*)(gl + base + d) = ll;
            }
        }
    }
}

// ---------------------------------------------------------------------------
// Stage 4: fused flash attention. S = bf16x3, P*V = single fp16 pass.
// smem: Qh [0,18432) Ql [18432,36864); KV buffers @36864 + {0,1}*27648:
//       Kh 0 | Kl 9216 | Vf 18432  (each region 9216 B)
#define FQBYTES (128 * PAD * 2)          /* 18432 */
#define FKV0    (2 * FQBYTES)            /* 36864 */
#define FBUF    (3 * 64 * PAD * 2)       /* 27648 per buffer */
#define SM_FLASH (FKV0 + 2 * FBUF)       /* 92160 */
__global__ void __launch_bounds__(256, 2) k_flash() {
    extern __shared__ __align__(16) char smraw[];
    int tid = threadIdx.x, wid = tid >> 5, lane = tid & 31;
    int bh = blockIdx.y, qb = blockIdx.x * 128;
    long base = (long)bh * NSEQ * HD;
    uint32_t sb = smem_u32(smraw);
    __nv_bfloat16* sQh = (__nv_bfloat16*)smraw;
    __nv_bfloat16* sQl = sQh + 128 * PAD;

    // stage Q (persistent) + prefetch t=0 K/V
    for (int i = tid; i < 128 * 8; i += 256) {
        int r = i >> 3, c = (i & 7) * 8;
        uint32_t doff = (uint32_t)((r * PAD + c) * 2);
        long g = base + (long)(qb + r) * 64 + c;
        CP16(sb + doff, g_Qh + g);
        CP16(sb + FQBYTES + doff, g_Ql + g);
    }
    for (int i = tid; i < 64 * 8; i += 256) {
        int r = i >> 3, c = (i & 7) * 8;
        uint32_t doff = (uint32_t)((r * PAD + c) * 2);
        long g = base + (long)r * 64 + c;
        CP16(sb + FKV0 + 0     + doff, g_Kh + g);
        CP16(sb + FKV0 + 9216  + doff, g_Kl + g);
        CP16(sb + FKV0 + 18432 + doff, g_Vf + g);
    }
    CPCOMMIT();
    CPWAIT0();
    __syncthreads();

    uint32_t qh[4][4], ql[4][4];
    {
        int qrowb = wid * 16 + (lane & 15);
        int qcolb = (lane >> 4) * 8;
#pragma unroll
        for (int c = 0; c < 4; c++) {
            LDSM_X4(qh[c][0], qh[c][1], qh[c][2], qh[c][3],
                    smem_u32(sQh + qrowb * PAD + c * 16 + qcolb));
            LDSM_X4(ql[c][0], ql[c][1], ql[c][2], ql[c][3],
                    smem_u32(sQl + qrowb * PAD + c * 16 + qcolb));
        }
    }

    float m0 = -1e30f, m1 = -1e30f, l0 = 0.f, l1 = 0.f;
    float O[8][4] = {};

    for (int t = 0; t < 16; t++) {
        if (t < 15) {
            uint32_t dbase = sb + FKV0 + ((t + 1) & 1) * FBUF;
            long gb = base + (long)(t + 1) * 64 * 64;
            for (int i = tid; i < 64 * 8; i += 256) {
                int r = i >> 3, c = (i & 7) * 8;
                uint32_t doff = (uint32_t)((r * PAD + c) * 2);
                long g = gb + (long)r * 64 + c;
                CP16(dbase + 0     + doff, g_Kh + g);
                CP16(dbase + 9216  + doff, g_Kl + g);
                CP16(dbase + 18432 + doff, g_Vf + g);
            }
            CPCOMMIT();
            CPWAIT1();
        } else {
            CPWAIT0();
        }
        __syncthreads();

        char* bufp = smraw + FKV0 + (t & 1) * FBUF;
        __nv_bfloat16* sKh = (__nv_bfloat16*)bufp;
        __nv_bfloat16* sKl = (__nv_bfloat16*)(bufp + 9216);
        __half*        sVf = (__half*)(bufp + 18432);

        // ---- S = Q K^T (bf16 3-pass), log2 domain
        float S[8][4] = {};
        {
            int rbase = (lane & 7);
            int cbase = (lane >> 3) * 8;
#pragma unroll
            for (int j = 0; j < 8; j++) {
                uint32_t off = (uint32_t)((8 * j + rbase) * PAD + cbase);
                uint32_t bh01[4], bh23[4], bl01[4], bl23[4];
                LDSM_X4(bh01[0], bh01[1], bh01[2], bh01[3], smem_u32(sKh + off));
                LDSM_X4(bh23[0], bh23[1], bh23[2], bh23[3], smem_u32(sKh + off + 32));
                LDSM_X4(bl01[0], bl01[1], bl01[2], bl01[3], smem_u32(sKl + off));
                LDSM_X4(bl23[0], bl23[1], bl23[2], bl23[3], smem_u32(sKl + off + 32));
                MMA16816(S[j], qh[0], bh01[0], bh01[1]);
                MMA16816(S[j], qh[1], bh01[2], bh01[3]);
                MMA16816(S[j], qh[2], bh23[0], bh23[1]);
                MMA16816(S[j], qh[3], bh23[2], bh23[3]);
                MMA16816(S[j], qh[0], bl01[0], bl01[1]);
                MMA16816(S[j], qh[1], bl01[2], bl01[3]);
                MMA16816(S[j], qh[2], bl23[0], bl23[1]);
                MMA16816(S[j], qh[3], bl23[2], bl23[3]);
                MMA16816(S[j], ql[0], bh01[0], bh01[1]);
                MMA16816(S[j], ql[1], bh01[2], bh01[3]);
                MMA16816(S[j], ql[2], bh23[0], bh23[1]);
                MMA16816(S[j], ql[3], bh23[2], bh23[3]);
            }
        }

        // ---- online softmax (exp2 domain)
        float mx0 = -1e30f, mx1 = -1e30f;
#pragma unroll
        for (int j = 0; j < 8; j++) {
            mx0 = fmaxf(mx0, fmaxf(S[j][0], S[j][1]));
            mx1 = fmaxf(mx1, fmaxf(S[j][2], S[j][3]));
        }
        mx0 = fmaxf(mx0, __shfl_xor_sync(~0u, mx0, 1));
        mx0 = fmaxf(mx0, __shfl_xor_sync(~0u, mx0, 2));
        mx1 = fmaxf(mx1, __shfl_xor_sync(~0u, mx1, 1));
        mx1 = fmaxf(mx1, __shfl_xor_sync(~0u, mx1, 2));
        float mn0 = fmaxf(m0, mx0), mn1 = fmaxf(m1, mx1);
        float a0 = exp2f(m0 - mn0), a1 = exp2f(m1 - mn1);
        float rs0 = 0.f, rs1 = 0.f;
#pragma unroll
        for (int j = 0; j < 8; j++) {
            S[j][0] = exp2f(S[j][0] - mn0); S[j][1] = exp2f(S[j][1] - mn0);
            S[j][2] = exp2f(S[j][2] - mn1); S[j][3] = exp2f(S[j][3] - mn1);
            rs0 += S[j][0] + S[j][1];
            rs1 += S[j][2] + S[j][3];
        }
        rs0 += __shfl_xor_sync(~0u, rs0, 1); rs0 += __shfl_xor_sync(~0u, rs0, 2);
        rs1 += __shfl_xor_sync(~0u, rs1, 1); rs1 += __shfl_xor_sync(~0u, rs1, 2);
        l0 = l0 * a0 + rs0; l1 = l1 * a1 + rs1;
        m0 = mn0; m1 = mn1;
#pragma unroll
        for (int j = 0; j < 8; j++) {
            O[j][0] *= a0; O[j][1] *= a0; O[j][2] *= a1; O[j][3] *= a1;
        }

        // ---- P fragments: single fp16
        uint32_t pf[4][4];
#pragma unroll
        for (int c = 0; c < 4; c++) {
            pf[c][0] = pack_f16x2(S[2 * c][0],     S[2 * c][1]);
            pf[c][1] = pack_f16x2(S[2 * c][2],     S[2 * c][3]);
            pf[c][2] = pack_f16x2(S[2 * c + 1][0], S[2 * c + 1][1]);
            pf[c][3] = pack_f16x2(S[2 * c + 1][2], S[2 * c + 1][3]);
        }

        // ---- O += P V (single fp16 pass)
        {
            int rbase = (lane & 15);
            int cb2 = (lane >> 4) * 8;
#pragma unroll
            for (int jj = 0; jj < 8; jj += 2) {
#pragma unroll
                for (int c = 0; c < 4; c++) {
                    uint32_t off = (uint32_t)((c * 16 + rbase) * PAD + jj * 8 + cb2);
                    uint32_t vf[4];
                    LDSM_X4_T(vf[0], vf[1], vf[2], vf[3], smem_u32(sVf + off));
                    MMAF16(O[jj],     pf[c], vf[0], vf[1]);
                    MMAF16(O[jj + 1], pf[c], vf[2], vf[3]);
                }
            }
        }
        __syncthreads();
    }

    // ---- epilogue
    float inv0 = 1.f / l0, inv1 = 1.f / l1;
    int g = lane >> 2, tg = lane & 3;
    int b_ = bh / NH, h = bh % NH;
    int r0 = qb + wid * 16 + g, r1 = r0 + 8;
    long ob0 = ((long)b_ * NSEQ + r0) * DIM + h * HD;
    long ob1 = ((long)b_ * NSEQ + r1) * DIM + h * HD;
#pragma unroll
    for (int j = 0; j < 8; j++) {
        int d = 8 * j + tg * 2;
        uint32_t hh, ll;
        split_pack(O[j][0] * inv0, O[j][1] * inv0, hh, ll);
        *(uint32_t*)(g_AOh + ob0 + d) = hh;
        *(uint32_t*)(g_AOl + ob0 + d) = ll;
        split_pack(O[j][2] * inv1, O[j][3] * inv1, hh, ll);
        *(uint32_t*)(g_AOh + ob1 + d) = hh;
        *(uint32_t*)(g_AOl + ob1 + d) = ll;
    }
}

// ---------------------------------------------------------------------------
// Stage 5: out = AO @ pw^T + pb (mma bf16x3, M=128 N=64, cp.async dbuf, 2/SM)
#define PBUF (55296)
__global__ void __launch_bounds__(256, 2) k_proj_mma(const float* __restrict__ pb,
                                                     float* __restrict__ out) {
    extern __shared__ __align__(16) char smraw[];
    int tid = threadIdx.x, wid = tid >> 5, lane = tid & 31;
    int m0 = blockIdx.x * 128, n0 = blockIdx.y * 64;
    uint32_t sb = smem_u32(smraw);
    float C[8][4] = {};

    for (int i = tid; i < 128 * 8; i += 256) {
        int r = i >> 3, c = (i & 7) * 8;
        uint32_t doff = (uint32_t)((r * PAD + c) * 2);
        long ga = (long)(m0 + r) * DIM + c;
        CP16(sb + 0 + doff, g_AOh + ga);
        CP16(sb + 18432 + doff, g_AOl + ga);
    }
    for (int i = tid; i < 64 * 8; i += 256) {
        int r = i >> 3, c = (i & 7) * 8;
        uint32_t doff = (uint32_t)((r * PAD + c) * 2);
        long gb = (long)(n0 + r) * DIM + c;
        CP16(sb + 36864 + doff, g_pwh + gb);
        CP16(sb + 46080 + doff, g_pwl + gb);
    }
    CPCOMMIT();

    for (int kb = 0; kb < 12; kb++) {
        if (kb < 11) {
            uint32_t dbase = sb + ((kb + 1) & 1) * PBUF;
            for (int i = tid; i < 128 * 8; i += 256) {
                int r = i >> 3, c = (i & 7) * 8;
                uint32_t doff = (uint32_t)((r * PAD + c) * 2);
                long ga = (long)(m0 + r) * DIM + (kb + 1) * 64 + c;
                CP16(dbase + 0 + doff, g_AOh + ga);
                CP16(dbase + 18432 + doff, g_AOl + ga);
            }
            for (int i = tid; i < 64 * 8; i += 256) {
                int r = i >> 3, c = (i & 7) * 8;
                uint32_t doff = (uint32_t)((r * PAD + c) * 2);
                long gb = (long)(n0 + r) * DIM + (kb + 1) * 64 + c;
                CP16(dbase + 36864 + doff, g_pwh + gb);
                CP16(dbase + 46080 + doff, g_pwl + gb);
            }
            CPCOMMIT();
            CPWAIT1();
        } else {
            CPWAIT0();
        }
        __syncthreads();

        __nv_bfloat16* bufp = (__nv_bfloat16*)(smraw + (kb & 1) * PBUF);
        __nv_bfloat16* sAh = bufp;
        __nv_bfloat16* sAl = sAh + 128 * PAD;
        __nv_bfloat16* sBh = sAl + 128 * PAD;
        __nv_bfloat16* sBl = sBh + 64 * PAD;

        uint32_t ah[4][4], al[4][4];
        {
            int rowb = wid * 16 + (lane & 15);
            int colb = (lane >> 4) * 8;
#pragma unroll
            for (int c = 0; c < 4; c++) {
                LDSM_X4(ah[c][0], ah[c][1], ah[c][2], ah[c][3],
                        smem_u32(sAh + rowb * PAD + c * 16 + colb));
                LDSM_X4(al[c][0], al[c][1], al[c][2], al[c][3],
                        smem_u32(sAl + rowb * PAD + c * 16 + colb));
            }
        }
        {
            int rbase = (lane & 7);
            int cbase = (lane >> 3) * 8;
#pragma unroll
            for (int j = 0; j < 8; j++) {
                uint32_t off = (uint32_t)((8 * j + rbase) * PAD + cbase);
                uint32_t bh01[4], bh23[4], bl01[4], bl23[4];
                LDSM_X4(bh01[0], bh01[1], bh01[2], bh01[3], smem_u32(sBh + off));
                LDSM_X4(bh23[0], bh23[1], bh23[2], bh23[3], smem_u32(sBh + off + 32));
                LDSM_X4(bl01[0], bl01[1], bl01[2], bl01[3], smem_u32(sBl + off));
                LDSM_X4(bl23[0], bl23[1], bl23[2], bl23[3], smem_u32(sBl + off + 32));
                MMA16816(C[j], ah[0], bh01[0], bh01[1]);
                MMA16816(C[j], ah[1], bh01[2], bh01[3]);
                MMA16816(C[j], ah[2], bh23[0], bh23[1]);
                MMA16816(C[j], ah[3], bh23[2], bh23[3]);
                MMA16816(C[j], ah[0], bl01[0], bl01[1]);
                MMA16816(C[j], ah[1], bl01[2], bl01[3]);
                MMA16816(C[j], ah[2], bl23[0], bl23[1]);
                MMA16816(C[j], ah[3], bl23[2], bl23[3]);
                MMA16816(C[j], al[0], bh01[0], bh01[1]);
                MMA16816(C[j], al[1], bh01[2], bh01[3]);
                MMA16816(C[j], al[2], bh23[0], bh23[1]);
                MMA16816(C[j], al[3], bh23[2], bh23[3]);
            }
        }
        __syncthreads();
    }

    int g = lane >> 2, tg = lane & 3;
    int r0 = m0 + wid * 16 + g, r1 = r0 + 8;
#pragma unroll
    for (int j = 0; j < 8; j++) {
        int col = n0 + 8 * j + tg * 2;
        float b0 = pb[col], b1 = pb[col + 1];
        *(float2*)(out + (long)r0 * DIM + col) = make_float2(C[j][0] + b0, C[j][1] + b1);
        *(float2*)(out + (long)r1 * DIM + col) = make_float2(C[j][2] + b0, C[j][3] + b1);
    }
}

// ---------------------------------------------------------------------------
extern "C" void kernel_launch(void* const* d_in, const int* in_sizes, int n_in,
                              void* d_out, int out_size) {
    const float* x   = (const float*)d_in[0];
    const float* WQ0 = (const float*)d_in[1];
    const float* WQ1 = (const float*)d_in[2];
    const float* WQ2 = (const float*)d_in[3];
    const float* WK0 = (const float*)d_in[4];
    const float* WK1 = (const float*)d_in[5];
    const float* WK2 = (const float*)d_in[6];
    const float* WV0 = (const float*)d_in[7];
    const float* WV1 = (const float*)d_in[8];
    const float* WV2 = (const float*)d_in[9];
    const float* pw  = (const float*)d_in[10];
    const float* pb  = (const float*)d_in[11];
    float* out = (float*)d_out;

    const int SM_GT   = 2 * GBUF;                   // 73728
    const int SM_EXP  = (128 + 64) * PAD * 2 * 2;   // 55296
    const int SM_PROJ = 2 * PBUF;                   // 110592
    cudaFuncSetAttribute(k_gemm_T_mma, cudaFuncAttributeMaxDynamicSharedMemorySize, SM_GT);
    cudaFuncSetAttribute(k_expand_mma, cudaFuncAttributeMaxDynamicSharedMemorySize, SM_EXP);
    cudaFuncSetAttribute(k_flash,      cudaFuncAttributeMaxDynamicSharedMemorySize, SM_FLASH);
    cudaFuncSetAttribute(k_proj_mma,   cudaFuncAttributeMaxDynamicSharedMemorySize, SM_PROJ);

    k_split_x<<<(BN * DIM / 2 + 255) / 256, 256>>>(x);
    k_build_weff<<<(3 * DIM * RNK + 255) / 256, 256>>>(WQ1, WQ2, WK1, WK2, WV1, WV2);
    k_split_pw<<<(DIM * DIM + 255) / 256, 256>>>(pw);
    k_gemm_T_mma<<<dim3(BN / 64, 3), 256, SM_GT>>>();
    k_expand_mma<<<dim3(BN / 128, NH, 3), 256, SM_EXP>>>(WQ0, WK0, WV0);
    k_flash<<<dim3(NSEQ / 128, NBH), 256, SM_FLASH>>>();
    k_proj_mma<<<dim3(BN / 128, DIM / 64), 256, SM_PROJ>>>(pb, out);
}

// round 8
// speedup vs baseline: 3.6167x; 1.0172x over previous
#include <cuda_runtime.h>
#include <cuda_bf16.h>
#include <cuda_fp16.h>
#include <cstdint>

#define BSZ  8
#define NSEQ 1024
#define DIM  768
#define NH   12
#define HD   64
#define RNK  64
#define BN   (BSZ*NSEQ)          /* 8192 */
#define NBH  (BSZ*NH)            /* 96 */
#define PAD  72                  /* padded smem row stride in 16-bit elems */
#define QSCALE 0.1803368801111f  /* 0.125 * log2(e) */

// ---------------------------------------------------------------------------
// Scratch (device globals; allocation-free per harness rules)
__device__ __nv_bfloat16 g_xh[(size_t)BN*DIM];
__device__ __nv_bfloat16 g_xl[(size_t)BN*DIM];
__device__ __nv_bfloat16 g_Wefh[192*DIM];            // [n=p*64+r][k=dim]
__device__ __nv_bfloat16 g_Wefl[192*DIM];
__device__ __nv_bfloat16 g_W0h[3*DIM*RNK];           // [p][hd][r]
__device__ __nv_bfloat16 g_W0l[3*DIM*RNK];
__device__ __nv_bfloat16 g_Th[(size_t)BN*192];       // [i][p*64+r]
__device__ __nv_bfloat16 g_Tl[(size_t)BN*192];
__device__ __nv_bfloat16 g_Qh[(size_t)NBH*NSEQ*HD];  // [bh][l][d] (pre-scaled by QSCALE)
__device__ __nv_bfloat16 g_Ql[(size_t)NBH*NSEQ*HD];
__device__ __nv_bfloat16 g_Kh[(size_t)NBH*NSEQ*HD];
__device__ __nv_bfloat16 g_Kl[(size_t)NBH*NSEQ*HD];
__device__ __half        g_Vf[(size_t)NBH*NSEQ*HD];  // single fp16, row-major [l][d]
__device__ __nv_bfloat16 g_AOh[(size_t)BN*DIM];      // [b*l][h*64+d]
__device__ __nv_bfloat16 g_AOl[(size_t)BN*DIM];
__device__ __nv_bfloat16 g_pwh[DIM*DIM];
__device__ __nv_bfloat16 g_pwl[DIM*DIM];

// ---------------------------------------------------------------------------
// helpers (baseline PTX, sm_80+)
__device__ __forceinline__ uint32_t smem_u32(const void* p) {
    uint32_t a;
    asm("{ .reg .u64 t; cvta.to.shared.u64 t, %1; cvt.u32.u64 %0, t; }" : "=r"(a) : "l"(p));
    return a;
}
#define LDSM_X4(r0,r1,r2,r3,addr) \
    asm volatile("ldmatrix.sync.aligned.m8n8.x4.shared.b16 {%0,%1,%2,%3}, [%4];" \
        : "=r"(r0), "=r"(r1), "=r"(r2), "=r"(r3) : "r"(addr))
#define LDSM_X4_T(r0,r1,r2,r3,addr) \
    asm volatile("ldmatrix.sync.aligned.m8n8.x4.trans.shared.b16 {%0,%1,%2,%3}, [%4];" \
        : "=r"(r0), "=r"(r1), "=r"(r2), "=r"(r3) : "r"(addr))
#define MMA16816(c, a, b0_, b1_) \
    asm volatile("mma.sync.aligned.m16n8k16.row.col.f32.bf16.bf16.f32 " \
        "{%0,%1,%2,%3}, {%4,%5,%6,%7}, {%8,%9}, {%0,%1,%2,%3};" \
        : "+f"((c)[0]), "+f"((c)[1]), "+f"((c)[2]), "+f"((c)[3]) \
        : "r"((a)[0]), "r"((a)[1]), "r"((a)[2]), "r"((a)[3]), "r"(b0_), "r"(b1_))
#define MMAF16(c, a, b0_, b1_) \
    asm volatile("mma.sync.aligned.m16n8k16.row.col.f32.f16.f16.f32 " \
        "{%0,%1,%2,%3}, {%4,%5,%6,%7}, {%8,%9}, {%0,%1,%2,%3};" \
        : "+f"((c)[0]), "+f"((c)[1]), "+f"((c)[2]), "+f"((c)[3]) \
        : "r"((a)[0]), "r"((a)[1]), "r"((a)[2]), "r"((a)[3]), "r"(b0_), "r"(b1_))
#define CP16(dst, src) \
    asm volatile("cp.async.cg.shared.global [%0], [%1], 16;" :: "r"(dst), "l"(src))
#define CPCOMMIT() asm volatile("cp.async.commit_group;" ::: "memory")
#define CPWAIT0()  asm volatile("cp.async.wait_group 0;" ::: "memory")

__device__ __forceinline__ void split2(float f, __nv_bfloat16& h, __nv_bfloat16& l) {
    h = __float2bfloat16(f);
    l = __float2bfloat16(f - __bfloat162float(h));
}
__device__ __forceinline__ void split_pack(float f0, float f1, uint32_t& h, uint32_t& l) {
    uint32_t hh;
    asm("cvt.rn.bf16x2.f32 %0, %1, %2;" : "=r"(hh) : "f"(f1), "f"(f0));
    float h0 = __uint_as_float(hh << 16);
    float h1 = __uint_as_float(hh & 0xffff0000u);
    float l0 = f0 - h0, l1 = f1 - h1;
    uint32_t ll;
    asm("cvt.rn.bf16x2.f32 %0, %1, %2;" : "=r"(ll) : "f"(l1), "f"(l0));
    h = hh; l = ll;
}
__device__ __forceinline__ uint32_t pack_f16x2(float f0, float f1) {
    uint32_t r;
    asm("cvt.rn.f16x2.f32 %0, %1, %2;" : "=r"(r) : "f"(f1), "f"(f0));
    return r;
}

// ---------------------------------------------------------------------------
// Stage 0: split x into bf16 hi/lo
__global__ void k_split_x(const float* __restrict__ x) {
    int i = blockIdx.x * blockDim.x + threadIdx.x;
    if (i >= BN * DIM / 2) return;
    float2 v = *(const float2*)(x + 2 * (size_t)i);
    uint32_t h, l;
    split_pack(v.x, v.y, h, l);
    *(uint32_t*)(g_xh + 2 * (size_t)i) = h;
    *(uint32_t*)(g_xl + 2 * (size_t)i) = l;
}

// Stage 1: Weff (transposed, split)
__global__ void k_build_weff(const float* __restrict__ W1q, const float* __restrict__ W2q,
                             const float* __restrict__ W1k, const float* __restrict__ W2k,
                             const float* __restrict__ W1v, const float* __restrict__ W2v) {
    int idx = blockIdx.x * blockDim.x + threadIdx.x;
    if (idx >= 3 * DIM * RNK) return;
    int p = idx / (DIM * RNK);
    int rem = idx % (DIM * RNK);
    int c = rem / RNK, r = rem % RNK;
    const float* W1 = (p == 0) ? W1q : ((p == 1) ? W1k : W1v);
    const float* W2 = (p == 0) ? W2q : ((p == 1) ? W2k : W2v);
    float f = W1[(c >> 6) * RNK + r] * W2[(c & 63) * RNK + r];
    __nv_bfloat16 h, l;
    split2(f, h, l);
    g_Wefh[(p * 64 + r) * DIM + c] = h;
    g_Wefl[(p * 64 + r) * DIM + c] = l;
}

__global__ void k_split_pw(const float* __restrict__ pw) {
    int i = blockIdx.x * blockDim.x + threadIdx.x;
    if (i >= DIM * DIM) return;
    split2(pw[i], g_pwh[i], g_pwl[i]);
}

// pre-split W0 (fp32 [768,64] x3) into bf16 hi/lo
__global__ void k_split_w0(const float* __restrict__ W0q, const float* __restrict__ W0k,
                           const float* __restrict__ W0v) {
    int idx = blockIdx.x * blockDim.x + threadIdx.x;
    if (idx >= 3 * DIM * RNK) return;
    int p = idx / (DIM * RNK);
    int rem = idx % (DIM * RNK);
    const float* W0 = (p == 0) ? W0q : ((p == 1) ? W0k : W0v);
    __nv_bfloat16 h, l;
    split2(W0[rem], h, l);
    g_W0h[idx] = h;
    g_W0l[idx] = l;
}

// ---------------------------------------------------------------------------
// Stage 2: T = x @ Weff (mma bf16x3). M=64, N=64, warps 4x2, cp.async dbuf,
// single barrier per k-iter: wait0 -> sync -> commit(next) -> compute.
#define GBUF 36864
__global__ void __launch_bounds__(256, 2) k_gemm_T_mma() {
    extern __shared__ __align__(16) char smraw[];
    uint32_t sb = smem_u32(smraw);
    int tid = threadIdx.x, wid = tid >> 5, lane = tid & 31;
    int wm = wid >> 1, wn = wid & 1;
    int m0 = blockIdx.x * 64, n0 = blockIdx.y * 64;
    float C[4][4] = {};

    // prefetch kb=0 into buf0
    for (int i = tid; i < 64 * 8; i += 256) {
        int r = i >> 3, c = (i & 7) * 8;
        uint32_t doff = (uint32_t)((r * PAD + c) * 2);
        long ga = (long)(m0 + r) * DIM + c;
        long gb = (long)(n0 + r) * DIM + c;
        CP16(sb + 0     + doff, g_xh + ga);
        CP16(sb + 9216  + doff, g_xl + ga);
        CP16(sb + 18432 + doff, g_Wefh + gb);
        CP16(sb + 27648 + doff, g_Wefl + gb);
    }
    CPCOMMIT();

    for (int kb = 0; kb < 12; kb++) {
        CPWAIT0();
        __syncthreads();
        if (kb < 11) {
            uint32_t dbase = sb + ((kb + 1) & 1) * GBUF;
            for (int i = tid; i < 64 * 8; i += 256) {
                int r = i >> 3, c = (i & 7) * 8;
                uint32_t doff = (uint32_t)((r * PAD + c) * 2);
                long ga = (long)(m0 + r) * DIM + (kb + 1) * 64 + c;
                long gb = (long)(n0 + r) * DIM + (kb + 1) * 64 + c;
                CP16(dbase + 0     + doff, g_xh + ga);
                CP16(dbase + 9216  + doff, g_xl + ga);
                CP16(dbase + 18432 + doff, g_Wefh + gb);
                CP16(dbase + 27648 + doff, g_Wefl + gb);
            }
            CPCOMMIT();
        }

        __nv_bfloat16* bufp = (__nv_bfloat16*)(smraw + (kb & 1) * GBUF);
        __nv_bfloat16* sAh = bufp;
        __nv_bfloat16* sAl = sAh + 64 * PAD;
        __nv_bfloat16* sBh = sAl + 64 * PAD;
        __nv_bfloat16* sBl = sBh + 64 * PAD;

        uint32_t ah[4][4], al[4][4];
        {
            int rowb = wm * 16 + (lane & 15);
            int colb = (lane >> 4) * 8;
#pragma unroll
            for (int c = 0; c < 4; c++) {
                LDSM_X4(ah[c][0], ah[c][1], ah[c][2], ah[c][3],
                        smem_u32(sAh + rowb * PAD + c * 16 + colb));
                LDSM_X4(al[c][0], al[c][1], al[c][2], al[c][3],
                        smem_u32(sAl + rowb * PAD + c * 16 + colb));
            }
        }
        {
            int rbase = (lane & 7);
            int cbase = (lane >> 3) * 8;
#pragma unroll
            for (int j = 0; j < 4; j++) {
                uint32_t off = (uint32_t)((wn * 32 + 8 * j + rbase) * PAD + cbase);
                uint32_t bh01[4], bh23[4], bl01[4], bl23[4];
                LDSM_X4(bh01[0], bh01[1], bh01[2], bh01[3], smem_u32(sBh + off));
                LDSM_X4(bh23[0], bh23[1], bh23[2], bh23[3], smem_u32(sBh + off + 32));
                LDSM_X4(bl01[0], bl01[1], bl01[2], bl01[3], smem_u32(sBl + off));
                LDSM_X4(bl23[0], bl23[1], bl23[2], bl23[3], smem_u32(sBl + off + 32));
                MMA16816(C[j], ah[0], bh01[0], bh01[1]);
                MMA16816(C[j], ah[1], bh01[2], bh01[3]);
                MMA16816(C[j], ah[2], bh23[0], bh23[1]);
                MMA16816(C[j], ah[3], bh23[2], bh23[3]);
                MMA16816(C[j], ah[0], bl01[0], bl01[1]);
                MMA16816(C[j], ah[1], bl01[2], bl01[3]);
                MMA16816(C[j], ah[2], bl23[0], bl23[1]);
                MMA16816(C[j], ah[3], bl23[2], bl23[3]);
                MMA16816(C[j], al[0], bh01[0], bh01[1]);
                MMA16816(C[j], al[1], bh01[2], bh01[3]);
                MMA16816(C[j], al[2], bh23[0], bh23[1]);
                MMA16816(C[j], al[3], bh23[2], bh23[3]);
            }
        }
    }
    int g = lane >> 2, tg = lane & 3;
    int r0 = m0 + wm * 16 + g, r1 = r0 + 8;
#pragma unroll
    for (int j = 0; j < 4; j++) {
        int col = n0 + wn * 32 + 8 * j + tg * 2;
        uint32_t hh, ll;
        split_pack(C[j][0], C[j][1], hh, ll);
        *(uint32_t*)(g_Th + (long)r0 * 192 + col) = hh;
        *(uint32_t*)(g_Tl + (long)r0 * 192 + col) = ll;
        split_pack(C[j][2], C[j][3], hh, ll);
        *(uint32_t*)(g_Th + (long)r1 * 192 + col) = hh;
        *(uint32_t*)(g_Tl + (long)r1 * 192 + col) = ll;
    }
}

// ---------------------------------------------------------------------------
// Stage 3: Q/K/V = T_p @ W0_h^T. M=128, N=64, K=64. All inputs via cp.async.
__global__ void __launch_bounds__(256, 2) k_expand_mma() {
    extern __shared__ __align__(16) char smraw[];
    __nv_bfloat16* sAh = (__nv_bfloat16*)smraw;          // 128 x PAD
    __nv_bfloat16* sAl = sAh + 128 * PAD;
    __nv_bfloat16* sBh = sAl + 128 * PAD;                // 64 x PAD
    __nv_bfloat16* sBl = sBh + 64 * PAD;
    int p = blockIdx.z, h = blockIdx.y;
    int m0 = blockIdx.x * 128;
    int tid = threadIdx.x, wid = tid >> 5, lane = tid & 31;
    uint32_t sb = smem_u32(smraw);

    for (int i = tid; i < 128 * 8; i += 256) {
        int r = i >> 3, c = (i & 7) * 8;
        uint32_t doff = (uint32_t)((r * PAD + c) * 2);
        long ga = (long)(m0 + r) * 192 + p * 64 + c;
        CP16(sb + doff, g_Th + ga);
        CP16(sb + 128 * PAD * 2 + doff, g_Tl + ga);
    }
    for (int i = tid; i < 64 * 8; i += 256) {
        int r = i >> 3, c = (i & 7) * 8;
        uint32_t doff = (uint32_t)((r * PAD + c) * 2);
        long gb = (long)(p * DIM + h * 64 + r) * RNK + c;
        CP16(sb + 256 * PAD * 2 + doff, g_W0h + gb);
        CP16(sb + 320 * PAD * 2 + doff, g_W0l + gb);
    }
    CPCOMMIT();
    CPWAIT0();
    __syncthreads();

    float C[8][4] = {};
    uint32_t ah[4][4], al[4][4];
    {
        int rowb = wid * 16 + (lane & 15);
        int colb = (lane >> 4) * 8;
#pragma unroll
        for (int c = 0; c < 4; c++) {
            LDSM_X4(ah[c][0], ah[c][1], ah[c][2], ah[c][3],
                    smem_u32(sAh + rowb * PAD + c * 16 + colb));
            LDSM_X4(al[c][0], al[c][1], al[c][2], al[c][3],
                    smem_u32(sAl + rowb * PAD + c * 16 + colb));
        }
    }
    {
        int rbase = (lane & 7);
        int cbase = (lane >> 3) * 8;
#pragma unroll
        for (int j = 0; j < 8; j++) {
            uint32_t off = (uint32_t)((8 * j + rbase) * PAD + cbase);
            uint32_t bh01[4], bh23[4], bl01[4], bl23[4];
            LDSM_X4(bh01[0], bh01[1], bh01[2], bh01[3], smem_u32(sBh + off));
            LDSM_X4(bh23[0], bh23[1], bh23[2], bh23[3], smem_u32(sBh + off + 32));
            LDSM_X4(bl01[0], bl01[1], bl01[2], bl01[3], smem_u32(sBl + off));
            LDSM_X4(bl23[0], bl23[1], bl23[2], bl23[3], smem_u32(sBl + off + 32));
            MMA16816(C[j], ah[0], bh01[0], bh01[1]);
            MMA16816(C[j], ah[1], bh01[2], bh01[3]);
            MMA16816(C[j], ah[2], bh23[0], bh23[1]);
            MMA16816(C[j], ah[3], bh23[2], bh23[3]);
            MMA16816(C[j], ah[0], bl01[0], bl01[1]);
            MMA16816(C[j], ah[1], bl01[2], bl01[3]);
            MMA16816(C[j], ah[2], bl23[0], bl23[1]);
            MMA16816(C[j], ah[3], bl23[2], bl23[3]);
            MMA16816(C[j], al[0], bh01[0], bh01[1]);
            MMA16816(C[j], al[1], bh01[2], bh01[3]);
            MMA16816(C[j], al[2], bh23[0], bh23[1]);
            MMA16816(C[j], al[3], bh23[2], bh23[3]);
        }
    }

    int g = lane >> 2, tg = lane & 3;
    float sc = (p == 0) ? QSCALE : 1.0f;
#pragma unroll
    for (int rr = 0; rr < 2; rr++) {
        int row = m0 + wid * 16 + g + rr * 8;
        int b_ = row >> 10, l = row & 1023;
        long base = ((long)b_ * NH + h) * 65536 + (long)l * 64;
        if (p == 2) {
#pragma unroll
            for (int j = 0; j < 8; j++) {
                int d = 8 * j + tg * 2;
                *(uint32_t*)(g_Vf + base + d) = pack_f16x2(C[j][2 * rr], C[j][2 * rr + 1]);
            }
        } else {
            __nv_bfloat16* gh = (p == 0) ? g_Qh : g_Kh;
            __nv_bfloat16* gl = (p == 0) ? g_Ql : g_Kl;
#pragma unroll
            for (int j = 0; j < 8; j++) {
                int d = 8 * j + tg * 2;
                uint32_t hh, ll;
                split_pack(C[j][2 * rr] * sc, C[j][2 * rr + 1] * sc, hh, ll);
                *(uint32_t*)(gh + base + d) = hh;
                *(uint32_t*)(gl + base + d) = ll;
            }
        }
    }
}

// ---------------------------------------------------------------------------
// Stage 4: fused flash attention. S = bf16x3, P*V = single fp16 pass.
// Single barrier per KV iter: wait0 -> sync -> commit(next) -> compute.
#define FQBYTES (128 * PAD * 2)          /* 18432 */
#define FKV0    (2 * FQBYTES)            /* 36864 */
#define FBUF    (3 * 64 * PAD * 2)       /* 27648 per buffer */
#define SM_FLASH (FKV0 + 2 * FBUF)       /* 92160 */
__global__ void __launch_bounds__(256, 2) k_flash() {
    extern __shared__ __align__(16) char smraw[];
    int tid = threadIdx.x, wid = tid >> 5, lane = tid & 31;
    int bh = blockIdx.y, qb = blockIdx.x * 128;
    long base = (long)bh * NSEQ * HD;
    uint32_t sb = smem_u32(smraw);
    __nv_bfloat16* sQh = (__nv_bfloat16*)smraw;
    __nv_bfloat16* sQl = sQh + 128 * PAD;

    // stage Q (persistent) + prefetch t=0 K/V (one group)
    for (int i = tid; i < 128 * 8; i += 256) {
        int r = i >> 3, c = (i & 7) * 8;
        uint32_t doff = (uint32_t)((r * PAD + c) * 2);
        long g = base + (long)(qb + r) * 64 + c;
        CP16(sb + doff, g_Qh + g);
        CP16(sb + FQBYTES + doff, g_Ql + g);
    }
    for (int i = tid; i < 64 * 8; i += 256) {
        int r = i >> 3, c = (i & 7) * 8;
        uint32_t doff = (uint32_t)((r * PAD + c) * 2);
        long g = base + (long)r * 64 + c;
        CP16(sb + FKV0 + 0     + doff, g_Kh + g);
        CP16(sb + FKV0 + 9216  + doff, g_Kl + g);
        CP16(sb + FKV0 + 18432 + doff, g_Vf + g);
    }
    CPCOMMIT();
    CPWAIT0();
    __syncthreads();

    uint32_t qh[4][4], ql[4][4];
    {
        int qrowb = wid * 16 + (lane & 15);
        int qcolb = (lane >> 4) * 8;
#pragma unroll
        for (int c = 0; c < 4; c++) {
            LDSM_X4(qh[c][0], qh[c][1], qh[c][2], qh[c][3],
                    smem_u32(sQh + qrowb * PAD + c * 16 + qcolb));
            LDSM_X4(ql[c][0], ql[c][1], ql[c][2], ql[c][3],
                    smem_u32(sQl + qrowb * PAD + c * 16 + qcolb));
        }
    }

    float m0 = -1e30f, m1 = -1e30f, l0 = 0.f, l1 = 0.f;
    float O[8][4] = {};

    for (int t = 0; t < 16; t++) {
        CPWAIT0();          // this thread's copies for tile t complete
        __syncthreads();    // all threads' data visible; all done reading buf[(t-1)&1]
        if (t < 15) {       // prefetch t+1 into the other buffer; overlaps compute
            uint32_t dbase = sb + FKV0 + ((t + 1) & 1) * FBUF;
            long gb = base + (long)(t + 1) * 64 * 64;
            for (int i = tid; i < 64 * 8; i += 256) {
                int r = i >> 3, c = (i & 7) * 8;
                uint32_t doff = (uint32_t)((r * PAD + c) * 2);
                long g = gb + (long)r * 64 + c;
                CP16(dbase + 0     + doff, g_Kh + g);
                CP16(dbase + 9216  + doff, g_Kl + g);
                CP16(dbase + 18432 + doff, g_Vf + g);
            }
            CPCOMMIT();
        }

        char* bufp = smraw + FKV0 + (t & 1) * FBUF;
        __nv_bfloat16* sKh = (__nv_bfloat16*)bufp;
        __nv_bfloat16* sKl = (__nv_bfloat16*)(bufp + 9216);
        __half*        sVf = (__half*)(bufp + 18432);

        // ---- S = Q K^T (bf16 3-pass), log2 domain
        float S[8][4] = {};
        {
            int rbase = (lane & 7);
            int cbase = (lane >> 3) * 8;
#pragma unroll
            for (int j = 0; j < 8; j++) {
                uint32_t off = (uint32_t)((8 * j + rbase) * PAD + cbase);
                uint32_t bh01[4], bh23[4], bl01[4], bl23[4];
                LDSM_X4(bh01[0], bh01[1], bh01[2], bh01[3], smem_u32(sKh + off));
                LDSM_X4(bh23[0], bh23[1], bh23[2], bh23[3], smem_u32(sKh + off + 32));
                LDSM_X4(bl01[0], bl01[1], bl01[2], bl01[3], smem_u32(sKl + off));
                LDSM_X4(bl23[0], bl23[1], bl23[2], bl23[3], smem_u32(sKl + off + 32));
                MMA16816(S[j], qh[0], bh01[0], bh01[1]);
                MMA16816(S[j], qh[1], bh01[2], bh01[3]);
                MMA16816(S[j], qh[2], bh23[0], bh23[1]);
                MMA16816(S[j], qh[3], bh23[2], bh23[3]);
                MMA16816(S[j], qh[0], bl01[0], bl01[1]);
                MMA16816(S[j], qh[1], bl01[2], bl01[3]);
                MMA16816(S[j], qh[2], bl23[0], bl23[1]);
                MMA16816(S[j], qh[3], bl23[2], bl23[3]);
                MMA16816(S[j], ql[0], bh01[0], bh01[1]);
                MMA16816(S[j], ql[1], bh01[2], bh01[3]);
                MMA16816(S[j], ql[2], bh23[0], bh23[1]);
                MMA16816(S[j], ql[3], bh23[2], bh23[3]);
            }
        }

        // ---- online softmax (exp2 domain)
        float mx0 = -1e30f, mx1 = -1e30f;
#pragma unroll
        for (int j = 0; j < 8; j++) {
            mx0 = fmaxf(mx0, fmaxf(S[j][0], S[j][1]));
            mx1 = fmaxf(mx1, fmaxf(S[j][2], S[j][3]));
        }
        mx0 = fmaxf(mx0, __shfl_xor_sync(~0u, mx0, 1));
        mx0 = fmaxf(mx0, __shfl_xor_sync(~0u, mx0, 2));
        mx1 = fmaxf(mx1, __shfl_xor_sync(~0u, mx1, 1));
        mx1 = fmaxf(mx1, __shfl_xor_sync(~0u, mx1, 2));
        float mn0 = fmaxf(m0, mx0), mn1 = fmaxf(m1, mx1);
        float a0 = exp2f(m0 - mn0), a1 = exp2f(m1 - mn1);
        float rs0 = 0.f, rs1 = 0.f;
#pragma unroll
        for (int j = 0; j < 8; j++) {
            S[j][0] = exp2f(S[j][0] - mn0); S[j][1] = exp2f(S[j][1] - mn0);
            S[j][2] = exp2f(S[j][2] - mn1); S[j][3] = exp2f(S[j][3] - mn1);
            rs0 += S[j][0] + S[j][1];
            rs1 += S[j][2] + S[j][3];
        }
        rs0 += __shfl_xor_sync(~0u, rs0, 1); rs0 += __shfl_xor_sync(~0u, rs0, 2);
        rs1 += __shfl_xor_sync(~0u, rs1, 1); rs1 += __shfl_xor_sync(~0u, rs1, 2);
        l0 = l0 * a0 + rs0; l1 = l1 * a1 + rs1;
        m0 = mn0; m1 = mn1;
#pragma unroll
        for (int j = 0; j < 8; j++) {
            O[j][0] *= a0; O[j][1] *= a0; O[j][2] *= a1; O[j][3] *= a1;
        }

        // ---- P fragments: single fp16
        uint32_t pf[4][4];
#pragma unroll
        for (int c = 0; c < 4; c++) {
            pf[c][0] = pack_f16x2(S[2 * c][0],     S[2 * c][1]);
            pf[c][1] = pack_f16x2(S[2 * c][2],     S[2 * c][3]);
            pf[c][2] = pack_f16x2(S[2 * c + 1][0], S[2 * c + 1][1]);
            pf[c][3] = pack_f16x2(S[2 * c + 1][2], S[2 * c + 1][3]);
        }

        // ---- O += P V (single fp16 pass)
        {
            int rbase = (lane & 15);
            int cb2 = (lane >> 4) * 8;
#pragma unroll
            for (int jj = 0; jj < 8; jj += 2) {
#pragma unroll
                for (int c = 0; c < 4; c++) {
                    uint32_t off = (uint32_t)((c * 16 + rbase) * PAD + jj * 8 + cb2);
                    uint32_t vf[4];
                    LDSM_X4_T(vf[0], vf[1], vf[2], vf[3], smem_u32(sVf + off));
                    MMAF16(O[jj],     pf[c], vf[0], vf[1]);
                    MMAF16(O[jj + 1], pf[c], vf[2], vf[3]);
                }
            }
        }
    }

    // ---- epilogue
    float inv0 = 1.f / l0, inv1 = 1.f / l1;
    int g = lane >> 2, tg = lane & 3;
    int b_ = bh / NH, h = bh % NH;
    int r0 = qb + wid * 16 + g, r1 = r0 + 8;
    long ob0 = ((long)b_ * NSEQ + r0) * DIM + h * HD;
    long ob1 = ((long)b_ * NSEQ + r1) * DIM + h * HD;
#pragma unroll
    for (int j = 0; j < 8; j++) {
        int d = 8 * j + tg * 2;
        uint32_t hh, ll;
        split_pack(O[j][0] * inv0, O[j][1] * inv0, hh, ll);
        *(uint32_t*)(g_AOh + ob0 + d) = hh;
        *(uint32_t*)(g_AOl + ob0 + d) = ll;
        split_pack(O[j][2] * inv1, O[j][3] * inv1, hh, ll);
        *(uint32_t*)(g_AOh + ob1 + d) = hh;
        *(uint32_t*)(g_AOl + ob1 + d) = ll;
    }
}

// ---------------------------------------------------------------------------
// Stage 5: out = AO @ pw^T + pb (mma bf16x3, M=128 N=64, cp.async dbuf,
// single barrier per k-iter, 2 CTAs/SM)
#define PBUF (55296)
__global__ void __launch_bounds__(256, 2) k_proj_mma(const float* __restrict__ pb,
                                                     float* __restrict__ out) {
    extern __shared__ __align__(16) char smraw[];
    int tid = threadIdx.x, wid = tid >> 5, lane = tid & 31;
    int m0 = blockIdx.x * 128, n0 = blockIdx.y * 64;
    uint32_t sb = smem_u32(smraw);
    float C[8][4] = {};

    for (int i = tid; i < 128 * 8; i += 256) {
        int r = i >> 3, c = (i & 7) * 8;
        uint32_t doff = (uint32_t)((r * PAD + c) * 2);
        long ga = (long)(m0 + r) * DIM + c;
        CP16(sb + 0 + doff, g_AOh + ga);
        CP16(sb + 18432 + doff, g_AOl + ga);
    }
    for (int i = tid; i < 64 * 8; i += 256) {
        int r = i >> 3, c = (i & 7) * 8;
        uint32_t doff = (uint32_t)((r * PAD + c) * 2);
        long gb = (long)(n0 + r) * DIM + c;
        CP16(sb + 36864 + doff, g_pwh + gb);
        CP16(sb + 46080 + doff, g_pwl + gb);
    }
    CPCOMMIT();

    for (int kb = 0; kb < 12; kb++) {
        CPWAIT0();
        __syncthreads();
        if (kb < 11) {
            uint32_t dbase = sb + ((kb + 1) & 1) * PBUF;
            for (int i = tid; i < 128 * 8; i += 256) {
                int r = i >> 3, c = (i & 7) * 8;
                uint32_t doff = (uint32_t)((r * PAD + c) * 2);
                long ga = (long)(m0 + r) * DIM + (kb + 1) * 64 + c;
                CP16(dbase + 0 + doff, g_AOh + ga);
                CP16(dbase + 18432 + doff, g_AOl + ga);
            }
            for (int i = tid; i < 64 * 8; i += 256) {
                int r = i >> 3, c = (i & 7) * 8;
                uint32_t doff = (uint32_t)((r * PAD + c) * 2);
                long gb = (long)(n0 + r) * DIM + (kb + 1) * 64 + c;
                CP16(dbase + 36864 + doff, g_pwh + gb);
                CP16(dbase + 46080 + doff, g_pwl + gb);
            }
            CPCOMMIT();
        }

        __nv_bfloat16* bufp = (__nv_bfloat16*)(smraw + (kb & 1) * PBUF);
        __nv_bfloat16* sAh = bufp;
        __nv_bfloat16* sAl = sAh + 128 * PAD;
        __nv_bfloat16* sBh = sAl + 128 * PAD;
        __nv_bfloat16* sBl = sBh + 64 * PAD;

        uint32_t ah[4][4], al[4][4];
        {
            int rowb = wid * 16 + (lane & 15);
            int colb = (lane >> 4) * 8;
#pragma unroll
            for (int c = 0; c < 4; c++) {
                LDSM_X4(ah[c][0], ah[c][1], ah[c][2], ah[c][3],
                        smem_u32(sAh + rowb * PAD + c * 16 + colb));
                LDSM_X4(al[c][0], al[c][1], al[c][2], al[c][3],
                        smem_u32(sAl + rowb * PAD + c * 16 + colb));
            }
        }
        {
            int rbase = (lane & 7);
            int cbase = (lane >> 3) * 8;
#pragma unroll
            for (int j = 0; j < 8; j++) {
                uint32_t off = (uint32_t)((8 * j + rbase) * PAD + cbase);
                uint32_t bh01[4], bh23[4], bl01[4], bl23[4];
                LDSM_X4(bh01[0], bh01[1], bh01[2], bh01[3], smem_u32(sBh + off));
                LDSM_X4(bh23[0], bh23[1], bh23[2], bh23[3], smem_u32(sBh + off + 32));
                LDSM_X4(bl01[0], bl01[1], bl01[2], bl01[3], smem_u32(sBl + off));
                LDSM_X4(bl23[0], bl23[1], bl23[2], bl23[3], smem_u32(sBl + off + 32));
                MMA16816(C[j], ah[0], bh01[0], bh01[1]);
                MMA16816(C[j], ah[1], bh01[2], bh01[3]);
                MMA16816(C[j], ah[2], bh23[0], bh23[1]);
                MMA16816(C[j], ah[3], bh23[2], bh23[3]);
                MMA16816(C[j], ah[0], bl01[0], bl01[1]);
                MMA16816(C[j], ah[1], bl01[2], bl01[3]);
                MMA16816(C[j], ah[2], bl23[0], bl23[1]);
                MMA16816(C[j], ah[3], bl23[2], bl23[3]);
                MMA16816(C[j], al[0], bh01[0], bh01[1]);
                MMA16816(C[j], al[1], bh01[2], bh01[3]);
                MMA16816(C[j], al[2], bh23[0], bh23[1]);
                MMA16816(C[j], al[3], bh23[2], bh23[3]);
            }
        }
    }

    int g = lane >> 2, tg = lane & 3;
    int r0 = m0 + wid * 16 + g, r1 = r0 + 8;
#pragma unroll
    for (int j = 0; j < 8; j++) {
        int col = n0 + 8 * j + tg * 2;
        float b0 = pb[col], b1 = pb[col + 1];
        *(float2*)(out + (long)r0 * DIM + col) = make_float2(C[j][0] + b0, C[j][1] + b1);
        *(float2*)(out + (long)r1 * DIM + col) = make_float2(C[j][2] + b0, C[j][3] + b1);
    }
}

// ---------------------------------------------------------------------------
extern "C" void kernel_launch(void* const* d_in, const int* in_sizes, int n_in,
                              void* d_out, int out_size) {
    const float* x   = (const float*)d_in[0];
    const float* WQ0 = (const float*)d_in[1];
    const float* WQ1 = (const float*)d_in[2];
    const float* WQ2 = (const float*)d_in[3];
    const float* WK0 = (const float*)d_in[4];
    const float* WK1 = (const float*)d_in[5];
    const float* WK2 = (const float*)d_in[6];
    const float* WV0 = (const float*)d_in[7];
    const float* WV1 = (const float*)d_in[8];
    const float* WV2 = (const float*)d_in[9];
    const float* pw  = (const float*)d_in[10];
    const float* pb  = (const float*)d_in[11];
    float* out = (float*)d_out;

    const int SM_GT   = 2 * GBUF;                   // 73728
    const int SM_EXP  = (128 + 64) * PAD * 2 * 2;   // 55296
    const int SM_PROJ = 2 * PBUF;                   // 110592
    cudaFuncSetAttribute(k_gemm_T_mma, cudaFuncAttributeMaxDynamicSharedMemorySize, SM_GT);
    cudaFuncSetAttribute(k_expand_mma, cudaFuncAttributeMaxDynamicSharedMemorySize, SM_EXP);
    cudaFuncSetAttribute(k_flash,      cudaFuncAttributeMaxDynamicSharedMemorySize, SM_FLASH);
    cudaFuncSetAttribute(k_proj_mma,   cudaFuncAttributeMaxDynamicSharedMemorySize, SM_PROJ);

    k_split_x<<<(BN * DIM / 2 + 255) / 256, 256>>>(x);
    k_build_weff<<<(3 * DIM * RNK + 255) / 256, 256>>>(WQ1, WQ2, WK1, WK2, WV1, WV2);
    k_split_pw<<<(DIM * DIM + 255) / 256, 256>>>(pw);
    k_split_w0<<<(3 * DIM * RNK + 255) / 256, 256>>>(WQ0, WK0, WV0);
    k_gemm_T_mma<<<dim3(BN / 64, 3), 256, SM_GT>>>();
    k_expand_mma<<<dim3(BN / 128, NH, 3), 256, SM_EXP>>>();
    k_flash<<<dim3(NSEQ / 128, NBH), 256, SM_FLASH>>>();
    k_proj_mma<<<dim3(BN / 128, DIM / 64), 256, SM_PROJ>>>(pb, out);
}

// round 9
// speedup vs baseline: 3.6565x; 1.0110x over previous
#include <cuda_runtime.h>
#include <cuda_bf16.h>
#include <cuda_fp16.h>
#include <cstdint>

#define BSZ  8
#define NSEQ 1024
#define DIM  768
#define NH   12
#define HD   64
#define RNK  64
#define BN   (BSZ*NSEQ)          /* 8192 */
#define NBH  (BSZ*NH)            /* 96 */
#define PAD  72                  /* padded smem row stride in 16-bit elems */
#define QSCALE 0.1803368801111f  /* 0.125 * log2(e) */

// ---------------------------------------------------------------------------
// Scratch (device globals; allocation-free per harness rules)
__device__ __nv_bfloat16 g_xh[(size_t)BN*DIM];
__device__ __nv_bfloat16 g_xl[(size_t)BN*DIM];
__device__ __nv_bfloat16 g_Wefh[192*DIM];            // [n=p*64+r][k=dim]
__device__ __nv_bfloat16 g_Wefl[192*DIM];
__device__ __nv_bfloat16 g_W0h[3*DIM*RNK];           // [p][hd][r]
__device__ __nv_bfloat16 g_W0l[3*DIM*RNK];
__device__ __nv_bfloat16 g_Th[(size_t)BN*192];       // [i][p*64+r]
__device__ __nv_bfloat16 g_Tl[(size_t)BN*192];
__device__ __nv_bfloat16 g_Qh[(size_t)NBH*NSEQ*HD];  // [bh][l][d] (pre-scaled by QSCALE)
__device__ __nv_bfloat16 g_Ql[(size_t)NBH*NSEQ*HD];
__device__ __nv_bfloat16 g_Kh[(size_t)NBH*NSEQ*HD];
__device__ __nv_bfloat16 g_Kl[(size_t)NBH*NSEQ*HD];
__device__ __half        g_Vf[(size_t)NBH*NSEQ*HD];  // single fp16, row-major [l][d]
__device__ __nv_bfloat16 g_AOh[(size_t)BN*DIM];      // [b*l][h*64+d]
__device__ __nv_bfloat16 g_AOl[(size_t)BN*DIM];
__device__ __nv_bfloat16 g_pwh[DIM*DIM];
__device__ __nv_bfloat16 g_pwl[DIM*DIM];

// ---------------------------------------------------------------------------
// helpers (baseline PTX, sm_80+)
__device__ __forceinline__ uint32_t smem_u32(const void* p) {
    uint32_t a;
    asm("{ .reg .u64 t; cvta.to.shared.u64 t, %1; cvt.u32.u64 %0, t; }" : "=r"(a) : "l"(p));
    return a;
}
#define LDSM_X4(r0,r1,r2,r3,addr) \
    asm volatile("ldmatrix.sync.aligned.m8n8.x4.shared.b16 {%0,%1,%2,%3}, [%4];" \
        : "=r"(r0), "=r"(r1), "=r"(r2), "=r"(r3) : "r"(addr))
#define LDSM_X4_T(r0,r1,r2,r3,addr) \
    asm volatile("ldmatrix.sync.aligned.m8n8.x4.trans.shared.b16 {%0,%1,%2,%3}, [%4];" \
        : "=r"(r0), "=r"(r1), "=r"(r2), "=r"(r3) : "r"(addr))
#define MMA16816(c, a, b0_, b1_) \
    asm volatile("mma.sync.aligned.m16n8k16.row.col.f32.bf16.bf16.f32 " \
        "{%0,%1,%2,%3}, {%4,%5,%6,%7}, {%8,%9}, {%0,%1,%2,%3};" \
        : "+f"((c)[0]), "+f"((c)[1]), "+f"((c)[2]), "+f"((c)[3]) \
        : "r"((a)[0]), "r"((a)[1]), "r"((a)[2]), "r"((a)[3]), "r"(b0_), "r"(b1_))
#define MMAF16(c, a, b0_, b1_) \
    asm volatile("mma.sync.aligned.m16n8k16.row.col.f32.f16.f16.f32 " \
        "{%0,%1,%2,%3}, {%4,%5,%6,%7}, {%8,%9}, {%0,%1,%2,%3};" \
        : "+f"((c)[0]), "+f"((c)[1]), "+f"((c)[2]), "+f"((c)[3]) \
        : "r"((a)[0]), "r"((a)[1]), "r"((a)[2]), "r"((a)[3]), "r"(b0_), "r"(b1_))
#define CP16(dst, src) \
    asm volatile("cp.async.cg.shared.global [%0], [%1], 16;" :: "r"(dst), "l"(src))
#define CPCOMMIT() asm volatile("cp.async.commit_group;" ::: "memory")
#define CPWAIT0()  asm volatile("cp.async.wait_group 0;" ::: "memory")

__device__ __forceinline__ void split2(float f, __nv_bfloat16& h, __nv_bfloat16& l) {
    h = __float2bfloat16(f);
    l = __float2bfloat16(f - __bfloat162float(h));
}
__device__ __forceinline__ void split_pack(float f0, float f1, uint32_t& h, uint32_t& l) {
    uint32_t hh;
    asm("cvt.rn.bf16x2.f32 %0, %1, %2;" : "=r"(hh) : "f"(f1), "f"(f0));
    float h0 = __uint_as_float(hh << 16);
    float h1 = __uint_as_float(hh & 0xffff0000u);
    float l0 = f0 - h0, l1 = f1 - h1;
    uint32_t ll;
    asm("cvt.rn.bf16x2.f32 %0, %1, %2;" : "=r"(ll) : "f"(l1), "f"(l0));
    h = hh; l = ll;
}
__device__ __forceinline__ uint32_t pack_f16x2(float f0, float f1) {
    uint32_t r;
    asm("cvt.rn.f16x2.f32 %0, %1, %2;" : "=r"(r) : "f"(f1), "f"(f0));
    return r;
}

// ---------------------------------------------------------------------------
// Stage 0+1: fused preprocessing — split x / pw / W0, build Weff.
// Block ranges: [0,12288) split_x | [12288,13440) split_pw |
//               [13440,14016) weff | [14016,14592) split_w0
__global__ void k_prep(const float* __restrict__ x,  const float* __restrict__ pw,
                       const float* __restrict__ W0q, const float* __restrict__ W0k,
                       const float* __restrict__ W0v,
                       const float* __restrict__ W1q, const float* __restrict__ W2q,
                       const float* __restrict__ W1k, const float* __restrict__ W2k,
                       const float* __restrict__ W1v, const float* __restrict__ W2v) {
    int b = blockIdx.x, tid = threadIdx.x;
    if (b < 12288) {                      // split_x: one float2 per thread
        size_t i = (size_t)b * 256 + tid;
        float2 v = *(const float2*)(x + 2 * i);
        uint32_t h, l;
        split_pack(v.x, v.y, h, l);
        *(uint32_t*)(g_xh + 2 * i) = h;
        *(uint32_t*)(g_xl + 2 * i) = l;
    } else if (b < 13440) {               // split_pw: one float2 per thread
        size_t i = (size_t)(b - 12288) * 256 + tid;
        float2 v = *(const float2*)(pw + 2 * i);
        uint32_t h, l;
        split_pack(v.x, v.y, h, l);
        *(uint32_t*)(g_pwh + 2 * i) = h;
        *(uint32_t*)(g_pwl + 2 * i) = l;
    } else if (b < 14016) {               // build Weff (transposed, split)
        int idx = (b - 13440) * 256 + tid;
        int p = idx / (DIM * RNK);
        int rem = idx % (DIM * RNK);
        int c = rem / RNK, r = rem % RNK;
        const float* W1 = (p == 0) ? W1q : ((p == 1) ? W1k : W1v);
        const float* W2 = (p == 0) ? W2q : ((p == 1) ? W2k : W2v);
        float f = W1[(c >> 6) * RNK + r] * W2[(c & 63) * RNK + r];
        __nv_bfloat16 h, l;
        split2(f, h, l);
        g_Wefh[(p * 64 + r) * DIM + c] = h;
        g_Wefl[(p * 64 + r) * DIM + c] = l;
    } else {                              // split_w0
        int idx = (b - 14016) * 256 + tid;
        int p = idx / (DIM * RNK);
        int rem = idx % (DIM * RNK);
        const float* W0 = (p == 0) ? W0q : ((p == 1) ? W0k : W0v);
        __nv_bfloat16 h, l;
        split2(W0[rem], h, l);
        g_W0h[idx] = h;
        g_W0l[idx] = l;
    }
}

// ---------------------------------------------------------------------------
// Stage 2: T = x @ Weff (mma bf16x3). M=64, N=64, warps 4x2, cp.async dbuf,
// single barrier per k-iter.
#define GBUF 36864
__global__ void __launch_bounds__(256, 2) k_gemm_T_mma() {
    extern __shared__ __align__(16) char smraw[];
    uint32_t sb = smem_u32(smraw);
    int tid = threadIdx.x, wid = tid >> 5, lane = tid & 31;
    int wm = wid >> 1, wn = wid & 1;
    int m0 = blockIdx.x * 64, n0 = blockIdx.y * 64;
    float C[4][4] = {};

    for (int i = tid; i < 64 * 8; i += 256) {
        int r = i >> 3, c = (i & 7) * 8;
        uint32_t doff = (uint32_t)((r * PAD + c) * 2);
        long ga = (long)(m0 + r) * DIM + c;
        long gb = (long)(n0 + r) * DIM + c;
        CP16(sb + 0     + doff, g_xh + ga);
        CP16(sb + 9216  + doff, g_xl + ga);
        CP16(sb + 18432 + doff, g_Wefh + gb);
        CP16(sb + 27648 + doff, g_Wefl + gb);
    }
    CPCOMMIT();

    for (int kb = 0; kb < 12; kb++) {
        CPWAIT0();
        __syncthreads();
        if (kb < 11) {
            uint32_t dbase = sb + ((kb + 1) & 1) * GBUF;
            for (int i = tid; i < 64 * 8; i += 256) {
                int r = i >> 3, c = (i & 7) * 8;
                uint32_t doff = (uint32_t)((r * PAD + c) * 2);
                long ga = (long)(m0 + r) * DIM + (kb + 1) * 64 + c;
                long gb = (long)(n0 + r) * DIM + (kb + 1) * 64 + c;
                CP16(dbase + 0     + doff, g_xh + ga);
                CP16(dbase + 9216  + doff, g_xl + ga);
                CP16(dbase + 18432 + doff, g_Wefh + gb);
                CP16(dbase + 27648 + doff, g_Wefl + gb);
            }
            CPCOMMIT();
        }

        __nv_bfloat16* bufp = (__nv_bfloat16*)(smraw + (kb & 1) * GBUF);
        __nv_bfloat16* sAh = bufp;
        __nv_bfloat16* sAl = sAh + 64 * PAD;
        __nv_bfloat16* sBh = sAl + 64 * PAD;
        __nv_bfloat16* sBl = sBh + 64 * PAD;

        uint32_t ah[4][4], al[4][4];
        {
            int rowb = wm * 16 + (lane & 15);
            int colb = (lane >> 4) * 8;
#pragma unroll
            for (int c = 0; c < 4; c++) {
                LDSM_X4(ah[c][0], ah[c][1], ah[c][2], ah[c][3],
                        smem_u32(sAh + rowb * PAD + c * 16 + colb));
                LDSM_X4(al[c][0], al[c][1], al[c][2], al[c][3],
                        smem_u32(sAl + rowb * PAD + c * 16 + colb));
            }
        }
        {
            int rbase = (lane & 7);
            int cbase = (lane >> 3) * 8;
#pragma unroll
            for (int j = 0; j < 4; j++) {
                uint32_t off = (uint32_t)((wn * 32 + 8 * j + rbase) * PAD + cbase);
                uint32_t bh01[4], bh23[4], bl01[4], bl23[4];
                LDSM_X4(bh01[0], bh01[1], bh01[2], bh01[3], smem_u32(sBh + off));
                LDSM_X4(bh23[0], bh23[1], bh23[2], bh23[3], smem_u32(sBh + off + 32));
                LDSM_X4(bl01[0], bl01[1], bl01[2], bl01[3], smem_u32(sBl + off));
                LDSM_X4(bl23[0], bl23[1], bl23[2], bl23[3], smem_u32(sBl + off + 32));
                MMA16816(C[j], ah[0], bh01[0], bh01[1]);
                MMA16816(C[j], ah[1], bh01[2], bh01[3]);
                MMA16816(C[j], ah[2], bh23[0], bh23[1]);
                MMA16816(C[j], ah[3], bh23[2], bh23[3]);
                MMA16816(C[j], ah[0], bl01[0], bl01[1]);
                MMA16816(C[j], ah[1], bl01[2], bl01[3]);
                MMA16816(C[j], ah[2], bl23[0], bl23[1]);
                MMA16816(C[j], ah[3], bl23[2], bl23[3]);
                MMA16816(C[j], al[0], bh01[0], bh01[1]);
                MMA16816(C[j], al[1], bh01[2], bh01[3]);
                MMA16816(C[j], al[2], bh23[0], bh23[1]);
                MMA16816(C[j], al[3], bh23[2], bh23[3]);
            }
        }
    }
    int g = lane >> 2, tg = lane & 3;
    int r0 = m0 + wm * 16 + g, r1 = r0 + 8;
#pragma unroll
    for (int j = 0; j < 4; j++) {
        int col = n0 + wn * 32 + 8 * j + tg * 2;
        uint32_t hh, ll;
        split_pack(C[j][0], C[j][1], hh, ll);
        *(uint32_t*)(g_Th + (long)r0 * 192 + col) = hh;
        *(uint32_t*)(g_Tl + (long)r0 * 192 + col) = ll;
        split_pack(C[j][2], C[j][3], hh, ll);
        *(uint32_t*)(g_Th + (long)r1 * 192 + col) = hh;
        *(uint32_t*)(g_Tl + (long)r1 * 192 + col) = ll;
    }
}

// ---------------------------------------------------------------------------
// Stage 3: Q/K/V = T_p @ W0_h^T. M=128, N=64, K=64. All inputs via cp.async.
__global__ void __launch_bounds__(256, 2) k_expand_mma() {
    extern __shared__ __align__(16) char smraw[];
    __nv_bfloat16* sAh = (__nv_bfloat16*)smraw;          // 128 x PAD
    __nv_bfloat16* sAl = sAh + 128 * PAD;
    __nv_bfloat16* sBh = sAl + 128 * PAD;                // 64 x PAD
    __nv_bfloat16* sBl = sBh + 64 * PAD;
    int p = blockIdx.z, h = blockIdx.y;
    int m0 = blockIdx.x * 128;
    int tid = threadIdx.x, wid = tid >> 5, lane = tid & 31;
    uint32_t sb = smem_u32(smraw);

    for (int i = tid; i < 128 * 8; i += 256) {
        int r = i >> 3, c = (i & 7) * 8;
        uint32_t doff = (uint32_t)((r * PAD + c) * 2);
        long ga = (long)(m0 + r) * 192 + p * 64 + c;
        CP16(sb + doff, g_Th + ga);
        CP16(sb + 128 * PAD * 2 + doff, g_Tl + ga);
    }
    for (int i = tid; i < 64 * 8; i += 256) {
        int r = i >> 3, c = (i & 7) * 8;
        uint32_t doff = (uint32_t)((r * PAD + c) * 2);
        long gb = (long)(p * DIM + h * 64 + r) * RNK + c;
        CP16(sb + 256 * PAD * 2 + doff, g_W0h + gb);
        CP16(sb + 320 * PAD * 2 + doff, g_W0l + gb);
    }
    CPCOMMIT();
    CPWAIT0();
    __syncthreads();

    float C[8][4] = {};
    uint32_t ah[4][4], al[4][4];
    {
        int rowb = wid * 16 + (lane & 15);
        int colb = (lane >> 4) * 8;
#pragma unroll
        for (int c = 0; c < 4; c++) {
            LDSM_X4(ah[c][0], ah[c][1], ah[c][2], ah[c][3],
                    smem_u32(sAh + rowb * PAD + c * 16 + colb));
            LDSM_X4(al[c][0], al[c][1], al[c][2], al[c][3],
                    smem_u32(sAl + rowb * PAD + c * 16 + colb));
        }
    }
    {
        int rbase = (lane & 7);
        int cbase = (lane >> 3) * 8;
#pragma unroll
        for (int j = 0; j < 8; j++) {
            uint32_t off = (uint32_t)((8 * j + rbase) * PAD + cbase);
            uint32_t bh01[4], bh23[4], bl01[4], bl23[4];
            LDSM_X4(bh01[0], bh01[1], bh01[2], bh01[3], smem_u32(sBh + off));
            LDSM_X4(bh23[0], bh23[1], bh23[2], bh23[3], smem_u32(sBh + off + 32));
            LDSM_X4(bl01[0], bl01[1], bl01[2], bl01[3], smem_u32(sBl + off));
            LDSM_X4(bl23[0], bl23[1], bl23[2], bl23[3], smem_u32(sBl + off + 32));
            MMA16816(C[j], ah[0], bh01[0], bh01[1]);
            MMA16816(C[j], ah[1], bh01[2], bh01[3]);
            MMA16816(C[j], ah[2], bh23[0], bh23[1]);
            MMA16816(C[j], ah[3], bh23[2], bh23[3]);
            MMA16816(C[j], ah[0], bl01[0], bl01[1]);
            MMA16816(C[j], ah[1], bl01[2], bl01[3]);
            MMA16816(C[j], ah[2], bl23[0], bl23[1]);
            MMA16816(C[j], ah[3], bl23[2], bl23[3]);
            MMA16816(C[j], al[0], bh01[0], bh01[1]);
            MMA16816(C[j], al[1], bh01[2], bh01[3]);
            MMA16816(C[j], al[2], bh23[0], bh23[1]);
            MMA16816(C[j], al[3], bh23[2], bh23[3]);
        }
    }

    int g = lane >> 2, tg = lane & 3;
    float sc = (p == 0) ? QSCALE : 1.0f;
#pragma unroll
    for (int rr = 0; rr < 2; rr++) {
        int row = m0 + wid * 16 + g + rr * 8;
        int b_ = row >> 10, l = row & 1023;
        long base = ((long)b_ * NH + h) * 65536 + (long)l * 64;
        if (p == 2) {
#pragma unroll
            for (int j = 0; j < 8; j++) {
                int d = 8 * j + tg * 2;
                *(uint32_t*)(g_Vf + base + d) = pack_f16x2(C[j][2 * rr], C[j][2 * rr + 1]);
            }
        } else {
            __nv_bfloat16* gh = (p == 0) ? g_Qh : g_Kh;
            __nv_bfloat16* gl = (p == 0) ? g_Ql : g_Kl;
#pragma unroll
            for (int j = 0; j < 8; j++) {
                int d = 8 * j + tg * 2;
                uint32_t hh, ll;
                split_pack(C[j][2 * rr] * sc, C[j][2 * rr + 1] * sc, hh, ll);
                *(uint32_t*)(gh + base + d) = hh;
                *(uint32_t*)(gl + base + d) = ll;
            }
        }
    }
}

// ---------------------------------------------------------------------------
// Stage 4: fused flash attention. S = bf16x3, P*V = single fp16 pass.
// Softmax interleaved with PV per k-chunk: exp2/pack of chunk c+1 issue while
// tensor pipe runs chunk c's PV MMAs (within-warp MUFU/tensor overlap).
#define FQBYTES (128 * PAD * 2)          /* 18432 */
#define FKV0    (2 * FQBYTES)            /* 36864 */
#define FBUF    (3 * 64 * PAD * 2)       /* 27648 per buffer */
#define SM_FLASH (FKV0 + 2 * FBUF)       /* 92160 */
__global__ void __launch_bounds__(256, 2) k_flash() {
    extern __shared__ __align__(16) char smraw[];
    int tid = threadIdx.x, wid = tid >> 5, lane = tid & 31;
    int bh = blockIdx.y, qb = blockIdx.x * 128;
    long base = (long)bh * NSEQ * HD;
    uint32_t sb = smem_u32(smraw);
    __nv_bfloat16* sQh = (__nv_bfloat16*)smraw;
    __nv_bfloat16* sQl = sQh + 128 * PAD;

    for (int i = tid; i < 128 * 8; i += 256) {
        int r = i >> 3, c = (i & 7) * 8;
        uint32_t doff = (uint32_t)((r * PAD + c) * 2);
        long g = base + (long)(qb + r) * 64 + c;
        CP16(sb + doff, g_Qh + g);
        CP16(sb + FQBYTES + doff, g_Ql + g);
    }
    for (int i = tid; i < 64 * 8; i += 256) {
        int r = i >> 3, c = (i & 7) * 8;
        uint32_t doff = (uint32_t)((r * PAD + c) * 2);
        long g = base + (long)r * 64 + c;
        CP16(sb + FKV0 + 0     + doff, g_Kh + g);
        CP16(sb + FKV0 + 9216  + doff, g_Kl + g);
        CP16(sb + FKV0 + 18432 + doff, g_Vf + g);
    }
    CPCOMMIT();
    CPWAIT0();
    __syncthreads();

    uint32_t qh[4][4], ql[4][4];
    {
        int qrowb = wid * 16 + (lane & 15);
        int qcolb = (lane >> 4) * 8;
#pragma unroll
        for (int c = 0; c < 4; c++) {
            LDSM_X4(qh[c][0], qh[c][1], qh[c][2], qh[c][3],
                    smem_u32(sQh + qrowb * PAD + c * 16 + qcolb));
            LDSM_X4(ql[c][0], ql[c][1], ql[c][2], ql[c][3],
                    smem_u32(sQl + qrowb * PAD + c * 16 + qcolb));
        }
    }

    float m0 = -1e30f, m1 = -1e30f, l0 = 0.f, l1 = 0.f;
    float O[8][4] = {};

    for (int t = 0; t < 16; t++) {
        CPWAIT0();
        __syncthreads();
        if (t < 15) {
            uint32_t dbase = sb + FKV0 + ((t + 1) & 1) * FBUF;
            long gb = base + (long)(t + 1) * 64 * 64;
            for (int i = tid; i < 64 * 8; i += 256) {
                int r = i >> 3, c = (i & 7) * 8;
                uint32_t doff = (uint32_t)((r * PAD + c) * 2);
                long g = gb + (long)r * 64 + c;
                CP16(dbase + 0     + doff, g_Kh + g);
                CP16(dbase + 9216  + doff, g_Kl + g);
                CP16(dbase + 18432 + doff, g_Vf + g);
            }
            CPCOMMIT();
        }

        char* bufp = smraw + FKV0 + (t & 1) * FBUF;
        __nv_bfloat16* sKh = (__nv_bfloat16*)bufp;
        __nv_bfloat16* sKl = (__nv_bfloat16*)(bufp + 9216);
        __half*        sVf = (__half*)(bufp + 18432);

        // ---- S = Q K^T (bf16 3-pass), log2 domain
        float S[8][4] = {};
        {
            int rbase = (lane & 7);
            int cbase = (lane >> 3) * 8;
#pragma unroll
            for (int j = 0; j < 8; j++) {
                uint32_t off = (uint32_t)((8 * j + rbase) * PAD + cbase);
                uint32_t bh01[4], bh23[4], bl01[4], bl23[4];
                LDSM_X4(bh01[0], bh01[1], bh01[2], bh01[3], smem_u32(sKh + off));
                LDSM_X4(bh23[0], bh23[1], bh23[2], bh23[3], smem_u32(sKh + off + 32));
                LDSM_X4(bl01[0], bl01[1], bl01[2], bl01[3], smem_u32(sKl + off));
                LDSM_X4(bl23[0], bl23[1], bl23[2], bl23[3], smem_u32(sKl + off + 32));
                MMA16816(S[j], qh[0], bh01[0], bh01[1]);
                MMA16816(S[j], qh[1], bh01[2], bh01[3]);
                MMA16816(S[j], qh[2], bh23[0], bh23[1]);
                MMA16816(S[j], qh[3], bh23[2], bh23[3]);
                MMA16816(S[j], qh[0], bl01[0], bl01[1]);
                MMA16816(S[j], qh[1], bl01[2], bl01[3]);
                MMA16816(S[j], qh[2], bl23[0], bl23[1]);
                MMA16816(S[j], qh[3], bl23[2], bl23[3]);
                MMA16816(S[j], ql[0], bh01[0], bh01[1]);
                MMA16816(S[j], ql[1], bh01[2], bh01[3]);
                MMA16816(S[j], ql[2], bh23[0], bh23[1]);
                MMA16816(S[j], ql[3], bh23[2], bh23[3]);
            }
        }

        // ---- online softmax: row max + O rescale
        float mx0 = -1e30f, mx1 = -1e30f;
#pragma unroll
        for (int j = 0; j < 8; j++) {
            mx0 = fmaxf(mx0, fmaxf(S[j][0], S[j][1]));
            mx1 = fmaxf(mx1, fmaxf(S[j][2], S[j][3]));
        }
        mx0 = fmaxf(mx0, __shfl_xor_sync(~0u, mx0, 1));
        mx0 = fmaxf(mx0, __shfl_xor_sync(~0u, mx0, 2));
        mx1 = fmaxf(mx1, __shfl_xor_sync(~0u, mx1, 1));
        mx1 = fmaxf(mx1, __shfl_xor_sync(~0u, mx1, 2));
        float mn0 = fmaxf(m0, mx0), mn1 = fmaxf(m1, mx1);
        float a0 = exp2f(m0 - mn0), a1 = exp2f(m1 - mn1);
        m0 = mn0; m1 = mn1;
#pragma unroll
        for (int j = 0; j < 8; j++) {
            O[j][0] *= a0; O[j][1] *= a0; O[j][2] *= a1; O[j][3] *= a1;
        }

        // ---- interleaved exp2 / pack / PV per k-chunk c (16 keys each).
        // exp2s of chunk c+1 are independent of chunk c's MMAs -> tensor
        // pipe stays fed through MUFU work.
        float rs0 = 0.f, rs1 = 0.f;
        {
            int rbase = (lane & 15);
            int cb2 = (lane >> 4) * 8;
#pragma unroll
            for (int c = 0; c < 4; c++) {
                int j0 = 2 * c, j1 = 2 * c + 1;
                S[j0][0] = exp2f(S[j0][0] - mn0); S[j0][1] = exp2f(S[j0][1] - mn0);
                S[j0][2] = exp2f(S[j0][2] - mn1); S[j0][3] = exp2f(S[j0][3] - mn1);
                S[j1][0] = exp2f(S[j1][0] - mn0); S[j1][1] = exp2f(S[j1][1] - mn0);
                S[j1][2] = exp2f(S[j1][2] - mn1); S[j1][3] = exp2f(S[j1][3] - mn1);
                rs0 += S[j0][0] + S[j0][1] + S[j1][0] + S[j1][1];
                rs1 += S[j0][2] + S[j0][3] + S[j1][2] + S[j1][3];
                uint32_t pf[4];
                pf[0] = pack_f16x2(S[j0][0], S[j0][1]);
                pf[1] = pack_f16x2(S[j0][2], S[j0][3]);
                pf[2] = pack_f16x2(S[j1][0], S[j1][1]);
                pf[3] = pack_f16x2(S[j1][2], S[j1][3]);
#pragma unroll
                for (int jj = 0; jj < 8; jj += 2) {
                    uint32_t off = (uint32_t)((c * 16 + rbase) * PAD + jj * 8 + cb2);
                    uint32_t vf[4];
                    LDSM_X4_T(vf[0], vf[1], vf[2], vf[3], smem_u32(sVf + off));
                    MMAF16(O[jj],     pf, vf[0], vf[1]);
                    MMAF16(O[jj + 1], pf, vf[2], vf[3]);
                }
            }
        }
        rs0 += __shfl_xor_sync(~0u, rs0, 1); rs0 += __shfl_xor_sync(~0u, rs0, 2);
        rs1 += __shfl_xor_sync(~0u, rs1, 1); rs1 += __shfl_xor_sync(~0u, rs1, 2);
        l0 = l0 * a0 + rs0; l1 = l1 * a1 + rs1;
    }

    // ---- epilogue
    float inv0 = 1.f / l0, inv1 = 1.f / l1;
    int g = lane >> 2, tg = lane & 3;
    int b_ = bh / NH, h = bh % NH;
    int r0 = qb + wid * 16 + g, r1 = r0 + 8;
    long ob0 = ((long)b_ * NSEQ + r0) * DIM + h * HD;
    long ob1 = ((long)b_ * NSEQ + r1) * DIM + h * HD;
#pragma unroll
    for (int j = 0; j < 8; j++) {
        int d = 8 * j + tg * 2;
        uint32_t hh, ll;
        split_pack(O[j][0] * inv0, O[j][1] * inv0, hh, ll);
        *(uint32_t*)(g_AOh + ob0 + d) = hh;
        *(uint32_t*)(g_AOl + ob0 + d) = ll;
        split_pack(O[j][2] * inv1, O[j][3] * inv1, hh, ll);
        *(uint32_t*)(g_AOh + ob1 + d) = hh;
        *(uint32_t*)(g_AOl + ob1 + d) = ll;
    }
}

// ---------------------------------------------------------------------------
// Stage 5: out = AO @ pw^T + pb (mma bf16x3, M=128 N=64, cp.async dbuf,
// single barrier per k-iter, 2 CTAs/SM)
#define PBUF (55296)
__global__ void __launch_bounds__(256, 2) k_proj_mma(const float* __restrict__ pb,
                                                     float* __restrict__ out) {
    extern __shared__ __align__(16) char smraw[];
    int tid = threadIdx.x, wid = tid >> 5, lane = tid & 31;
    int m0 = blockIdx.x * 128, n0 = blockIdx.y * 64;
    uint32_t sb = smem_u32(smraw);
    float C[8][4] = {};

    for (int i = tid; i < 128 * 8; i += 256) {
        int r = i >> 3, c = (i & 7) * 8;
        uint32_t doff = (uint32_t)((r * PAD + c) * 2);
        long ga = (long)(m0 + r) * DIM + c;
        CP16(sb + 0 + doff, g_AOh + ga);
        CP16(sb + 18432 + doff, g_AOl + ga);
    }
    for (int i = tid; i < 64 * 8; i += 256) {
        int r = i >> 3, c = (i & 7) * 8;
        uint32_t doff = (uint32_t)((r * PAD + c) * 2);
        long gb = (long)(n0 + r) * DIM + c;
        CP16(sb + 36864 + doff, g_pwh + gb);
        CP16(sb + 46080 + doff, g_pwl + gb);
    }
    CPCOMMIT();

    for (int kb = 0; kb < 12; kb++) {
        CPWAIT0();
        __syncthreads();
        if (kb < 11) {
            uint32_t dbase = sb + ((kb + 1) & 1) * PBUF;
            for (int i = tid; i < 128 * 8; i += 256) {
                int r = i >> 3, c = (i & 7) * 8;
                uint32_t doff = (uint32_t)((r * PAD + c) * 2);
                long ga = (long)(m0 + r) * DIM + (kb + 1) * 64 + c;
                CP16(dbase + 0 + doff, g_AOh + ga);
                CP16(dbase + 18432 + doff, g_AOl + ga);
            }
            for (int i = tid; i < 64 * 8; i += 256) {
                int r = i >> 3, c = (i & 7) * 8;
                uint32_t doff = (uint32_t)((r * PAD + c) * 2);
                long gb = (long)(n0 + r) * DIM + (kb + 1) * 64 + c;
                CP16(dbase + 36864 + doff, g_pwh + gb);
                CP16(dbase + 46080 + doff, g_pwl + gb);
            }
            CPCOMMIT();
        }

        __nv_bfloat16* bufp = (__nv_bfloat16*)(smraw + (kb & 1) * PBUF);
        __nv_bfloat16* sAh = bufp;
        __nv_bfloat16* sAl = sAh + 128 * PAD;
        __nv_bfloat16* sBh = sAl + 128 * PAD;
        __nv_bfloat16* sBl = sBh + 64 * PAD;

        uint32_t ah[4][4], al[4][4];
        {
            int rowb = wid * 16 + (lane & 15);
            int colb = (lane >> 4) * 8;
#pragma unroll
            for (int c = 0; c < 4; c++) {
                LDSM_X4(ah[c][0], ah[c][1], ah[c][2], ah[c][3],
                        smem_u32(sAh + rowb * PAD + c * 16 + colb));
                LDSM_X4(al[c][0], al[c][1], al[c][2], al[c][3],
                        smem_u32(sAl + rowb * PAD + c * 16 + colb));
            }
        }
        {
            int rbase = (lane & 7);
            int cbase = (lane >> 3) * 8;
#pragma unroll
            for (int j = 0; j < 8; j++) {
                uint32_t off = (uint32_t)((8 * j + rbase) * PAD + cbase);
                uint32_t bh01[4], bh23[4], bl01[4], bl23[4];
                LDSM_X4(bh01[0], bh01[1], bh01[2], bh01[3], smem_u32(sBh + off));
                LDSM_X4(bh23[0], bh23[1], bh23[2], bh23[3], smem_u32(sBh + off + 32));
                LDSM_X4(bl01[0], bl01[1], bl01[2], bl01[3], smem_u32(sBl + off));
                LDSM_X4(bl23[0], bl23[1], bl23[2], bl23[3], smem_u32(sBl + off + 32));
                MMA16816(C[j], ah[0], bh01[0], bh01[1]);
                MMA16816(C[j], ah[1], bh01[2], bh01[3]);
                MMA16816(C[j], ah[2], bh23[0], bh23[1]);
                MMA16816(C[j], ah[3], bh23[2], bh23[3]);
                MMA16816(C[j], ah[0], bl01[0], bl01[1]);
                MMA16816(C[j], ah[1], bl01[2], bl01[3]);
                MMA16816(C[j], ah[2], bl23[0], bl23[1]);
                MMA16816(C[j], ah[3], bl23[2], bl23[3]);
                MMA16816(C[j], al[0], bh01[0], bh01[1]);
                MMA16816(C[j], al[1], bh01[2], bh01[3]);
                MMA16816(C[j], al[2], bh23[0], bh23[1]);
                MMA16816(C[j], al[3], bh23[2], bh23[3]);
            }
        }
    }

    int g = lane >> 2, tg = lane & 3;
    int r0 = m0 + wid * 16 + g, r1 = r0 + 8;
#pragma unroll
    for (int j = 0; j < 8; j++) {
        int col = n0 + 8 * j + tg * 2;
        float b0 = pb[col], b1 = pb[col + 1];
        *(float2*)(out + (long)r0 * DIM + col) = make_float2(C[j][0] + b0, C[j][1] + b1);
        *(float2*)(out + (long)r1 * DIM + col) = make_float2(C[j][2] + b0, C[j][3] + b1);
    }
}

// ---------------------------------------------------------------------------
extern "C" void kernel_launch(void* const* d_in, const int* in_sizes, int n_in,
                              void* d_out, int out_size) {
    const float* x   = (const float*)d_in[0];
    const float* WQ0 = (const float*)d_in[1];
    const float* WQ1 = (const float*)d_in[2];
    const float* WQ2 = (const float*)d_in[3];
    const float* WK0 = (const float*)d_in[4];
    const float* WK1 = (const float*)d_in[5];
    const float* WK2 = (const float*)d_in[6];
    const float* WV0 = (const float*)d_in[7];
    const float* WV1 = (const float*)d_in[8];
    const float* WV2 = (const float*)d_in[9];
    const float* pw  = (const float*)d_in[10];
    const float* pb  = (const float*)d_in[11];
    float* out = (float*)d_out;

    const int SM_GT   = 2 * GBUF;                   // 73728
    const int SM_EXP  = (128 + 64) * PAD * 2 * 2;   // 55296
    const int SM_PROJ = 2 * PBUF;                   // 110592
    cudaFuncSetAttribute(k_gemm_T_mma, cudaFuncAttributeMaxDynamicSharedMemorySize, SM_GT);
    cudaFuncSetAttribute(k_expand_mma, cudaFuncAttributeMaxDynamicSharedMemorySize, SM_EXP);
    cudaFuncSetAttribute(k_flash,      cudaFuncAttributeMaxDynamicSharedMemorySize, SM_FLASH);
    cudaFuncSetAttribute(k_proj_mma,   cudaFuncAttributeMaxDynamicSharedMemorySize, SM_PROJ);

    k_prep<<<14592, 256>>>(x, pw, WQ0, WK0, WV0, WQ1, WQ2, WK1, WK2, WV1, WV2);
    k_gemm_T_mma<<<dim3(BN / 64, 3), 256, SM_GT>>>();
    k_expand_mma<<<dim3(BN / 128, NH, 3), 256, SM_EXP>>>();
    k_flash<<<dim3(NSEQ / 128, NBH), 256, SM_FLASH>>>();
    k_proj_mma<<<dim3(BN / 128, DIM / 64), 256, SM_PROJ>>>(pb, out);
}